// round 12
// baseline (speedup 1.0000x reference)
#include <cuda_runtime.h>
#include <cuda_bf16.h>
#include <cuda_fp16.h>
#include <math.h>
#include <stdint.h>

// ---------------- Problem constants ----------------
#define Bz   16
#define Lz   1024
#define DMz  512
#define Hz   8
#define DKz  64
#define DVz  64
#define DHz  2048
#define Uz   35
#define BHz  (Bz*Hz)     // 128
#define ROWSz (Bz*Lz)    // 16384
#define EPSz 1e-5f

// ---------------- fp32 scratch ----------------
__device__ float g_Q[ROWSz*DMz];
__device__ float g_K[ROWSz*DMz];
__device__ float g_V[ROWSz*DMz];
__device__ float g_M[BHz*Lz];
__device__ int   g_Mtop[BHz*Uz];
__device__ int   g_rowmap[BHz*Lz];
__device__ float g_attn[(size_t)BHz*Uz*Lz];
__device__ float g_ctxrow[BHz*Uz*DVz];
__device__ float g_vmean[BHz*DVz];
__device__ float g_y[ROWSz*DMz];
__device__ float g_x1[ROWSz*DMz];
__device__ float g_y2[ROWSz*DMz];

// ---------------- bf16 split scratch (Q/K path, 3-term) ----------------
__device__ __nv_bfloat16 g_xh[ROWSz*DMz], g_xl[ROWSz*DMz];
__device__ __nv_bfloat16 g_WqTh[DMz*DMz], g_WqTl[DMz*DMz];
__device__ __nv_bfloat16 g_WkTh[DMz*DMz], g_WkTl[DMz*DMz];

// ---------------- fp16 scratch (V/Wo/FFN path, single-pass) ----------------
__device__ __half g_xf[ROWSz*DMz];
__device__ __half g_cf[ROWSz*DMz];
__device__ __half g_x1f[ROWSz*DMz];
__device__ __half g_hf[(size_t)ROWSz*DHz];
__device__ __half g_WvTf[DMz*DMz];
__device__ __half g_WoTf[DMz*DMz];
__device__ __half g_W1Tf[DMz*DHz];
__device__ __half g_W2Tf[DHz*DMz];

// ---------------- helpers ----------------
__device__ __forceinline__ void cp16(uint32_t s, const void* g) {
    asm volatile("cp.async.cg.shared.global [%0], [%1], 16;"
                 :: "r"(s), "l"(__cvta_generic_to_global(g)));
}
__device__ __forceinline__ void cp_commit() {
    asm volatile("cp.async.commit_group;" ::: "memory");
}
__device__ __forceinline__ void ldm_x4(uint32_t& r0, uint32_t& r1, uint32_t& r2, uint32_t& r3,
                                       uint32_t addr) {
    asm volatile("ldmatrix.sync.aligned.m8n8.x4.shared.b16 {%0,%1,%2,%3}, [%4];"
                 : "=r"(r0), "=r"(r1), "=r"(r2), "=r"(r3) : "r"(addr));
}
__device__ __forceinline__ void mma_bf16(float* c, const uint32_t* a, const uint32_t* b) {
    asm volatile("mma.sync.aligned.m16n8k16.row.col.f32.bf16.bf16.f32 "
                 "{%0,%1,%2,%3}, {%4,%5,%6,%7}, {%8,%9}, {%0,%1,%2,%3};"
                 : "+f"(c[0]), "+f"(c[1]), "+f"(c[2]), "+f"(c[3])
                 : "r"(a[0]), "r"(a[1]), "r"(a[2]), "r"(a[3]), "r"(b[0]), "r"(b[1]));
}
__device__ __forceinline__ void mma_fp16(float* c, const uint32_t* a, const uint32_t* b) {
    asm volatile("mma.sync.aligned.m16n8k16.row.col.f32.f16.f16.f32 "
                 "{%0,%1,%2,%3}, {%4,%5,%6,%7}, {%8,%9}, {%0,%1,%2,%3};"
                 : "+f"(c[0]), "+f"(c[1]), "+f"(c[2]), "+f"(c[3])
                 : "r"(a[0]), "r"(a[1]), "r"(a[2]), "r"(a[3]), "r"(b[0]), "r"(b[1]));
}

#define ROWB 80
#define TILEB (128 * ROWB)      // 10240: 128-row operand tile
#define BTILE (256 * ROWB)      // 20480: 256-row operand tile (gemm1 B)

// ---------------- bf16 3-term GEMM (Q/K): BM=BN=128, warp 64x32 ----------------
#define SM3 (2 * 4 * TILEB)     // 81920

__global__ void __launch_bounds__(256, 2)
gemm3_kernel(const uint16_t* __restrict__ Ahi, const uint16_t* __restrict__ Alo,
             const uint16_t* __restrict__ Bhi, const uint16_t* __restrict__ Blo,
             const float* __restrict__ bias, float* __restrict__ C,
             float* __restrict__ fillp, int fillPerBlk, int N, int K)
{
    extern __shared__ __align__(16) char smem[];
    const uint32_t smem_u = (uint32_t)__cvta_generic_to_shared(smem);

    const int tid = threadIdx.x;
    const int wid = tid >> 5, lane = tid & 31;
    const int wm = (wid >> 2) * 64;
    const int wn = (wid & 3) * 32;
    const int g = lane >> 3, r = lane & 7;
    const int bm = blockIdx.y * 128;
    const int bn = blockIdx.x * 128;
    const int kt = K >> 5;

    float acc[4][4][4];
#pragma unroll
    for (int i = 0; i < 4; i++)
#pragma unroll
        for (int j = 0; j < 4; j++)
#pragma unroll
            for (int c = 0; c < 4; c++) acc[i][j][c] = 0.f;

    const int ar = tid >> 2, ac = tid & 3;

    auto load_tile = [&](int it, int buf) {
        const int kk = it << 5;
        const uint32_t s0 = smem_u + buf * (4 * TILEB);
        const size_t gaof = (size_t)(bm + ar) * K + kk + ac * 8;
        const size_t gbof = (size_t)(bn + ar) * K + kk + ac * 8;
        const size_t rowK64 = (size_t)64 * K;
        const uint32_t sof = ar * ROWB + ac * 16;
        cp16(s0 + sof, Ahi + gaof);
        cp16(s0 + sof + 64 * ROWB, Ahi + gaof + rowK64);
        cp16(s0 + TILEB + sof, Alo + gaof);
        cp16(s0 + TILEB + sof + 64 * ROWB, Alo + gaof + rowK64);
        cp16(s0 + 2 * TILEB + sof, Bhi + gbof);
        cp16(s0 + 2 * TILEB + sof + 64 * ROWB, Bhi + gbof + rowK64);
        cp16(s0 + 3 * TILEB + sof, Blo + gbof);
        cp16(s0 + 3 * TILEB + sof + 64 * ROWB, Blo + gbof + rowK64);
        cp_commit();
    };

    load_tile(0, 0);

    for (int it = 0; it < kt; it++) {
        const int buf = it & 1;
        asm volatile("cp.async.wait_group 0;" ::: "memory");
        __syncthreads();
        if (it + 1 < kt) load_tile(it + 1, buf ^ 1);

        const uint32_t sAh = smem_u + buf * (4 * TILEB);
        const uint32_t sAl = sAh + TILEB;
        const uint32_t sBh = sAh + 2 * TILEB;
        const uint32_t sBl = sAh + 3 * TILEB;
#pragma unroll
        for (int s = 0; s < 2; s++) {
            const int chkA = 2 * s + (g >> 1);
            const int chkB = 2 * s + (g & 1);
            const uint32_t aoff = (wm + ((g & 1) << 3) + r) * ROWB + chkA * 16;
            const uint32_t boff = (wn + ((g >> 1) << 3) + r) * ROWB + chkB * 16;

            uint32_t ah[4][4];
#pragma unroll
            for (int mf = 0; mf < 4; mf++)
                ldm_x4(ah[mf][0], ah[mf][1], ah[mf][2], ah[mf][3], sAh + aoff + mf * 16 * ROWB);
            uint32_t bh[4][2], bl[4][2];
#pragma unroll
            for (int ng = 0; ng < 2; ng++) {
                ldm_x4(bh[2 * ng][0], bh[2 * ng][1], bh[2 * ng + 1][0], bh[2 * ng + 1][1],
                       sBh + boff + ng * 16 * ROWB);
                ldm_x4(bl[2 * ng][0], bl[2 * ng][1], bl[2 * ng + 1][0], bl[2 * ng + 1][1],
                       sBl + boff + ng * 16 * ROWB);
            }
#pragma unroll
            for (int mf = 0; mf < 4; mf++)
#pragma unroll
                for (int nf = 0; nf < 4; nf++) {
                    mma_bf16(acc[mf][nf], ah[mf], bh[nf]);
                    mma_bf16(acc[mf][nf], ah[mf], bl[nf]);
                }
#pragma unroll
            for (int mf = 0; mf < 4; mf++)
                ldm_x4(ah[mf][0], ah[mf][1], ah[mf][2], ah[mf][3], sAl + aoff + mf * 16 * ROWB);
#pragma unroll
            for (int mf = 0; mf < 4; mf++)
#pragma unroll
                for (int nf = 0; nf < 4; nf++)
                    mma_bf16(acc[mf][nf], ah[mf], bh[nf]);
        }
    }

    const int rl = lane >> 2, cl = (lane & 3) * 2;
#pragma unroll
    for (int mf = 0; mf < 4; mf++) {
        const int row0 = bm + wm + mf * 16 + rl;
#pragma unroll
        for (int nf = 0; nf < 4; nf++) {
            const int col = bn + wn + nf * 8 + cl;
            const float b0 = bias[col], b1 = bias[col + 1];
            *(float2*)(C + (size_t)row0 * N + col) =
                make_float2(acc[mf][nf][0] + b0, acc[mf][nf][1] + b1);
            *(float2*)(C + (size_t)(row0 + 8) * N + col) =
                make_float2(acc[mf][nf][2] + b0, acc[mf][nf][3] + b1);
        }
    }

    if (fillp) {
        const int nv4 = fillPerBlk >> 2;
        const int blin = blockIdx.y * gridDim.x + blockIdx.x;
        float4* dst = (float4*)fillp + (size_t)blin * nv4;
        const float c = 1.0f / Lz;
        const float4 f4 = make_float4(c, c, c, c);
        for (int i = tid; i < nv4; i += 256) __stcs(dst + i, f4);
    }
}

// ---------------- fp16 single-pass GEMM: BM=128, BN=256, warp 64x64 ----------------
#define SM1 (2 * (TILEB + BTILE))   // 61440

__global__ void __launch_bounds__(256, 1)
gemm1_kernel(const uint16_t* __restrict__ A, const uint16_t* __restrict__ B,
             const float* __restrict__ bias, const float* __restrict__ res,
             float* __restrict__ C, uint16_t* __restrict__ Chi,
             float* __restrict__ fillp, int fillPerBlk,
             int N, int K, int eop)
{
    extern __shared__ __align__(16) char smem[];
    const uint32_t smem_u = (uint32_t)__cvta_generic_to_shared(smem);
    constexpr uint32_t STG = TILEB + BTILE;

    const int tid = threadIdx.x;
    const int wid = tid >> 5, lane = tid & 31;
    const int wm = (wid >> 2) * 64;
    const int wn = (wid & 3) * 64;
    const int g = lane >> 3, r = lane & 7;
    const int bm = blockIdx.y * 128;
    const int bn = blockIdx.x * 256;
    const int kt = K >> 5;

    float acc[4][8][4];
#pragma unroll
    for (int i = 0; i < 4; i++)
#pragma unroll
        for (int j = 0; j < 8; j++)
#pragma unroll
            for (int c = 0; c < 4; c++) acc[i][j][c] = 0.f;

    const int ar = tid >> 2, ac = tid & 3;

    auto load_tile = [&](int it, int buf) {
        const int kk = it << 5;
        const uint32_t s0 = smem_u + buf * STG;
        const size_t gaof = (size_t)(bm + ar) * K + kk + ac * 8;
        const size_t gbof = (size_t)(bn + ar) * K + kk + ac * 8;
        const size_t rowK64 = (size_t)64 * K;
        const uint32_t sof = ar * ROWB + ac * 16;
        cp16(s0 + sof, A + gaof);
        cp16(s0 + sof + 64 * ROWB, A + gaof + rowK64);
        const uint32_t sB = s0 + TILEB;
#pragma unroll
        for (int q = 0; q < 4; q++)
            cp16(sB + sof + q * 64 * ROWB, B + gbof + q * rowK64);
        cp_commit();
    };

    load_tile(0, 0);

    for (int it = 0; it < kt; it++) {
        const int buf = it & 1;
        asm volatile("cp.async.wait_group 0;" ::: "memory");
        __syncthreads();
        if (it + 1 < kt) load_tile(it + 1, buf ^ 1);

        const uint32_t sA = smem_u + buf * STG;
        const uint32_t sB = sA + TILEB;
#pragma unroll
        for (int s = 0; s < 2; s++) {
            const int chkA = 2 * s + (g >> 1);
            const int chkB = 2 * s + (g & 1);
            const uint32_t aoff = (wm + ((g & 1) << 3) + r) * ROWB + chkA * 16;
            const uint32_t boff = (wn + ((g >> 1) << 3) + r) * ROWB + chkB * 16;

            uint32_t ah[4][4];
#pragma unroll
            for (int mf = 0; mf < 4; mf++)
                ldm_x4(ah[mf][0], ah[mf][1], ah[mf][2], ah[mf][3], sA + aoff + mf * 16 * ROWB);
            uint32_t bh[8][2];
#pragma unroll
            for (int ng = 0; ng < 4; ng++)
                ldm_x4(bh[2 * ng][0], bh[2 * ng][1], bh[2 * ng + 1][0], bh[2 * ng + 1][1],
                       sB + boff + ng * 16 * ROWB);
#pragma unroll
            for (int mf = 0; mf < 4; mf++)
#pragma unroll
                for (int nf = 0; nf < 8; nf++)
                    mma_fp16(acc[mf][nf], ah[mf], bh[nf]);
        }
    }

    const int rl = lane >> 2, cl = (lane & 3) * 2;
#pragma unroll
    for (int mf = 0; mf < 4; mf++) {
        const int row0 = bm + wm + mf * 16 + rl;
#pragma unroll
        for (int nf = 0; nf < 8; nf++) {
            const int col = bn + wn + nf * 8 + cl;
            const float b0 = bias[col], b1 = bias[col + 1];
            float v0 = acc[mf][nf][0] + b0, v1 = acc[mf][nf][1] + b1;
            float v2 = acc[mf][nf][2] + b0, v3 = acc[mf][nf][3] + b1;
            if (eop == 1) {
                const float* r0 = res + (size_t)row0 * N + col;
                const float* r1 = res + (size_t)(row0 + 8) * N + col;
                v0 += r0[0]; v1 += r0[1]; v2 += r1[0]; v3 += r1[1];
            } else if (eop == 2) {
                v0 = fmaxf(v0, 0.f); v1 = fmaxf(v1, 0.f);
                v2 = fmaxf(v2, 0.f); v3 = fmaxf(v3, 0.f);
                *(__half2*)(Chi + (size_t)row0 * N + col)       = __floats2half2_rn(v0, v1);
                *(__half2*)(Chi + (size_t)(row0 + 8) * N + col) = __floats2half2_rn(v2, v3);
                continue;
            }
            *(float2*)(C + (size_t)row0 * N + col) = make_float2(v0, v1);
            *(float2*)(C + (size_t)(row0 + 8) * N + col) = make_float2(v2, v3);
        }
    }

    if (fillp) {
        const int nv4 = fillPerBlk >> 2;
        const int blin = blockIdx.y * gridDim.x + blockIdx.x;
        float4* dst = (float4*)fillp + (size_t)blin * nv4;
        const float c = 1.0f / Lz;
        const float4 f4 = make_float4(c, c, c, c);
        for (int i = tid; i < nv4; i += 256) __stcs(dst + i, f4);
    }
}

// ---------------- x -> bf16 hi/lo + fp16, one read ----------------
__global__ void __launch_bounds__(256)
split_x_kernel(const float* __restrict__ src, __nv_bfloat16* __restrict__ hi,
               __nv_bfloat16* __restrict__ lo, __half* __restrict__ f16)
{
    const size_t i = (size_t)blockIdx.x * 256 + threadIdx.x;
    const float4 v = ((const float4*)src)[i];
    __nv_bfloat16 h0 = __float2bfloat16(v.x), h1 = __float2bfloat16(v.y);
    __nv_bfloat16 h2 = __float2bfloat16(v.z), h3 = __float2bfloat16(v.w);
    __nv_bfloat162 ha; ha.x = h0; ha.y = h1;
    __nv_bfloat162 hb; hb.x = h2; hb.y = h3;
    ((__nv_bfloat162*)hi)[i * 2 + 0] = ha;
    ((__nv_bfloat162*)hi)[i * 2 + 1] = hb;
    __nv_bfloat162 la, lb;
    la.x = __float2bfloat16(v.x - __bfloat162float(h0));
    la.y = __float2bfloat16(v.y - __bfloat162float(h1));
    lb.x = __float2bfloat16(v.z - __bfloat162float(h2));
    lb.y = __float2bfloat16(v.w - __bfloat162float(h3));
    ((__nv_bfloat162*)lo)[i * 2 + 0] = la;
    ((__nv_bfloat162*)lo)[i * 2 + 1] = lb;
    ((__half2*)f16)[i * 2 + 0] = __floats2half2_rn(v.x, v.y);
    ((__half2*)f16)[i * 2 + 1] = __floats2half2_rn(v.z, v.w);
}

// ---------------- weight transpose + bf16 hi/lo split ----------------
__global__ void __launch_bounds__(256)
tsplit_kernel(const float* __restrict__ src, __nv_bfloat16* __restrict__ hi,
              __nv_bfloat16* __restrict__ lo, int K, int N)
{
    __shared__ float tile[32][33];
    const int tx = threadIdx.x & 31, ty = threadIdx.x >> 5;
    const int n0 = blockIdx.x * 32, k0 = blockIdx.y * 32;
#pragma unroll
    for (int i = 0; i < 4; i++)
        tile[ty + 8 * i][tx] = src[(size_t)(k0 + ty + 8 * i) * N + n0 + tx];
    __syncthreads();
#pragma unroll
    for (int i = 0; i < 4; i++) {
        const int n = n0 + ty + 8 * i, k = k0 + tx;
        const float v = tile[tx][ty + 8 * i];
        const __nv_bfloat16 h = __float2bfloat16(v);
        hi[(size_t)n * K + k] = h;
        lo[(size_t)n * K + k] = __float2bfloat16(v - __bfloat162float(h));
    }
}

// ---------------- weight transpose -> fp16 ----------------
__global__ void __launch_bounds__(256)
tsplitf_kernel(const float* __restrict__ src, __half* __restrict__ dst, int K, int N)
{
    __shared__ float tile[32][33];
    const int tx = threadIdx.x & 31, ty = threadIdx.x >> 5;
    const int n0 = blockIdx.x * 32, k0 = blockIdx.y * 32;
#pragma unroll
    for (int i = 0; i < 4; i++)
        tile[ty + 8 * i][tx] = src[(size_t)(k0 + ty + 8 * i) * N + n0 + tx];
    __syncthreads();
#pragma unroll
    for (int i = 0; i < 4; i++) {
        const int n = n0 + ty + 8 * i, k = k0 + tx;
        dst[(size_t)n * K + k] = __float2half(tile[tx][ty + 8 * i]);
    }
}

// ---------------- Sampled scores + fill chunk ----------------
__global__ void compute_m_kernel(const int* __restrict__ idx, float* __restrict__ fillp)
{
    {
        const float c = 1.0f / Lz;
        const float4 f4 = make_float4(c, c, c, c);
        float4* dst = (float4*)fillp + (size_t)blockIdx.x * 512;
        __stcs(dst + threadIdx.x, f4);
        __stcs(dst + threadIdx.x + 256, f4);
    }

    const int gw = (blockIdx.x * blockDim.x + threadIdx.x) >> 5;
    const int lane = threadIdx.x & 31;
    const int l = gw & (Lz - 1);
    const int bh = gw >> 10;
    const int h = bh & (Hz - 1), b = bh >> 3;

    const float2* qrow = (const float2*)(g_Q + (size_t)(b * Lz + l) * DMz + h * DKz);
    const float2 q2 = qrow[lane];
    float mx = -INFINITY, sum = 0.f;
#pragma unroll 1
    for (int s = 0; s < Uz; s++) {
        const int j = idx[l * Uz + s];
        const float2 k2 = ((const float2*)(g_K + (size_t)(b * Lz + j) * DMz + h * DKz))[lane];
        float p = q2.x * k2.x + q2.y * k2.y;
#pragma unroll
        for (int o = 16; o; o >>= 1) p += __shfl_xor_sync(0xffffffffu, p, o);
        mx = fmaxf(mx, p);
        sum += p;
    }
    if (lane == 0) g_M[bh * Lz + l] = mx - sum * (1.0f / Uz);
}

// ---------------- top-35 per (b,h) ----------------
__global__ void __launch_bounds__(256) topk_kernel()
{
    const int bh = blockIdx.x;
    const int tid = threadIdx.x;
    const int wid = tid >> 5, lane = tid & 31;
    __shared__ float vals[Lz];
    __shared__ float wv[8];
    __shared__ int   wi[8];

    for (int l = tid; l < Lz; l += 256) {
        vals[l] = g_M[bh * Lz + l];
        g_rowmap[bh * Lz + l] = -1;
    }
    __syncthreads();

    for (int u = 0; u < Uz; u++) {
        float best = -INFINITY; int bi = 0x7fffffff;
#pragma unroll
        for (int c = 0; c < 4; c++) {
            const int l = tid + c * 256;
            const float v = vals[l];
            if (v > best) { best = v; bi = l; }
        }
#pragma unroll
        for (int o = 16; o; o >>= 1) {
            const float ov = __shfl_xor_sync(0xffffffffu, best, o);
            const int   oi = __shfl_xor_sync(0xffffffffu, bi, o);
            if (ov > best || (ov == best && oi < bi)) { best = ov; bi = oi; }
        }
        if (lane == 0) { wv[wid] = best; wi[wid] = bi; }
        __syncthreads();
        if (tid == 0) {
            float fb = wv[0]; int fi = wi[0];
#pragma unroll
            for (int w = 1; w < 8; w++) {
                if (wv[w] > fb || (wv[w] == fb && wi[w] < fi)) { fb = wv[w]; fi = wi[w]; }
            }
            g_Mtop[bh * Uz + u] = fi;
            g_rowmap[bh * Lz + fi] = u;
            vals[fi] = -INFINITY;
        }
        __syncthreads();
    }
}

// ---------------- scores = Q_top @ K^T / 8 ----------------
__global__ void __launch_bounds__(256) scores_kernel()
{
    const int bh = blockIdx.x;
    const int b = bh >> 3, h = bh & (Hz - 1);
    const int tid = threadIdx.x;
    __shared__ float Qr[Uz * DKz];

    for (int i = tid; i < Uz * DKz; i += 256) {
        const int u = i / DKz, d = i - u * DKz;
        const int l = g_Mtop[bh * Uz + u];
        Qr[i] = g_Q[(size_t)(b * Lz + l) * DMz + h * DKz + d];
    }
    __syncthreads();

    for (int l = tid; l < Lz; l += 256) {
        float acc[Uz];
#pragma unroll
        for (int u = 0; u < Uz; u++) acc[u] = 0.f;
        const float* krow = g_K + (size_t)(b * Lz + l) * DMz + h * DKz;
#pragma unroll 4
        for (int d = 0; d < DKz; d++) {
            const float kd = krow[d];
#pragma unroll
            for (int u = 0; u < Uz; u++) acc[u] += kd * Qr[u * DKz + d];
        }
#pragma unroll
        for (int u = 0; u < Uz; u++)
            g_attn[((size_t)bh * Uz + u) * Lz + l] = acc[u] * 0.125f;
    }
}

// ---------------- row softmax over L ----------------
__global__ void __launch_bounds__(256) softmax_kernel()
{
    const int row = blockIdx.x;
    float* p = g_attn + (size_t)row * Lz;
    const int tid = threadIdx.x;
    __shared__ float red[256];

    float4 v = ((float4*)p)[tid];
    float m = fmaxf(fmaxf(v.x, v.y), fmaxf(v.z, v.w));
    red[tid] = m; __syncthreads();
    for (int s = 128; s; s >>= 1) { if (tid < s) red[tid] = fmaxf(red[tid], red[tid + s]); __syncthreads(); }
    m = red[0]; __syncthreads();

    v.x = __expf(v.x - m); v.y = __expf(v.y - m);
    v.z = __expf(v.z - m); v.w = __expf(v.w - m);
    red[tid] = v.x + v.y + v.z + v.w; __syncthreads();
    for (int s = 128; s; s >>= 1) { if (tid < s) red[tid] += red[tid + s]; __syncthreads(); }
    const float inv = 1.0f / red[0];
    v.x *= inv; v.y *= inv; v.z *= inv; v.w *= inv;
    ((float4*)p)[tid] = v;
}

// ---------------- context (+fused V-mean) ----------------
__global__ void __launch_bounds__(256) context_kernel()
{
    const int bh = blockIdx.x;
    const int b = bh >> 3, h = bh & (Hz - 1);
    const int t = threadIdx.x;
    const int d = t & 63, ug = t >> 6;
    __shared__ float sat[Uz][129];

    float acc[9];
#pragma unroll
    for (int k = 0; k < 9; k++) acc[k] = 0.f;
    float vsum = 0.f;

    for (int c = 0; c < 8; c++) {
        for (int i = t; i < Uz * 128; i += 256) {
            const int u = i >> 7, li = i & 127;
            sat[u][li] = g_attn[((size_t)bh * Uz + u) * Lz + c * 128 + li];
        }
        __syncthreads();
        const float* vb = g_V + (size_t)(b * Lz + c * 128) * DMz + h * DVz + d;
#pragma unroll 4
        for (int i = 0; i < 128; i++) {
            const float v = vb[(size_t)i * DMz];
            vsum += v;
#pragma unroll
            for (int k = 0; k < 9; k++) {
                const int u = ug + 4 * k;
                if (u < Uz) acc[k] += sat[u][i] * v;
            }
        }
        __syncthreads();
    }
#pragma unroll
    for (int k = 0; k < 9; k++) {
        const int u = ug + 4 * k;
        if (u < Uz) g_ctxrow[(bh * Uz + u) * DVz + d] = acc[k];
    }
    if (ug == 0) g_vmean[bh * DVz + d] = vsum * (1.0f / Lz);
}

// ---------------- copy selected attn rows into pre-filled score output ----------------
__global__ void __launch_bounds__(256) copy_scores_kernel(float* __restrict__ outp)
{
    const int bhu = blockIdx.x;
    const int bh = bhu / Uz;
    const int l = g_Mtop[bhu];
    const float4* src = (const float4*)(g_attn + (size_t)bhu * Lz);
    float4* dst = (float4*)(outp + ((size_t)bh * Lz + l) * Lz);
    dst[threadIdx.x] = src[threadIdx.x];
}

// ---------------- assemble ctx -> fp16 ----------------
__global__ void __launch_bounds__(256) ctx_assemble_kernel(__half* __restrict__ dst)
{
    const size_t gidx = (size_t)blockIdx.x * 256 + threadIdx.x;
    const int row = (int)(gidx >> 9);
    const int c = (int)(gidx & 511);
    const int h = c >> 6, d = c & 63;
    const int b = row >> 10, l = row & (Lz - 1);
    const int bh = b * Hz + h;
    const int u = g_rowmap[bh * Lz + l];
    const float v = (u < 0) ? g_vmean[bh * DVz + d]
                            : g_ctxrow[(bh * Uz + u) * DVz + d];
    dst[gidx] = __float2half(v);
}

// ---------------- LayerNorm (512), optional fused fp16 output ----------------
__global__ void __launch_bounds__(256)
ln_kernel(const float* __restrict__ in, const float* __restrict__ g,
          const float* __restrict__ beta, float* __restrict__ out,
          __half* __restrict__ outf)
{
    const int row = blockIdx.x;
    const int tid = threadIdx.x;
    __shared__ float red[256];
    const float* r = in + (size_t)row * DMz;
    const float a = r[tid], b2 = r[tid + 256];

    red[tid] = a + b2; __syncthreads();
    for (int s = 128; s; s >>= 1) { if (tid < s) red[tid] += red[tid + s]; __syncthreads(); }
    const float mean = red[0] * (1.0f / DMz);
    __syncthreads();
    const float d0 = a - mean, d1 = b2 - mean;
    red[tid] = d0 * d0 + d1 * d1; __syncthreads();
    for (int s = 128; s; s >>= 1) { if (tid < s) red[tid] += red[tid + s]; __syncthreads(); }
    const float inv = rsqrtf(red[0] * (1.0f / DMz) + EPSz);
    const float o0 = g[tid]       * d0 * inv + beta[tid];
    const float o1 = g[tid + 256] * d1 * inv + beta[tid + 256];
    out[(size_t)row * DMz + tid]       = o0;
    out[(size_t)row * DMz + tid + 256] = o1;
    if (outf) {
        outf[(size_t)row * DMz + tid]       = __float2half(o0);
        outf[(size_t)row * DMz + tid + 256] = __float2half(o1);
    }
}

// ---------------- launch ----------------
extern "C" void kernel_launch(void* const* d_in, const int* in_sizes, int n_in,
                              void* d_out, int out_size)
{
    const float* x   = (const float*)d_in[0];
    const float* Wq  = (const float*)d_in[1];
    const float* bq  = (const float*)d_in[2];
    const float* Wk  = (const float*)d_in[3];
    const float* bk  = (const float*)d_in[4];
    const float* Wv  = (const float*)d_in[5];
    const float* bv  = (const float*)d_in[6];
    const float* Wo  = (const float*)d_in[7];
    const float* bo  = (const float*)d_in[8];
    const float* g1  = (const float*)d_in[9];
    const float* be1 = (const float*)d_in[10];
    const float* W1  = (const float*)d_in[11];
    const float* bf1 = (const float*)d_in[12];
    const float* W2  = (const float*)d_in[13];
    const float* bf2 = (const float*)d_in[14];
    const float* g2  = (const float*)d_in[15];
    const float* be2 = (const float*)d_in[16];
    const int*   idx = (const int*)d_in[17];
    float* out = (float*)d_out;
    float* score = out + (size_t)ROWSz * DMz;

    float *Qp, *Kp, *Vp, *yp, *x1p, *y2p;
    cudaGetSymbolAddress((void**)&Qp,   g_Q);
    cudaGetSymbolAddress((void**)&Kp,   g_K);
    cudaGetSymbolAddress((void**)&Vp,   g_V);
    cudaGetSymbolAddress((void**)&yp,   g_y);
    cudaGetSymbolAddress((void**)&x1p,  g_x1);
    cudaGetSymbolAddress((void**)&y2p,  g_y2);

    __nv_bfloat16 *xh, *xl, *WqTh, *WqTl, *WkTh, *WkTl;
    __half *xf, *cf, *x1f, *hf, *WvTf, *WoTf, *W1Tf, *W2Tf;
    cudaGetSymbolAddress((void**)&xh, g_xh);     cudaGetSymbolAddress((void**)&xl, g_xl);
    cudaGetSymbolAddress((void**)&WqTh, g_WqTh); cudaGetSymbolAddress((void**)&WqTl, g_WqTl);
    cudaGetSymbolAddress((void**)&WkTh, g_WkTh); cudaGetSymbolAddress((void**)&WkTl, g_WkTl);
    cudaGetSymbolAddress((void**)&xf, g_xf);     cudaGetSymbolAddress((void**)&cf, g_cf);
    cudaGetSymbolAddress((void**)&x1f, g_x1f);   cudaGetSymbolAddress((void**)&hf, g_hf);
    cudaGetSymbolAddress((void**)&WvTf, g_WvTf); cudaGetSymbolAddress((void**)&WoTf, g_WoTf);
    cudaGetSymbolAddress((void**)&W1Tf, g_W1Tf); cudaGetSymbolAddress((void**)&W2Tf, g_W2Tf);

    cudaFuncSetAttribute(gemm3_kernel,
                         cudaFuncAttributeMaxDynamicSharedMemorySize, SM3);
    cudaFuncSetAttribute(gemm1_kernel,
                         cudaFuncAttributeMaxDynamicSharedMemorySize, SM1);

    const dim3 g3_512(4, 128);     // gemm3: BN=128
    const dim3 g1_512(2, 128);     // gemm1: BN=256, N=512
    const dim3 g1_2048(8, 128);    // gemm1: BN=256, N=2048

    // fill partition: Q 512*65536 + K 512*65536 + V 256*131072 + compute_m 16384*2048
    //               = 33.5M + 33.5M + 33.5M + 33.5M = 134217728 = BHz*Lz*Lz
    const int FPB_G3 = 65536;
    const int FPB_G1 = 131072;
    float* fill0 = score;
    float* fill1 = score + (size_t)512 * FPB_G3;
    float* fill2 = score + (size_t)1024 * FPB_G3;
    float* fill3 = score + (size_t)1024 * FPB_G3 + (size_t)256 * FPB_G1;

    // conversions for QKV (launch #6 = GEMM Q for ncu)
    split_x_kernel<<<(ROWSz * DMz) / 1024, 256>>>(x, xh, xl, xf);          // 1
    tsplit_kernel<<<dim3(16, 16), 256>>>(Wq, WqTh, WqTl, DMz, DMz);        // 2
    tsplit_kernel<<<dim3(16, 16), 256>>>(Wk, WkTh, WkTl, DMz, DMz);        // 3
    tsplitf_kernel<<<dim3(16, 16), 256>>>(Wv, WvTf, DMz, DMz);             // 4
    tsplitf_kernel<<<dim3(16, 16), 256>>>(Wo, WoTf, DMz, DMz);             // 5

    // QKV projections (+score fill)
    gemm3_kernel<<<g3_512, 256, SM3>>>((const uint16_t*)xh, (const uint16_t*)xl,
        (const uint16_t*)WqTh, (const uint16_t*)WqTl, bq, Qp, fill0, FPB_G3, DMz, DMz); // 6 (ncu)
    gemm3_kernel<<<g3_512, 256, SM3>>>((const uint16_t*)xh, (const uint16_t*)xl,
        (const uint16_t*)WkTh, (const uint16_t*)WkTl, bk, Kp, fill1, FPB_G3, DMz, DMz); // 7
    gemm1_kernel<<<g1_512, 256, SM1>>>((const uint16_t*)xf, (const uint16_t*)WvTf,
        bv, nullptr, Vp, nullptr, fill2, FPB_G1, DMz, DMz, 0);                          // 8

    // remaining weight conversions
    tsplitf_kernel<<<dim3(64, 16), 256>>>(W1, W1Tf, DMz, DHz);
    tsplitf_kernel<<<dim3(16, 64), 256>>>(W2, W2Tf, DHz, DMz);

    // ProbSparse attention
    compute_m_kernel<<<(BHz * Lz) / 8, 256>>>(idx, fill3);
    topk_kernel<<<BHz, 256>>>();
    scores_kernel<<<BHz, 256>>>();
    softmax_kernel<<<BHz * Uz, 256>>>();
    context_kernel<<<BHz, 256>>>();
    copy_scores_kernel<<<BHz * Uz, 256>>>(score);
    ctx_assemble_kernel<<<(ROWSz * DMz) / 256, 256>>>(cf);

    // Wo projection + residual, LN1 (fused fp16 x1)
    gemm1_kernel<<<g1_512, 256, SM1>>>((const uint16_t*)cf, (const uint16_t*)WoTf,
        bo, x, yp, nullptr, nullptr, 0, DMz, DMz, 1);
    ln_kernel<<<ROWSz, 256>>>(yp, g1, be1, x1p, x1f);

    // FFN
    gemm1_kernel<<<g1_2048, 256, SM1>>>((const uint16_t*)x1f, (const uint16_t*)W1Tf,
        bf1, nullptr, nullptr, (uint16_t*)hf, nullptr, 0, DHz, DMz, 2);
    gemm1_kernel<<<g1_512, 256, SM1>>>((const uint16_t*)hf, (const uint16_t*)W2Tf,
        bf2, x1p, y2p, nullptr, nullptr, 0, DMz, DHz, 1);
    ln_kernel<<<ROWSz, 256>>>(y2p, g2, be2, out, nullptr);
}

// round 13
// speedup vs baseline: 1.0516x; 1.0516x over previous
#include <cuda_runtime.h>
#include <cuda_bf16.h>
#include <cuda_fp16.h>
#include <math.h>
#include <stdint.h>

// ---------------- Problem constants ----------------
#define Bz   16
#define Lz   1024
#define DMz  512
#define Hz   8
#define DKz  64
#define DVz  64
#define DHz  2048
#define Uz   35
#define BHz  (Bz*Hz)     // 128
#define ROWSz (Bz*Lz)    // 16384
#define EPSz 1e-5f

// ---------------- fp32 scratch ----------------
__device__ float g_Q[ROWSz*DMz];
__device__ float g_K[ROWSz*DMz];
__device__ float g_V[ROWSz*DMz];
__device__ float g_M[BHz*Lz];
__device__ int   g_Mtop[BHz*Uz];
__device__ int   g_rowmap[BHz*Lz];
__device__ float g_attn[(size_t)BHz*Uz*Lz];
__device__ float g_ctxrow[BHz*Uz*DVz];
__device__ float g_vmean[BHz*DVz];
__device__ float g_y[ROWSz*DMz];
__device__ float g_x1[ROWSz*DMz];
__device__ float g_y2[ROWSz*DMz];

// ---------------- bf16 split scratch (Q/K path, 3-term) ----------------
__device__ __nv_bfloat16 g_xh[ROWSz*DMz], g_xl[ROWSz*DMz];
__device__ __nv_bfloat16 g_WqTh[DMz*DMz], g_WqTl[DMz*DMz];
__device__ __nv_bfloat16 g_WkTh[DMz*DMz], g_WkTl[DMz*DMz];

// ---------------- fp16 scratch (V/Wo/FFN path, single-pass) ----------------
__device__ __half g_xf[ROWSz*DMz];
__device__ __half g_cf[ROWSz*DMz];
__device__ __half g_x1f[ROWSz*DMz];
__device__ __half g_hf[(size_t)ROWSz*DHz];
__device__ __half g_WvTf[DMz*DMz];
__device__ __half g_WoTf[DMz*DMz];
__device__ __half g_W1Tf[DMz*DHz];
__device__ __half g_W2Tf[DHz*DMz];

// ---------------- helpers ----------------
__device__ __forceinline__ void cp16(uint32_t s, const void* g) {
    asm volatile("cp.async.cg.shared.global [%0], [%1], 16;"
                 :: "r"(s), "l"(__cvta_generic_to_global(g)));
}
__device__ __forceinline__ void cp_commit() {
    asm volatile("cp.async.commit_group;" ::: "memory");
}
__device__ __forceinline__ void ldm_x4(uint32_t& r0, uint32_t& r1, uint32_t& r2, uint32_t& r3,
                                       uint32_t addr) {
    asm volatile("ldmatrix.sync.aligned.m8n8.x4.shared.b16 {%0,%1,%2,%3}, [%4];"
                 : "=r"(r0), "=r"(r1), "=r"(r2), "=r"(r3) : "r"(addr));
}
template<bool ISBF16>
__device__ __forceinline__ void mma_t(float* c, const uint32_t* a, const uint32_t* b) {
    if constexpr (ISBF16)
        asm volatile("mma.sync.aligned.m16n8k16.row.col.f32.bf16.bf16.f32 "
                     "{%0,%1,%2,%3}, {%4,%5,%6,%7}, {%8,%9}, {%0,%1,%2,%3};"
                     : "+f"(c[0]), "+f"(c[1]), "+f"(c[2]), "+f"(c[3])
                     : "r"(a[0]), "r"(a[1]), "r"(a[2]), "r"(a[3]), "r"(b[0]), "r"(b[1]));
    else
        asm volatile("mma.sync.aligned.m16n8k16.row.col.f32.f16.f16.f32 "
                     "{%0,%1,%2,%3}, {%4,%5,%6,%7}, {%8,%9}, {%0,%1,%2,%3};"
                     : "+f"(c[0]), "+f"(c[1]), "+f"(c[2]), "+f"(c[3])
                     : "r"(a[0]), "r"(a[1]), "r"(a[2]), "r"(a[3]), "r"(b[0]), "r"(b[1]));
}

// ---------------- mma.sync GEMM, templated <TERMS, ISBF16>, optional score-fill ----------------
// (R11 configuration: BM=BN=128, warp 64x32, 2-stage, occupancy 2)
#define ROWB 80
#define TILEB (128 * ROWB)

template<int TERMS, bool ISBF16>
__global__ void __launch_bounds__(256, 2)
gemm_kernel(const uint16_t* __restrict__ Ahi, const uint16_t* __restrict__ Alo,
            const uint16_t* __restrict__ Bhi, const uint16_t* __restrict__ Blo,
            const float* __restrict__ bias, const float* __restrict__ res,
            float* __restrict__ C, uint16_t* __restrict__ Chi,
            float* __restrict__ fillp, int fillPerBlk,
            int M, int N, int K, int eop)
{
    constexpr int NT = (TERMS == 3) ? 4 : 2;
    constexpr uint32_t STG = NT * TILEB;
    extern __shared__ __align__(16) char smem[];
    const uint32_t smem_u = (uint32_t)__cvta_generic_to_shared(smem);

    const int tid = threadIdx.x;
    const int wid = tid >> 5, lane = tid & 31;
    const int wm = (wid >> 2) * 64;
    const int wn = (wid & 3) * 32;
    const int g = lane >> 3, r = lane & 7;
    const int bm = blockIdx.y * 128;
    const int bn = blockIdx.x * 128;

    const int kt = K >> 5;

    float acc[4][4][4];
#pragma unroll
    for (int i = 0; i < 4; i++)
#pragma unroll
        for (int j = 0; j < 4; j++)
#pragma unroll
            for (int c = 0; c < 4; c++) acc[i][j][c] = 0.f;

    const int ar = tid >> 2, ac = tid & 3;

    auto load_tile = [&](int it, int buf) {
        const int kk = it << 5;
        const uint32_t s0 = smem_u + buf * STG;
        const size_t gaof = (size_t)(bm + ar) * K + kk + ac * 8;
        const size_t gbof = (size_t)(bn + ar) * K + kk + ac * 8;
        const size_t rowK64 = (size_t)64 * K;
        const uint32_t sof = ar * ROWB + ac * 16;
        cp16(s0 + sof, Ahi + gaof);
        cp16(s0 + sof + 64 * ROWB, Ahi + gaof + rowK64);
        if constexpr (TERMS == 3) {
            cp16(s0 + TILEB + sof, Alo + gaof);
            cp16(s0 + TILEB + sof + 64 * ROWB, Alo + gaof + rowK64);
            cp16(s0 + 2 * TILEB + sof, Bhi + gbof);
            cp16(s0 + 2 * TILEB + sof + 64 * ROWB, Bhi + gbof + rowK64);
            cp16(s0 + 3 * TILEB + sof, Blo + gbof);
            cp16(s0 + 3 * TILEB + sof + 64 * ROWB, Blo + gbof + rowK64);
        } else {
            cp16(s0 + TILEB + sof, Bhi + gbof);
            cp16(s0 + TILEB + sof + 64 * ROWB, Bhi + gbof + rowK64);
        }
        cp_commit();
    };

    load_tile(0, 0);

    for (int it = 0; it < kt; it++) {
        const int buf = it & 1;
        asm volatile("cp.async.wait_group 0;" ::: "memory");
        __syncthreads();

        if (it + 1 < kt) load_tile(it + 1, buf ^ 1);

        const uint32_t sAh = smem_u + buf * STG;
        const uint32_t sBh = sAh + ((TERMS == 3) ? 2 : 1) * TILEB;
#pragma unroll
        for (int s = 0; s < 2; s++) {
            const int chkA = 2 * s + (g >> 1);
            const int chkB = 2 * s + (g & 1);
            const uint32_t aoff = (wm + ((g & 1) << 3) + r) * ROWB + chkA * 16;
            const uint32_t boff = (wn + ((g >> 1) << 3) + r) * ROWB + chkB * 16;

            uint32_t ah[4][4];
#pragma unroll
            for (int mf = 0; mf < 4; mf++)
                ldm_x4(ah[mf][0], ah[mf][1], ah[mf][2], ah[mf][3], sAh + aoff + mf * 16 * ROWB);
            uint32_t bh[4][2];
#pragma unroll
            for (int ng = 0; ng < 2; ng++)
                ldm_x4(bh[2 * ng][0], bh[2 * ng][1], bh[2 * ng + 1][0], bh[2 * ng + 1][1],
                       sBh + boff + ng * 16 * ROWB);

            if constexpr (TERMS == 3) {
                const uint32_t sAl = sAh + TILEB;
                const uint32_t sBl = sAh + 3 * TILEB;
                uint32_t bl[4][2];
#pragma unroll
                for (int ng = 0; ng < 2; ng++)
                    ldm_x4(bl[2 * ng][0], bl[2 * ng][1], bl[2 * ng + 1][0], bl[2 * ng + 1][1],
                           sBl + boff + ng * 16 * ROWB);
#pragma unroll
                for (int mf = 0; mf < 4; mf++)
#pragma unroll
                    for (int nf = 0; nf < 4; nf++) {
                        mma_t<ISBF16>(acc[mf][nf], ah[mf], bh[nf]);
                        mma_t<ISBF16>(acc[mf][nf], ah[mf], bl[nf]);
                    }
#pragma unroll
                for (int mf = 0; mf < 4; mf++)
                    ldm_x4(ah[mf][0], ah[mf][1], ah[mf][2], ah[mf][3], sAl + aoff + mf * 16 * ROWB);
#pragma unroll
                for (int mf = 0; mf < 4; mf++)
#pragma unroll
                    for (int nf = 0; nf < 4; nf++)
                        mma_t<ISBF16>(acc[mf][nf], ah[mf], bh[nf]);
            } else {
#pragma unroll
                for (int mf = 0; mf < 4; mf++)
#pragma unroll
                    for (int nf = 0; nf < 4; nf++)
                        mma_t<ISBF16>(acc[mf][nf], ah[mf], bh[nf]);
            }
        }
    }

    // epilogue
    const int rl = lane >> 2, cl = (lane & 3) * 2;
#pragma unroll
    for (int mf = 0; mf < 4; mf++) {
        const int row0 = bm + wm + mf * 16 + rl;
#pragma unroll
        for (int nf = 0; nf < 4; nf++) {
            const int col = bn + wn + nf * 8 + cl;
            const float b0 = bias[col], b1 = bias[col + 1];
            float v0 = acc[mf][nf][0] + b0, v1 = acc[mf][nf][1] + b1;
            float v2 = acc[mf][nf][2] + b0, v3 = acc[mf][nf][3] + b1;
            if (eop == 1) {
                const float* r0 = res + (size_t)row0 * N + col;
                const float* r1 = res + (size_t)(row0 + 8) * N + col;
                v0 += r0[0]; v1 += r0[1]; v2 += r1[0]; v3 += r1[1];
            } else if (eop == 2) {
                v0 = fmaxf(v0, 0.f); v1 = fmaxf(v1, 0.f);
                v2 = fmaxf(v2, 0.f); v3 = fmaxf(v3, 0.f);
                *(__half2*)(Chi + (size_t)row0 * N + col)       = __floats2half2_rn(v0, v1);
                *(__half2*)(Chi + (size_t)(row0 + 8) * N + col) = __floats2half2_rn(v2, v3);
                continue;
            }
            *(float2*)(C + (size_t)row0 * N + col) = make_float2(v0, v1);
            *(float2*)(C + (size_t)(row0 + 8) * N + col) = make_float2(v2, v3);
        }
    }

    // piggybacked constant fill of the score output (streaming stores)
    if (fillp) {
        const int nv4 = fillPerBlk >> 2;
        const int blin = blockIdx.y * gridDim.x + blockIdx.x;
        float4* dst = (float4*)fillp + (size_t)blin * nv4;
        const float c = 1.0f / Lz;
        const float4 f4 = make_float4(c, c, c, c);
        for (int i = tid; i < nv4; i += 256) __stcs(dst + i, f4);
    }
}

// ---------------- x -> bf16 hi/lo + fp16, one read ----------------
__global__ void __launch_bounds__(256)
split_x_kernel(const float* __restrict__ src, __nv_bfloat16* __restrict__ hi,
               __nv_bfloat16* __restrict__ lo, __half* __restrict__ f16)
{
    const size_t i = (size_t)blockIdx.x * 256 + threadIdx.x;
    const float4 v = ((const float4*)src)[i];
    __nv_bfloat16 h0 = __float2bfloat16(v.x), h1 = __float2bfloat16(v.y);
    __nv_bfloat16 h2 = __float2bfloat16(v.z), h3 = __float2bfloat16(v.w);
    __nv_bfloat162 ha; ha.x = h0; ha.y = h1;
    __nv_bfloat162 hb; hb.x = h2; hb.y = h3;
    ((__nv_bfloat162*)hi)[i * 2 + 0] = ha;
    ((__nv_bfloat162*)hi)[i * 2 + 1] = hb;
    __nv_bfloat162 la, lb;
    la.x = __float2bfloat16(v.x - __bfloat162float(h0));
    la.y = __float2bfloat16(v.y - __bfloat162float(h1));
    lb.x = __float2bfloat16(v.z - __bfloat162float(h2));
    lb.y = __float2bfloat16(v.w - __bfloat162float(h3));
    ((__nv_bfloat162*)lo)[i * 2 + 0] = la;
    ((__nv_bfloat162*)lo)[i * 2 + 1] = lb;
    ((__half2*)f16)[i * 2 + 0] = __floats2half2_rn(v.x, v.y);
    ((__half2*)f16)[i * 2 + 1] = __floats2half2_rn(v.z, v.w);
}

// ---------------- weight transpose + bf16 hi/lo split ----------------
__global__ void __launch_bounds__(256)
tsplit_kernel(const float* __restrict__ src, __nv_bfloat16* __restrict__ hi,
              __nv_bfloat16* __restrict__ lo, int K, int N)
{
    __shared__ float tile[32][33];
    const int tx = threadIdx.x & 31, ty = threadIdx.x >> 5;
    const int n0 = blockIdx.x * 32, k0 = blockIdx.y * 32;
#pragma unroll
    for (int i = 0; i < 4; i++)
        tile[ty + 8 * i][tx] = src[(size_t)(k0 + ty + 8 * i) * N + n0 + tx];
    __syncthreads();
#pragma unroll
    for (int i = 0; i < 4; i++) {
        const int n = n0 + ty + 8 * i, k = k0 + tx;
        const float v = tile[tx][ty + 8 * i];
        const __nv_bfloat16 h = __float2bfloat16(v);
        hi[(size_t)n * K + k] = h;
        lo[(size_t)n * K + k] = __float2bfloat16(v - __bfloat162float(h));
    }
}

// ---------------- weight transpose -> fp16 ----------------
__global__ void __launch_bounds__(256)
tsplitf_kernel(const float* __restrict__ src, __half* __restrict__ dst, int K, int N)
{
    __shared__ float tile[32][33];
    const int tx = threadIdx.x & 31, ty = threadIdx.x >> 5;
    const int n0 = blockIdx.x * 32, k0 = blockIdx.y * 32;
#pragma unroll
    for (int i = 0; i < 4; i++)
        tile[ty + 8 * i][tx] = src[(size_t)(k0 + ty + 8 * i) * N + n0 + tx];
    __syncthreads();
#pragma unroll
    for (int i = 0; i < 4; i++) {
        const int n = n0 + ty + 8 * i, k = k0 + tx;
        dst[(size_t)n * K + k] = __float2half(tile[tx][ty + 8 * i]);
    }
}

// ---------------- Sampled scores + fill chunk (5-way interleaved samples) ----------------
__global__ void compute_m_kernel(const int* __restrict__ idx, float* __restrict__ fillp)
{
    {
        const float c = 1.0f / Lz;
        const float4 f4 = make_float4(c, c, c, c);
        float4* dst = (float4*)fillp + (size_t)blockIdx.x * 512;
        __stcs(dst + threadIdx.x, f4);
        __stcs(dst + threadIdx.x + 256, f4);
    }

    const int gw = (blockIdx.x * blockDim.x + threadIdx.x) >> 5;
    const int lane = threadIdx.x & 31;
    const int l = gw & (Lz - 1);
    const int bh = gw >> 10;
    const int h = bh & (Hz - 1), b = bh >> 3;

    const float2* qrow = (const float2*)(g_Q + (size_t)(b * Lz + l) * DMz + h * DKz);
    const float2 q2 = qrow[lane];
    float mx = -INFINITY, sum = 0.f;
    // 35 = 7 x 5: unroll-by-5 puts 5 independent gather+shfl chains in flight
#pragma unroll 1
    for (int s0 = 0; s0 < Uz; s0 += 5) {
        float p[5];
#pragma unroll
        for (int q = 0; q < 5; q++) {
            const int j = idx[l * Uz + s0 + q];
            const float2 k2 = ((const float2*)(g_K + (size_t)(b * Lz + j) * DMz + h * DKz))[lane];
            p[q] = q2.x * k2.x + q2.y * k2.y;
        }
#pragma unroll
        for (int o = 16; o; o >>= 1) {
#pragma unroll
            for (int q = 0; q < 5; q++)
                p[q] += __shfl_xor_sync(0xffffffffu, p[q], o);
        }
#pragma unroll
        for (int q = 0; q < 5; q++) { mx = fmaxf(mx, p[q]); sum += p[q]; }
    }
    if (lane == 0) g_M[bh * Lz + l] = mx - sum * (1.0f / Uz);
}

// ---------------- top-35 per (b,h) ----------------
__global__ void __launch_bounds__(256) topk_kernel()
{
    const int bh = blockIdx.x;
    const int tid = threadIdx.x;
    const int wid = tid >> 5, lane = tid & 31;
    __shared__ float vals[Lz];
    __shared__ float wv[8];
    __shared__ int   wi[8];

    for (int l = tid; l < Lz; l += 256) {
        vals[l] = g_M[bh * Lz + l];
        g_rowmap[bh * Lz + l] = -1;
    }
    __syncthreads();

    for (int u = 0; u < Uz; u++) {
        float best = -INFINITY; int bi = 0x7fffffff;
#pragma unroll
        for (int c = 0; c < 4; c++) {
            const int l = tid + c * 256;
            const float v = vals[l];
            if (v > best) { best = v; bi = l; }
        }
#pragma unroll
        for (int o = 16; o; o >>= 1) {
            const float ov = __shfl_xor_sync(0xffffffffu, best, o);
            const int   oi = __shfl_xor_sync(0xffffffffu, bi, o);
            if (ov > best || (ov == best && oi < bi)) { best = ov; bi = oi; }
        }
        if (lane == 0) { wv[wid] = best; wi[wid] = bi; }
        __syncthreads();
        if (tid == 0) {
            float fb = wv[0]; int fi = wi[0];
#pragma unroll
            for (int w = 1; w < 8; w++) {
                if (wv[w] > fb || (wv[w] == fb && wi[w] < fi)) { fb = wv[w]; fi = wi[w]; }
            }
            g_Mtop[bh * Uz + u] = fi;
            g_rowmap[bh * Lz + fi] = u;
            vals[fi] = -INFINITY;
        }
        __syncthreads();
    }
}

// ---------------- scores = Q_top @ K^T / 8 ----------------
__global__ void __launch_bounds__(256) scores_kernel()
{
    const int bh = blockIdx.x;
    const int b = bh >> 3, h = bh & (Hz - 1);
    const int tid = threadIdx.x;
    __shared__ float Qr[Uz * DKz];

    for (int i = tid; i < Uz * DKz; i += 256) {
        const int u = i / DKz, d = i - u * DKz;
        const int l = g_Mtop[bh * Uz + u];
        Qr[i] = g_Q[(size_t)(b * Lz + l) * DMz + h * DKz + d];
    }
    __syncthreads();

    for (int l = tid; l < Lz; l += 256) {
        float acc[Uz];
#pragma unroll
        for (int u = 0; u < Uz; u++) acc[u] = 0.f;
        const float* krow = g_K + (size_t)(b * Lz + l) * DMz + h * DKz;
#pragma unroll 4
        for (int d = 0; d < DKz; d++) {
            const float kd = krow[d];
#pragma unroll
            for (int u = 0; u < Uz; u++) acc[u] += kd * Qr[u * DKz + d];
        }
#pragma unroll
        for (int u = 0; u < Uz; u++)
            g_attn[((size_t)bh * Uz + u) * Lz + l] = acc[u] * 0.125f;
    }
}

// ---------------- row softmax over L ----------------
__global__ void __launch_bounds__(256) softmax_kernel()
{
    const int row = blockIdx.x;
    float* p = g_attn + (size_t)row * Lz;
    const int tid = threadIdx.x;
    __shared__ float red[256];

    float4 v = ((float4*)p)[tid];
    float m = fmaxf(fmaxf(v.x, v.y), fmaxf(v.z, v.w));
    red[tid] = m; __syncthreads();
    for (int s = 128; s; s >>= 1) { if (tid < s) red[tid] = fmaxf(red[tid], red[tid + s]); __syncthreads(); }
    m = red[0]; __syncthreads();

    v.x = __expf(v.x - m); v.y = __expf(v.y - m);
    v.z = __expf(v.z - m); v.w = __expf(v.w - m);
    red[tid] = v.x + v.y + v.z + v.w; __syncthreads();
    for (int s = 128; s; s >>= 1) { if (tid < s) red[tid] += red[tid + s]; __syncthreads(); }
    const float inv = 1.0f / red[0];
    v.x *= inv; v.y *= inv; v.z *= inv; v.w *= inv;
    ((float4*)p)[tid] = v;
}

// ---------------- context (+fused V-mean) ----------------
__global__ void __launch_bounds__(256) context_kernel()
{
    const int bh = blockIdx.x;
    const int b = bh >> 3, h = bh & (Hz - 1);
    const int t = threadIdx.x;
    const int d = t & 63, ug = t >> 6;
    __shared__ float sat[Uz][129];

    float acc[9];
#pragma unroll
    for (int k = 0; k < 9; k++) acc[k] = 0.f;
    float vsum = 0.f;

    for (int c = 0; c < 8; c++) {
        for (int i = t; i < Uz * 128; i += 256) {
            const int u = i >> 7, li = i & 127;
            sat[u][li] = g_attn[((size_t)bh * Uz + u) * Lz + c * 128 + li];
        }
        __syncthreads();
        const float* vb = g_V + (size_t)(b * Lz + c * 128) * DMz + h * DVz + d;
#pragma unroll 4
        for (int i = 0; i < 128; i++) {
            const float v = vb[(size_t)i * DMz];
            vsum += v;
#pragma unroll
            for (int k = 0; k < 9; k++) {
                const int u = ug + 4 * k;
                if (u < Uz) acc[k] += sat[u][i] * v;
            }
        }
        __syncthreads();
    }
#pragma unroll
    for (int k = 0; k < 9; k++) {
        const int u = ug + 4 * k;
        if (u < Uz) g_ctxrow[(bh * Uz + u) * DVz + d] = acc[k];
    }
    if (ug == 0) g_vmean[bh * DVz + d] = vsum * (1.0f / Lz);
}

// ---------------- copy selected attn rows into pre-filled score output ----------------
__global__ void __launch_bounds__(256) copy_scores_kernel(float* __restrict__ outp)
{
    const int bhu = blockIdx.x;
    const int bh = bhu / Uz;
    const int l = g_Mtop[bhu];
    const float4* src = (const float4*)(g_attn + (size_t)bhu * Lz);
    float4* dst = (float4*)(outp + ((size_t)bh * Lz + l) * Lz);
    dst[threadIdx.x] = src[threadIdx.x];
}

// ---------------- assemble ctx -> fp16 ----------------
__global__ void __launch_bounds__(256) ctx_assemble_kernel(__half* __restrict__ dst)
{
    const size_t gidx = (size_t)blockIdx.x * 256 + threadIdx.x;
    const int row = (int)(gidx >> 9);
    const int c = (int)(gidx & 511);
    const int h = c >> 6, d = c & 63;
    const int b = row >> 10, l = row & (Lz - 1);
    const int bh = b * Hz + h;
    const int u = g_rowmap[bh * Lz + l];
    const float v = (u < 0) ? g_vmean[bh * DVz + d]
                            : g_ctxrow[(bh * Uz + u) * DVz + d];
    dst[gidx] = __float2half(v);
}

// ---------------- LayerNorm (512), optional fused fp16 output ----------------
__global__ void __launch_bounds__(256)
ln_kernel(const float* __restrict__ in, const float* __restrict__ g,
          const float* __restrict__ beta, float* __restrict__ out,
          __half* __restrict__ outf)
{
    const int row = blockIdx.x;
    const int tid = threadIdx.x;
    __shared__ float red[256];
    const float* r = in + (size_t)row * DMz;
    const float a = r[tid], b2 = r[tid + 256];

    red[tid] = a + b2; __syncthreads();
    for (int s = 128; s; s >>= 1) { if (tid < s) red[tid] += red[tid + s]; __syncthreads(); }
    const float mean = red[0] * (1.0f / DMz);
    __syncthreads();
    const float d0 = a - mean, d1 = b2 - mean;
    red[tid] = d0 * d0 + d1 * d1; __syncthreads();
    for (int s = 128; s; s >>= 1) { if (tid < s) red[tid] += red[tid + s]; __syncthreads(); }
    const float inv = rsqrtf(red[0] * (1.0f / DMz) + EPSz);
    const float o0 = g[tid]       * d0 * inv + beta[tid];
    const float o1 = g[tid + 256] * d1 * inv + beta[tid + 256];
    out[(size_t)row * DMz + tid]       = o0;
    out[(size_t)row * DMz + tid + 256] = o1;
    if (outf) {
        outf[(size_t)row * DMz + tid]       = __float2half(o0);
        outf[(size_t)row * DMz + tid + 256] = __float2half(o1);
    }
}

// ---------------- launch ----------------
extern "C" void kernel_launch(void* const* d_in, const int* in_sizes, int n_in,
                              void* d_out, int out_size)
{
    const float* x   = (const float*)d_in[0];
    const float* Wq  = (const float*)d_in[1];
    const float* bq  = (const float*)d_in[2];
    const float* Wk  = (const float*)d_in[3];
    const float* bk  = (const float*)d_in[4];
    const float* Wv  = (const float*)d_in[5];
    const float* bv  = (const float*)d_in[6];
    const float* Wo  = (const float*)d_in[7];
    const float* bo  = (const float*)d_in[8];
    const float* g1  = (const float*)d_in[9];
    const float* be1 = (const float*)d_in[10];
    const float* W1  = (const float*)d_in[11];
    const float* bf1 = (const float*)d_in[12];
    const float* W2  = (const float*)d_in[13];
    const float* bf2 = (const float*)d_in[14];
    const float* g2  = (const float*)d_in[15];
    const float* be2 = (const float*)d_in[16];
    const int*   idx = (const int*)d_in[17];
    float* out = (float*)d_out;
    float* score = out + (size_t)ROWSz * DMz;

    float *Qp, *Kp, *Vp, *yp, *x1p, *y2p;
    cudaGetSymbolAddress((void**)&Qp,   g_Q);
    cudaGetSymbolAddress((void**)&Kp,   g_K);
    cudaGetSymbolAddress((void**)&Vp,   g_V);
    cudaGetSymbolAddress((void**)&yp,   g_y);
    cudaGetSymbolAddress((void**)&x1p,  g_x1);
    cudaGetSymbolAddress((void**)&y2p,  g_y2);

    __nv_bfloat16 *xh, *xl, *WqTh, *WqTl, *WkTh, *WkTl;
    __half *xf, *cf, *x1f, *hf, *WvTf, *WoTf, *W1Tf, *W2Tf;
    cudaGetSymbolAddress((void**)&xh, g_xh);     cudaGetSymbolAddress((void**)&xl, g_xl);
    cudaGetSymbolAddress((void**)&WqTh, g_WqTh); cudaGetSymbolAddress((void**)&WqTl, g_WqTl);
    cudaGetSymbolAddress((void**)&WkTh, g_WkTh); cudaGetSymbolAddress((void**)&WkTl, g_WkTl);
    cudaGetSymbolAddress((void**)&xf, g_xf);     cudaGetSymbolAddress((void**)&cf, g_cf);
    cudaGetSymbolAddress((void**)&x1f, g_x1f);   cudaGetSymbolAddress((void**)&hf, g_hf);
    cudaGetSymbolAddress((void**)&WvTf, g_WvTf); cudaGetSymbolAddress((void**)&WoTf, g_WoTf);
    cudaGetSymbolAddress((void**)&W1Tf, g_W1Tf); cudaGetSymbolAddress((void**)&W2Tf, g_W2Tf);

    const int SM3 = 2 * 4 * TILEB;   // 81920
    const int SM1 = 2 * 2 * TILEB;   // 40960
    cudaFuncSetAttribute(gemm_kernel<3, true>,
                         cudaFuncAttributeMaxDynamicSharedMemorySize, SM3);
    cudaFuncSetAttribute(gemm_kernel<1, false>,
                         cudaFuncAttributeMaxDynamicSharedMemorySize, SM1);

    const dim3 gN512(4, 128);
    const dim3 gN2048(16, 128);

    // fill partition: 3 GEMM launches x 512 blocks x 65536 floats + compute_m 16384 x 2048
    const int FPB_GEMM = 65536;
    float* fill0 = score;
    float* fill1 = score + (size_t)512 * FPB_GEMM;
    float* fill2 = score + (size_t)1024 * FPB_GEMM;
    float* fill3 = score + (size_t)1536 * FPB_GEMM;

    // conversions for QKV (launch #6 = GEMM Q for ncu)
    split_x_kernel<<<(ROWSz * DMz) / 1024, 256>>>(x, xh, xl, xf);          // 1
    tsplit_kernel<<<dim3(16, 16), 256>>>(Wq, WqTh, WqTl, DMz, DMz);        // 2
    tsplit_kernel<<<dim3(16, 16), 256>>>(Wk, WkTh, WkTl, DMz, DMz);        // 3
    tsplitf_kernel<<<dim3(16, 16), 256>>>(Wv, WvTf, DMz, DMz);             // 4
    tsplitf_kernel<<<dim3(16, 16), 256>>>(Wo, WoTf, DMz, DMz);             // 5

    // QKV projections (+score fill)
    gemm_kernel<3, true><<<gN512, 256, SM3>>>((const uint16_t*)xh, (const uint16_t*)xl,
        (const uint16_t*)WqTh, (const uint16_t*)WqTl, bq, nullptr, Qp, nullptr,
        fill0, FPB_GEMM, ROWSz, DMz, DMz, 0);                              // 6 (ncu)
    gemm_kernel<3, true><<<gN512, 256, SM3>>>((const uint16_t*)xh, (const uint16_t*)xl,
        (const uint16_t*)WkTh, (const uint16_t*)WkTl, bk, nullptr, Kp, nullptr,
        fill1, FPB_GEMM, ROWSz, DMz, DMz, 0);                              // 7
    gemm_kernel<1, false><<<gN512, 256, SM1>>>((const uint16_t*)xf, nullptr,
        (const uint16_t*)WvTf, nullptr, bv, nullptr, Vp, nullptr,
        fill2, FPB_GEMM, ROWSz, DMz, DMz, 0);                              // 8

    // remaining weight conversions
    tsplitf_kernel<<<dim3(64, 16), 256>>>(W1, W1Tf, DMz, DHz);
    tsplitf_kernel<<<dim3(16, 64), 256>>>(W2, W2Tf, DHz, DMz);

    // ProbSparse attention
    compute_m_kernel<<<(BHz * Lz) / 8, 256>>>(idx, fill3);
    topk_kernel<<<BHz, 256>>>();
    scores_kernel<<<BHz, 256>>>();
    softmax_kernel<<<BHz * Uz, 256>>>();
    context_kernel<<<BHz, 256>>>();
    copy_scores_kernel<<<BHz * Uz, 256>>>(score);
    ctx_assemble_kernel<<<(ROWSz * DMz) / 256, 256>>>(cf);

    // Wo projection + residual, LN1 (fused fp16 x1)
    gemm_kernel<1, false><<<gN512, 256, SM1>>>((const uint16_t*)cf, nullptr,
        (const uint16_t*)WoTf, nullptr, bo, x, yp, nullptr,
        nullptr, 0, ROWSz, DMz, DMz, 1);
    ln_kernel<<<ROWSz, 256>>>(yp, g1, be1, x1p, x1f);

    // FFN
    gemm_kernel<1, false><<<gN2048, 256, SM1>>>((const uint16_t*)x1f, nullptr,
        (const uint16_t*)W1Tf, nullptr, bf1, nullptr, nullptr, (uint16_t*)hf,
        nullptr, 0, ROWSz, DHz, DMz, 2);
    gemm_kernel<1, false><<<gN512, 256, SM1>>>((const uint16_t*)hf, nullptr,
        (const uint16_t*)W2Tf, nullptr, bf2, x1p, y2p, nullptr,
        nullptr, 0, ROWSz, DMz, DHz, 1);
    ln_kernel<<<ROWSz, 256>>>(y2p, g2, be2, out, nullptr);
}

// round 14
// speedup vs baseline: 1.0726x; 1.0200x over previous
#include <cuda_runtime.h>
#include <cuda_bf16.h>
#include <cuda_fp16.h>
#include <math.h>
#include <stdint.h>

// ---------------- Problem constants ----------------
#define Bz   16
#define Lz   1024
#define DMz  512
#define Hz   8
#define DKz  64
#define DVz  64
#define DHz  2048
#define Uz   35
#define BHz  (Bz*Hz)     // 128
#define ROWSz (Bz*Lz)    // 16384
#define EPSz 1e-5f

// ---------------- fp32 scratch ----------------
__device__ float g_Q[ROWSz*DMz];
__device__ float g_K[ROWSz*DMz];
__device__ float g_V[ROWSz*DMz];
__device__ float g_M[BHz*Lz];
__device__ int   g_Mtop[BHz*Uz];
__device__ int   g_rowmap[BHz*Lz];
__device__ float g_attn[(size_t)BHz*Uz*Lz];
__device__ float g_ctxrow[BHz*Uz*DVz];
__device__ float g_vmean[BHz*DVz];
__device__ float g_y[ROWSz*DMz];
__device__ float g_x1[ROWSz*DMz];
__device__ float g_y2[ROWSz*DMz];

// ---------------- bf16 split scratch (Q/K path, 3-term) ----------------
__device__ __nv_bfloat16 g_xh[ROWSz*DMz], g_xl[ROWSz*DMz];
__device__ __nv_bfloat16 g_WqTh[DMz*DMz], g_WqTl[DMz*DMz];
__device__ __nv_bfloat16 g_WkTh[DMz*DMz], g_WkTl[DMz*DMz];

// ---------------- fp16 scratch (V/Wo/FFN path, single-pass) ----------------
__device__ __half g_xf[ROWSz*DMz];
__device__ __half g_cf[ROWSz*DMz];
__device__ __half g_x1f[ROWSz*DMz];
__device__ __half g_hf[(size_t)ROWSz*DHz];
__device__ __half g_WvTf[DMz*DMz];
__device__ __half g_WoTf[DMz*DMz];
__device__ __half g_W1Tf[DMz*DHz];
__device__ __half g_W2Tf[DHz*DMz];

// ---------------- helpers ----------------
__device__ __forceinline__ void cp16(uint32_t s, const void* g) {
    asm volatile("cp.async.cg.shared.global [%0], [%1], 16;"
                 :: "r"(s), "l"(__cvta_generic_to_global(g)));
}
__device__ __forceinline__ void cp_commit() {
    asm volatile("cp.async.commit_group;" ::: "memory");
}
__device__ __forceinline__ void ldm_x4(uint32_t& r0, uint32_t& r1, uint32_t& r2, uint32_t& r3,
                                       uint32_t addr) {
    asm volatile("ldmatrix.sync.aligned.m8n8.x4.shared.b16 {%0,%1,%2,%3}, [%4];"
                 : "=r"(r0), "=r"(r1), "=r"(r2), "=r"(r3) : "r"(addr));
}
template<bool ISBF16>
__device__ __forceinline__ void mma_t(float* c, const uint32_t* a, const uint32_t* b) {
    if constexpr (ISBF16)
        asm volatile("mma.sync.aligned.m16n8k16.row.col.f32.bf16.bf16.f32 "
                     "{%0,%1,%2,%3}, {%4,%5,%6,%7}, {%8,%9}, {%0,%1,%2,%3};"
                     : "+f"(c[0]), "+f"(c[1]), "+f"(c[2]), "+f"(c[3])
                     : "r"(a[0]), "r"(a[1]), "r"(a[2]), "r"(a[3]), "r"(b[0]), "r"(b[1]));
    else
        asm volatile("mma.sync.aligned.m16n8k16.row.col.f32.f16.f16.f32 "
                     "{%0,%1,%2,%3}, {%4,%5,%6,%7}, {%8,%9}, {%0,%1,%2,%3};"
                     : "+f"(c[0]), "+f"(c[1]), "+f"(c[2]), "+f"(c[3])
                     : "r"(a[0]), "r"(a[1]), "r"(a[2]), "r"(a[3]), "r"(b[0]), "r"(b[1]));
}

// ---------------- mma.sync GEMM, templated <TERMS, ISBF16> ----------------
// BM=BN=128, warp 64x32, occupancy 2.
// TERMS=3 (bf16 split): 2-stage (4 tiles/stage). TERMS=1 (fp16): 3-stage ring.
#define ROWB 80
#define TILEB (128 * ROWB)

template<int TERMS, bool ISBF16>
__global__ void __launch_bounds__(256, 2)
gemm_kernel(const uint16_t* __restrict__ Ahi, const uint16_t* __restrict__ Alo,
            const uint16_t* __restrict__ Bhi, const uint16_t* __restrict__ Blo,
            const float* __restrict__ bias, const float* __restrict__ res,
            float* __restrict__ C, uint16_t* __restrict__ Chi,
            float* __restrict__ fillp, int fillPerBlk,
            int M, int N, int K, int eop)
{
    constexpr int NT = (TERMS == 3) ? 4 : 2;          // tiles per stage
    constexpr int NSTAGE = (TERMS == 3) ? 2 : 3;      // pipeline depth
    constexpr uint32_t STG = NT * TILEB;
    extern __shared__ __align__(16) char smem[];
    const uint32_t smem_u = (uint32_t)__cvta_generic_to_shared(smem);

    const int tid = threadIdx.x;
    const int wid = tid >> 5, lane = tid & 31;
    const int wm = (wid >> 2) * 64;
    const int wn = (wid & 3) * 32;
    const int g = lane >> 3, r = lane & 7;
    const int bm = blockIdx.y * 128;
    const int bn = blockIdx.x * 128;

    const int kt = K >> 5;

    float acc[4][4][4];
#pragma unroll
    for (int i = 0; i < 4; i++)
#pragma unroll
        for (int j = 0; j < 4; j++)
#pragma unroll
            for (int c = 0; c < 4; c++) acc[i][j][c] = 0.f;

    const int ar = tid >> 2, ac = tid & 3;

    auto load_tile = [&](int it, int buf) {
        const int kk = it << 5;
        const uint32_t s0 = smem_u + buf * STG;
        const size_t gaof = (size_t)(bm + ar) * K + kk + ac * 8;
        const size_t gbof = (size_t)(bn + ar) * K + kk + ac * 8;
        const size_t rowK64 = (size_t)64 * K;
        const uint32_t sof = ar * ROWB + ac * 16;
        cp16(s0 + sof, Ahi + gaof);
        cp16(s0 + sof + 64 * ROWB, Ahi + gaof + rowK64);
        if constexpr (TERMS == 3) {
            cp16(s0 + TILEB + sof, Alo + gaof);
            cp16(s0 + TILEB + sof + 64 * ROWB, Alo + gaof + rowK64);
            cp16(s0 + 2 * TILEB + sof, Bhi + gbof);
            cp16(s0 + 2 * TILEB + sof + 64 * ROWB, Bhi + gbof + rowK64);
            cp16(s0 + 3 * TILEB + sof, Blo + gbof);
            cp16(s0 + 3 * TILEB + sof + 64 * ROWB, Blo + gbof + rowK64);
        } else {
            cp16(s0 + TILEB + sof, Bhi + gbof);
            cp16(s0 + TILEB + sof + 64 * ROWB, Bhi + gbof + rowK64);
        }
        cp_commit();
    };

#pragma unroll
    for (int p = 0; p < NSTAGE - 1; p++)
        if (p < kt) load_tile(p, p);

    int buf = 0;
    for (int it = 0; it < kt; it++) {
        // tiles loaded so far: up to it + NSTAGE - 2. Allow the newer ones to stay pending.
        if (it + NSTAGE - 2 < kt && NSTAGE == 3) {
            asm volatile("cp.async.wait_group 1;" ::: "memory");
        } else {
            asm volatile("cp.async.wait_group 0;" ::: "memory");
        }
        __syncthreads();   // tile `it` visible; all warps done with the slot being refilled

        if (it + NSTAGE - 1 < kt) {
            int nb = buf + NSTAGE - 1; if (nb >= NSTAGE) nb -= NSTAGE;
            load_tile(it + NSTAGE - 1, nb);
        }

        const uint32_t sAh = smem_u + buf * STG;
        const uint32_t sBh = sAh + ((TERMS == 3) ? 2 : 1) * TILEB;
#pragma unroll
        for (int s = 0; s < 2; s++) {
            const int chkA = 2 * s + (g >> 1);
            const int chkB = 2 * s + (g & 1);
            const uint32_t aoff = (wm + ((g & 1) << 3) + r) * ROWB + chkA * 16;
            const uint32_t boff = (wn + ((g >> 1) << 3) + r) * ROWB + chkB * 16;

            uint32_t ah[4][4];
#pragma unroll
            for (int mf = 0; mf < 4; mf++)
                ldm_x4(ah[mf][0], ah[mf][1], ah[mf][2], ah[mf][3], sAh + aoff + mf * 16 * ROWB);
            uint32_t bh[4][2];
#pragma unroll
            for (int ng = 0; ng < 2; ng++)
                ldm_x4(bh[2 * ng][0], bh[2 * ng][1], bh[2 * ng + 1][0], bh[2 * ng + 1][1],
                       sBh + boff + ng * 16 * ROWB);

            if constexpr (TERMS == 3) {
                const uint32_t sAl = sAh + TILEB;
                const uint32_t sBl = sAh + 3 * TILEB;
                uint32_t bl[4][2];
#pragma unroll
                for (int ng = 0; ng < 2; ng++)
                    ldm_x4(bl[2 * ng][0], bl[2 * ng][1], bl[2 * ng + 1][0], bl[2 * ng + 1][1],
                           sBl + boff + ng * 16 * ROWB);
#pragma unroll
                for (int mf = 0; mf < 4; mf++)
#pragma unroll
                    for (int nf = 0; nf < 4; nf++) {
                        mma_t<ISBF16>(acc[mf][nf], ah[mf], bh[nf]);
                        mma_t<ISBF16>(acc[mf][nf], ah[mf], bl[nf]);
                    }
#pragma unroll
                for (int mf = 0; mf < 4; mf++)
                    ldm_x4(ah[mf][0], ah[mf][1], ah[mf][2], ah[mf][3], sAl + aoff + mf * 16 * ROWB);
#pragma unroll
                for (int mf = 0; mf < 4; mf++)
#pragma unroll
                    for (int nf = 0; nf < 4; nf++)
                        mma_t<ISBF16>(acc[mf][nf], ah[mf], bh[nf]);
            } else {
#pragma unroll
                for (int mf = 0; mf < 4; mf++)
#pragma unroll
                    for (int nf = 0; nf < 4; nf++)
                        mma_t<ISBF16>(acc[mf][nf], ah[mf], bh[nf]);
            }
        }
        if (++buf >= NSTAGE) buf = 0;
    }

    // epilogue
    const int rl = lane >> 2, cl = (lane & 3) * 2;
#pragma unroll
    for (int mf = 0; mf < 4; mf++) {
        const int row0 = bm + wm + mf * 16 + rl;
#pragma unroll
        for (int nf = 0; nf < 4; nf++) {
            const int col = bn + wn + nf * 8 + cl;
            const float b0 = bias[col], b1 = bias[col + 1];
            float v0 = acc[mf][nf][0] + b0, v1 = acc[mf][nf][1] + b1;
            float v2 = acc[mf][nf][2] + b0, v3 = acc[mf][nf][3] + b1;
            if (eop == 1) {
                const float* r0 = res + (size_t)row0 * N + col;
                const float* r1 = res + (size_t)(row0 + 8) * N + col;
                v0 += r0[0]; v1 += r0[1]; v2 += r1[0]; v3 += r1[1];
            } else if (eop == 2) {
                v0 = fmaxf(v0, 0.f); v1 = fmaxf(v1, 0.f);
                v2 = fmaxf(v2, 0.f); v3 = fmaxf(v3, 0.f);
                *(__half2*)(Chi + (size_t)row0 * N + col)       = __floats2half2_rn(v0, v1);
                *(__half2*)(Chi + (size_t)(row0 + 8) * N + col) = __floats2half2_rn(v2, v3);
                continue;
            }
            *(float2*)(C + (size_t)row0 * N + col) = make_float2(v0, v1);
            *(float2*)(C + (size_t)(row0 + 8) * N + col) = make_float2(v2, v3);
        }
    }

    // piggybacked constant fill of the score output (streaming stores)
    if (fillp) {
        const int nv4 = fillPerBlk >> 2;
        const int blin = blockIdx.y * gridDim.x + blockIdx.x;
        float4* dst = (float4*)fillp + (size_t)blin * nv4;
        const float c = 1.0f / Lz;
        const float4 f4 = make_float4(c, c, c, c);
        for (int i = tid; i < nv4; i += 256) __stcs(dst + i, f4);
    }
}

// ---------------- x -> bf16 hi/lo + fp16, one read ----------------
__global__ void __launch_bounds__(256)
split_x_kernel(const float* __restrict__ src, __nv_bfloat16* __restrict__ hi,
               __nv_bfloat16* __restrict__ lo, __half* __restrict__ f16)
{
    const size_t i = (size_t)blockIdx.x * 256 + threadIdx.x;
    const float4 v = ((const float4*)src)[i];
    __nv_bfloat16 h0 = __float2bfloat16(v.x), h1 = __float2bfloat16(v.y);
    __nv_bfloat16 h2 = __float2bfloat16(v.z), h3 = __float2bfloat16(v.w);
    __nv_bfloat162 ha; ha.x = h0; ha.y = h1;
    __nv_bfloat162 hb; hb.x = h2; hb.y = h3;
    ((__nv_bfloat162*)hi)[i * 2 + 0] = ha;
    ((__nv_bfloat162*)hi)[i * 2 + 1] = hb;
    __nv_bfloat162 la, lb;
    la.x = __float2bfloat16(v.x - __bfloat162float(h0));
    la.y = __float2bfloat16(v.y - __bfloat162float(h1));
    lb.x = __float2bfloat16(v.z - __bfloat162float(h2));
    lb.y = __float2bfloat16(v.w - __bfloat162float(h3));
    ((__nv_bfloat162*)lo)[i * 2 + 0] = la;
    ((__nv_bfloat162*)lo)[i * 2 + 1] = lb;
    ((__half2*)f16)[i * 2 + 0] = __floats2half2_rn(v.x, v.y);
    ((__half2*)f16)[i * 2 + 1] = __floats2half2_rn(v.z, v.w);
}

// ---------------- weight transpose + bf16 hi/lo split ----------------
__global__ void __launch_bounds__(256)
tsplit_kernel(const float* __restrict__ src, __nv_bfloat16* __restrict__ hi,
              __nv_bfloat16* __restrict__ lo, int K, int N)
{
    __shared__ float tile[32][33];
    const int tx = threadIdx.x & 31, ty = threadIdx.x >> 5;
    const int n0 = blockIdx.x * 32, k0 = blockIdx.y * 32;
#pragma unroll
    for (int i = 0; i < 4; i++)
        tile[ty + 8 * i][tx] = src[(size_t)(k0 + ty + 8 * i) * N + n0 + tx];
    __syncthreads();
#pragma unroll
    for (int i = 0; i < 4; i++) {
        const int n = n0 + ty + 8 * i, k = k0 + tx;
        const float v = tile[tx][ty + 8 * i];
        const __nv_bfloat16 h = __float2bfloat16(v);
        hi[(size_t)n * K + k] = h;
        lo[(size_t)n * K + k] = __float2bfloat16(v - __bfloat162float(h));
    }
}

// ---------------- weight transpose -> fp16 ----------------
__global__ void __launch_bounds__(256)
tsplitf_kernel(const float* __restrict__ src, __half* __restrict__ dst, int K, int N)
{
    __shared__ float tile[32][33];
    const int tx = threadIdx.x & 31, ty = threadIdx.x >> 5;
    const int n0 = blockIdx.x * 32, k0 = blockIdx.y * 32;
#pragma unroll
    for (int i = 0; i < 4; i++)
        tile[ty + 8 * i][tx] = src[(size_t)(k0 + ty + 8 * i) * N + n0 + tx];
    __syncthreads();
#pragma unroll
    for (int i = 0; i < 4; i++) {
        const int n = n0 + ty + 8 * i, k = k0 + tx;
        dst[(size_t)n * K + k] = __float2half(tile[tx][ty + 8 * i]);
    }
}

// ---------------- Sampled scores + fill chunk (5-way interleaved samples) ----------------
__global__ void compute_m_kernel(const int* __restrict__ idx, float* __restrict__ fillp)
{
    {
        const float c = 1.0f / Lz;
        const float4 f4 = make_float4(c, c, c, c);
        float4* dst = (float4*)fillp + (size_t)blockIdx.x * 512;
        __stcs(dst + threadIdx.x, f4);
        __stcs(dst + threadIdx.x + 256, f4);
    }

    const int gw = (blockIdx.x * blockDim.x + threadIdx.x) >> 5;
    const int lane = threadIdx.x & 31;
    const int l = gw & (Lz - 1);
    const int bh = gw >> 10;
    const int h = bh & (Hz - 1), b = bh >> 3;

    const float2* qrow = (const float2*)(g_Q + (size_t)(b * Lz + l) * DMz + h * DKz);
    const float2 q2 = qrow[lane];
    float mx = -INFINITY, sum = 0.f;
#pragma unroll 1
    for (int s0 = 0; s0 < Uz; s0 += 5) {
        float p[5];
#pragma unroll
        for (int q = 0; q < 5; q++) {
            const int j = idx[l * Uz + s0 + q];
            const float2 k2 = ((const float2*)(g_K + (size_t)(b * Lz + j) * DMz + h * DKz))[lane];
            p[q] = q2.x * k2.x + q2.y * k2.y;
        }
#pragma unroll
        for (int o = 16; o; o >>= 1) {
#pragma unroll
            for (int q = 0; q < 5; q++)
                p[q] += __shfl_xor_sync(0xffffffffu, p[q], o);
        }
#pragma unroll
        for (int q = 0; q < 5; q++) { mx = fmaxf(mx, p[q]); sum += p[q]; }
    }
    if (lane == 0) g_M[bh * Lz + l] = mx - sum * (1.0f / Uz);
}

// ---------------- top-35 per (b,h) ----------------
__global__ void __launch_bounds__(256) topk_kernel()
{
    const int bh = blockIdx.x;
    const int tid = threadIdx.x;
    const int wid = tid >> 5, lane = tid & 31;
    __shared__ float vals[Lz];
    __shared__ float wv[8];
    __shared__ int   wi[8];

    for (int l = tid; l < Lz; l += 256) {
        vals[l] = g_M[bh * Lz + l];
        g_rowmap[bh * Lz + l] = -1;
    }
    __syncthreads();

    for (int u = 0; u < Uz; u++) {
        float best = -INFINITY; int bi = 0x7fffffff;
#pragma unroll
        for (int c = 0; c < 4; c++) {
            const int l = tid + c * 256;
            const float v = vals[l];
            if (v > best) { best = v; bi = l; }
        }
#pragma unroll
        for (int o = 16; o; o >>= 1) {
            const float ov = __shfl_xor_sync(0xffffffffu, best, o);
            const int   oi = __shfl_xor_sync(0xffffffffu, bi, o);
            if (ov > best || (ov == best && oi < bi)) { best = ov; bi = oi; }
        }
        if (lane == 0) { wv[wid] = best; wi[wid] = bi; }
        __syncthreads();
        if (tid == 0) {
            float fb = wv[0]; int fi = wi[0];
#pragma unroll
            for (int w = 1; w < 8; w++) {
                if (wv[w] > fb || (wv[w] == fb && wi[w] < fi)) { fb = wv[w]; fi = wi[w]; }
            }
            g_Mtop[bh * Uz + u] = fi;
            g_rowmap[bh * Lz + fi] = u;
            vals[fi] = -INFINITY;
        }
        __syncthreads();
    }
}

// ---------------- scores = Q_top @ K^T / 8 ----------------
__global__ void __launch_bounds__(256) scores_kernel()
{
    const int bh = blockIdx.x;
    const int b = bh >> 3, h = bh & (Hz - 1);
    const int tid = threadIdx.x;
    __shared__ float Qr[Uz * DKz];

    for (int i = tid; i < Uz * DKz; i += 256) {
        const int u = i / DKz, d = i - u * DKz;
        const int l = g_Mtop[bh * Uz + u];
        Qr[i] = g_Q[(size_t)(b * Lz + l) * DMz + h * DKz + d];
    }
    __syncthreads();

    for (int l = tid; l < Lz; l += 256) {
        float acc[Uz];
#pragma unroll
        for (int u = 0; u < Uz; u++) acc[u] = 0.f;
        const float* krow = g_K + (size_t)(b * Lz + l) * DMz + h * DKz;
#pragma unroll 4
        for (int d = 0; d < DKz; d++) {
            const float kd = krow[d];
#pragma unroll
            for (int u = 0; u < Uz; u++) acc[u] += kd * Qr[u * DKz + d];
        }
#pragma unroll
        for (int u = 0; u < Uz; u++)
            g_attn[((size_t)bh * Uz + u) * Lz + l] = acc[u] * 0.125f;
    }
}

// ---------------- row softmax over L (+ fused score-output write) ----------------
__global__ void __launch_bounds__(256) softmax_kernel(float* __restrict__ outp)
{
    const int row = blockIdx.x;          // bh*Uz + u
    float* p = g_attn + (size_t)row * Lz;
    const int tid = threadIdx.x;
    __shared__ float red[256];

    float4 v = ((float4*)p)[tid];
    float m = fmaxf(fmaxf(v.x, v.y), fmaxf(v.z, v.w));
    red[tid] = m; __syncthreads();
    for (int s = 128; s; s >>= 1) { if (tid < s) red[tid] = fmaxf(red[tid], red[tid + s]); __syncthreads(); }
    m = red[0]; __syncthreads();

    v.x = __expf(v.x - m); v.y = __expf(v.y - m);
    v.z = __expf(v.z - m); v.w = __expf(v.w - m);
    red[tid] = v.x + v.y + v.z + v.w; __syncthreads();
    for (int s = 128; s; s >>= 1) { if (tid < s) red[tid] += red[tid + s]; __syncthreads(); }
    const float inv = 1.0f / red[0];
    v.x *= inv; v.y *= inv; v.z *= inv; v.w *= inv;
    ((float4*)p)[tid] = v;

    // fused: write this attention row straight into the pre-filled score output
    const int bh = row / Uz;
    const int l = g_Mtop[row];
    __stcs((float4*)(outp + ((size_t)bh * Lz + l) * Lz) + tid, v);
}

// ---------------- context (+fused V-mean) ----------------
__global__ void __launch_bounds__(256) context_kernel()
{
    const int bh = blockIdx.x;
    const int b = bh >> 3, h = bh & (Hz - 1);
    const int t = threadIdx.x;
    const int d = t & 63, ug = t >> 6;
    __shared__ float sat[Uz][129];

    float acc[9];
#pragma unroll
    for (int k = 0; k < 9; k++) acc[k] = 0.f;
    float vsum = 0.f;

    for (int c = 0; c < 8; c++) {
        for (int i = t; i < Uz * 128; i += 256) {
            const int u = i >> 7, li = i & 127;
            sat[u][li] = g_attn[((size_t)bh * Uz + u) * Lz + c * 128 + li];
        }
        __syncthreads();
        const float* vb = g_V + (size_t)(b * Lz + c * 128) * DMz + h * DVz + d;
#pragma unroll 4
        for (int i = 0; i < 128; i++) {
            const float v = vb[(size_t)i * DMz];
            vsum += v;
#pragma unroll
            for (int k = 0; k < 9; k++) {
                const int u = ug + 4 * k;
                if (u < Uz) acc[k] += sat[u][i] * v;
            }
        }
        __syncthreads();
    }
#pragma unroll
    for (int k = 0; k < 9; k++) {
        const int u = ug + 4 * k;
        if (u < Uz) g_ctxrow[(bh * Uz + u) * DVz + d] = acc[k];
    }
    if (ug == 0) g_vmean[bh * DVz + d] = vsum * (1.0f / Lz);
}

// ---------------- assemble ctx -> fp16 ----------------
__global__ void __launch_bounds__(256) ctx_assemble_kernel(__half* __restrict__ dst)
{
    const size_t gidx = (size_t)blockIdx.x * 256 + threadIdx.x;
    const int row = (int)(gidx >> 9);
    const int c = (int)(gidx & 511);
    const int h = c >> 6, d = c & 63;
    const int b = row >> 10, l = row & (Lz - 1);
    const int bh = b * Hz + h;
    const int u = g_rowmap[bh * Lz + l];
    const float v = (u < 0) ? g_vmean[bh * DVz + d]
                            : g_ctxrow[(bh * Uz + u) * DVz + d];
    dst[gidx] = __float2half(v);
}

// ---------------- LayerNorm (512), optional fused fp16 output ----------------
__global__ void __launch_bounds__(256)
ln_kernel(const float* __restrict__ in, const float* __restrict__ g,
          const float* __restrict__ beta, float* __restrict__ out,
          __half* __restrict__ outf)
{
    const int row = blockIdx.x;
    const int tid = threadIdx.x;
    __shared__ float red[256];
    const float* r = in + (size_t)row * DMz;
    const float a = r[tid], b2 = r[tid + 256];

    red[tid] = a + b2; __syncthreads();
    for (int s = 128; s; s >>= 1) { if (tid < s) red[tid] += red[tid + s]; __syncthreads(); }
    const float mean = red[0] * (1.0f / DMz);
    __syncthreads();
    const float d0 = a - mean, d1 = b2 - mean;
    red[tid] = d0 * d0 + d1 * d1; __syncthreads();
    for (int s = 128; s; s >>= 1) { if (tid < s) red[tid] += red[tid + s]; __syncthreads(); }
    const float inv = rsqrtf(red[0] * (1.0f / DMz) + EPSz);
    const float o0 = g[tid]       * d0 * inv + beta[tid];
    const float o1 = g[tid + 256] * d1 * inv + beta[tid + 256];
    out[(size_t)row * DMz + tid]       = o0;
    out[(size_t)row * DMz + tid + 256] = o1;
    if (outf) {
        outf[(size_t)row * DMz + tid]       = __float2half(o0);
        outf[(size_t)row * DMz + tid + 256] = __float2half(o1);
    }
}

// ---------------- launch ----------------
extern "C" void kernel_launch(void* const* d_in, const int* in_sizes, int n_in,
                              void* d_out, int out_size)
{
    const float* x   = (const float*)d_in[0];
    const float* Wq  = (const float*)d_in[1];
    const float* bq  = (const float*)d_in[2];
    const float* Wk  = (const float*)d_in[3];
    const float* bk  = (const float*)d_in[4];
    const float* Wv  = (const float*)d_in[5];
    const float* bv  = (const float*)d_in[6];
    const float* Wo  = (const float*)d_in[7];
    const float* bo  = (const float*)d_in[8];
    const float* g1  = (const float*)d_in[9];
    const float* be1 = (const float*)d_in[10];
    const float* W1  = (const float*)d_in[11];
    const float* bf1 = (const float*)d_in[12];
    const float* W2  = (const float*)d_in[13];
    const float* bf2 = (const float*)d_in[14];
    const float* g2  = (const float*)d_in[15];
    const float* be2 = (const float*)d_in[16];
    const int*   idx = (const int*)d_in[17];
    float* out = (float*)d_out;
    float* score = out + (size_t)ROWSz * DMz;

    float *Qp, *Kp, *Vp, *yp, *x1p, *y2p;
    cudaGetSymbolAddress((void**)&Qp,   g_Q);
    cudaGetSymbolAddress((void**)&Kp,   g_K);
    cudaGetSymbolAddress((void**)&Vp,   g_V);
    cudaGetSymbolAddress((void**)&yp,   g_y);
    cudaGetSymbolAddress((void**)&x1p,  g_x1);
    cudaGetSymbolAddress((void**)&y2p,  g_y2);

    __nv_bfloat16 *xh, *xl, *WqTh, *WqTl, *WkTh, *WkTl;
    __half *xf, *cf, *x1f, *hf, *WvTf, *WoTf, *W1Tf, *W2Tf;
    cudaGetSymbolAddress((void**)&xh, g_xh);     cudaGetSymbolAddress((void**)&xl, g_xl);
    cudaGetSymbolAddress((void**)&WqTh, g_WqTh); cudaGetSymbolAddress((void**)&WqTl, g_WqTl);
    cudaGetSymbolAddress((void**)&WkTh, g_WkTh); cudaGetSymbolAddress((void**)&WkTl, g_WkTl);
    cudaGetSymbolAddress((void**)&xf, g_xf);     cudaGetSymbolAddress((void**)&cf, g_cf);
    cudaGetSymbolAddress((void**)&x1f, g_x1f);   cudaGetSymbolAddress((void**)&hf, g_hf);
    cudaGetSymbolAddress((void**)&WvTf, g_WvTf); cudaGetSymbolAddress((void**)&WoTf, g_WoTf);
    cudaGetSymbolAddress((void**)&W1Tf, g_W1Tf); cudaGetSymbolAddress((void**)&W2Tf, g_W2Tf);

    const int SM3 = 2 * 4 * TILEB;   // 81920 (2-stage x 4 tiles)
    const int SM1 = 3 * 2 * TILEB;   // 61440 (3-stage x 2 tiles)
    cudaFuncSetAttribute(gemm_kernel<3, true>,
                         cudaFuncAttributeMaxDynamicSharedMemorySize, SM3);
    cudaFuncSetAttribute(gemm_kernel<1, false>,
                         cudaFuncAttributeMaxDynamicSharedMemorySize, SM1);

    const dim3 gN512(4, 128);
    const dim3 gN2048(16, 128);

    // fill partition: 3 GEMM launches x 512 blocks x 65536 floats + compute_m 16384 x 2048
    const int FPB_GEMM = 65536;
    float* fill0 = score;
    float* fill1 = score + (size_t)512 * FPB_GEMM;
    float* fill2 = score + (size_t)1024 * FPB_GEMM;
    float* fill3 = score + (size_t)1536 * FPB_GEMM;

    // conversions for QKV (launch #6 = GEMM Q for ncu)
    split_x_kernel<<<(ROWSz * DMz) / 1024, 256>>>(x, xh, xl, xf);          // 1
    tsplit_kernel<<<dim3(16, 16), 256>>>(Wq, WqTh, WqTl, DMz, DMz);        // 2
    tsplit_kernel<<<dim3(16, 16), 256>>>(Wk, WkTh, WkTl, DMz, DMz);        // 3
    tsplitf_kernel<<<dim3(16, 16), 256>>>(Wv, WvTf, DMz, DMz);             // 4
    tsplitf_kernel<<<dim3(16, 16), 256>>>(Wo, WoTf, DMz, DMz);             // 5

    // QKV projections (+score fill)
    gemm_kernel<3, true><<<gN512, 256, SM3>>>((const uint16_t*)xh, (const uint16_t*)xl,
        (const uint16_t*)WqTh, (const uint16_t*)WqTl, bq, nullptr, Qp, nullptr,
        fill0, FPB_GEMM, ROWSz, DMz, DMz, 0);                              // 6 (ncu)
    gemm_kernel<3, true><<<gN512, 256, SM3>>>((const uint16_t*)xh, (const uint16_t*)xl,
        (const uint16_t*)WkTh, (const uint16_t*)WkTl, bk, nullptr, Kp, nullptr,
        fill1, FPB_GEMM, ROWSz, DMz, DMz, 0);                              // 7
    gemm_kernel<1, false><<<gN512, 256, SM1>>>((const uint16_t*)xf, nullptr,
        (const uint16_t*)WvTf, nullptr, bv, nullptr, Vp, nullptr,
        fill2, FPB_GEMM, ROWSz, DMz, DMz, 0);                              // 8

    // remaining weight conversions
    tsplitf_kernel<<<dim3(64, 16), 256>>>(W1, W1Tf, DMz, DHz);
    tsplitf_kernel<<<dim3(16, 64), 256>>>(W2, W2Tf, DHz, DMz);

    // ProbSparse attention
    compute_m_kernel<<<(BHz * Lz) / 8, 256>>>(idx, fill3);
    topk_kernel<<<BHz, 256>>>();
    scores_kernel<<<BHz, 256>>>();
    softmax_kernel<<<BHz * Uz, 256>>>(score);   // fused score-output write
    context_kernel<<<BHz, 256>>>();
    ctx_assemble_kernel<<<(ROWSz * DMz) / 256, 256>>>(cf);

    // Wo projection + residual, LN1 (fused fp16 x1)
    gemm_kernel<1, false><<<gN512, 256, SM1>>>((const uint16_t*)cf, nullptr,
        (const uint16_t*)WoTf, nullptr, bo, x, yp, nullptr,
        nullptr, 0, ROWSz, DMz, DMz, 1);
    ln_kernel<<<ROWSz, 256>>>(yp, g1, be1, x1p, x1f);

    // FFN
    gemm_kernel<1, false><<<gN2048, 256, SM1>>>((const uint16_t*)x1f, nullptr,
        (const uint16_t*)W1Tf, nullptr, bf1, nullptr, nullptr, (uint16_t*)hf,
        nullptr, 0, ROWSz, DHz, DMz, 2);
    gemm_kernel<1, false><<<gN512, 256, SM1>>>((const uint16_t*)hf, nullptr,
        (const uint16_t*)W2Tf, nullptr, bf2, x1p, y2p, nullptr,
        nullptr, 0, ROWSz, DMz, DHz, 1);
    ln_kernel<<<ROWSz, 256>>>(y2p, g2, be2, out, nullptr);
}

// round 15
// speedup vs baseline: 1.0787x; 1.0056x over previous
#include <cuda_runtime.h>
#include <cuda_bf16.h>
#include <cuda_fp16.h>
#include <math.h>
#include <stdint.h>

// ---------------- Problem constants ----------------
#define Bz   16
#define Lz   1024
#define DMz  512
#define Hz   8
#define DKz  64
#define DVz  64
#define DHz  2048
#define Uz   35
#define BHz  (Bz*Hz)     // 128
#define ROWSz (Bz*Lz)    // 16384
#define EPSz 1e-5f

// ---------------- fp32 scratch ----------------
__device__ float g_Q[ROWSz*DMz];
__device__ float g_K[ROWSz*DMz];
__device__ float g_V[ROWSz*DMz];
__device__ float g_M[BHz*Lz];
__device__ int   g_Mtop[BHz*Uz];
__device__ int   g_rowmap[BHz*Lz];
__device__ float g_attn[(size_t)BHz*Uz*Lz];
__device__ float g_ctxrow[BHz*Uz*DVz];
__device__ float g_vmean[BHz*DVz];
__device__ float g_y[ROWSz*DMz];
__device__ float g_x1[ROWSz*DMz];
__device__ float g_y2[ROWSz*DMz];

// ---------------- bf16 split scratch (Q/K path, 3-term) ----------------
__device__ __nv_bfloat16 g_xh[ROWSz*DMz], g_xl[ROWSz*DMz];
__device__ __nv_bfloat16 g_WqTh[DMz*DMz], g_WqTl[DMz*DMz];
__device__ __nv_bfloat16 g_WkTh[DMz*DMz], g_WkTl[DMz*DMz];

// ---------------- fp16 scratch (V/Wo/FFN path, single-pass) ----------------
__device__ __half g_xf[ROWSz*DMz];
__device__ __half g_cf[ROWSz*DMz];
__device__ __half g_x1f[ROWSz*DMz];
__device__ __half g_hf[(size_t)ROWSz*DHz];
__device__ __half g_WvTf[DMz*DMz];
__device__ __half g_WoTf[DMz*DMz];
__device__ __half g_W1Tf[DMz*DHz];
__device__ __half g_W2Tf[DHz*DMz];

// ---------------- helpers ----------------
__device__ __forceinline__ void cp16(uint32_t s, const void* g) {
    asm volatile("cp.async.cg.shared.global [%0], [%1], 16;"
                 :: "r"(s), "l"(__cvta_generic_to_global(g)));
}
__device__ __forceinline__ void cp_commit() {
    asm volatile("cp.async.commit_group;" ::: "memory");
}
__device__ __forceinline__ void ldm_x4(uint32_t& r0, uint32_t& r1, uint32_t& r2, uint32_t& r3,
                                       uint32_t addr) {
    asm volatile("ldmatrix.sync.aligned.m8n8.x4.shared.b16 {%0,%1,%2,%3}, [%4];"
                 : "=r"(r0), "=r"(r1), "=r"(r2), "=r"(r3) : "r"(addr));
}
template<bool ISBF16>
__device__ __forceinline__ void mma_t(float* c, const uint32_t* a, const uint32_t* b) {
    if constexpr (ISBF16)
        asm volatile("mma.sync.aligned.m16n8k16.row.col.f32.bf16.bf16.f32 "
                     "{%0,%1,%2,%3}, {%4,%5,%6,%7}, {%8,%9}, {%0,%1,%2,%3};"
                     : "+f"(c[0]), "+f"(c[1]), "+f"(c[2]), "+f"(c[3])
                     : "r"(a[0]), "r"(a[1]), "r"(a[2]), "r"(a[3]), "r"(b[0]), "r"(b[1]));
    else
        asm volatile("mma.sync.aligned.m16n8k16.row.col.f32.f16.f16.f32 "
                     "{%0,%1,%2,%3}, {%4,%5,%6,%7}, {%8,%9}, {%0,%1,%2,%3};"
                     : "+f"(c[0]), "+f"(c[1]), "+f"(c[2]), "+f"(c[3])
                     : "r"(a[0]), "r"(a[1]), "r"(a[2]), "r"(a[3]), "r"(b[0]), "r"(b[1]));
}

// ---------------- mma.sync GEMM, templated <TERMS, ISBF16> ----------------
// BM=BN=128, warp 64x32, occupancy 2.
// TERMS=3 (bf16 split): 2-stage (4 tiles/stage). TERMS=1 (fp16): 3-stage ring.
#define ROWB 80
#define TILEB (128 * ROWB)

template<int TERMS, bool ISBF16>
__global__ void __launch_bounds__(256, 2)
gemm_kernel(const uint16_t* __restrict__ Ahi, const uint16_t* __restrict__ Alo,
            const uint16_t* __restrict__ Bhi, const uint16_t* __restrict__ Blo,
            const float* __restrict__ bias, const float* __restrict__ res,
            float* __restrict__ C, uint16_t* __restrict__ Chi,
            float* __restrict__ fillp, int fillPerBlk,
            int M, int N, int K, int eop)
{
    constexpr int NT = (TERMS == 3) ? 4 : 2;
    constexpr int NSTAGE = (TERMS == 3) ? 2 : 3;
    constexpr uint32_t STG = NT * TILEB;
    extern __shared__ __align__(16) char smem[];
    const uint32_t smem_u = (uint32_t)__cvta_generic_to_shared(smem);

    const int tid = threadIdx.x;
    const int wid = tid >> 5, lane = tid & 31;
    const int wm = (wid >> 2) * 64;
    const int wn = (wid & 3) * 32;
    const int g = lane >> 3, r = lane & 7;
    const int bm = blockIdx.y * 128;
    const int bn = blockIdx.x * 128;

    const int kt = K >> 5;

    float acc[4][4][4];
#pragma unroll
    for (int i = 0; i < 4; i++)
#pragma unroll
        for (int j = 0; j < 4; j++)
#pragma unroll
            for (int c = 0; c < 4; c++) acc[i][j][c] = 0.f;

    const int ar = tid >> 2, ac = tid & 3;

    auto load_tile = [&](int it, int buf) {
        const int kk = it << 5;
        const uint32_t s0 = smem_u + buf * STG;
        const size_t gaof = (size_t)(bm + ar) * K + kk + ac * 8;
        const size_t gbof = (size_t)(bn + ar) * K + kk + ac * 8;
        const size_t rowK64 = (size_t)64 * K;
        const uint32_t sof = ar * ROWB + ac * 16;
        cp16(s0 + sof, Ahi + gaof);
        cp16(s0 + sof + 64 * ROWB, Ahi + gaof + rowK64);
        if constexpr (TERMS == 3) {
            cp16(s0 + TILEB + sof, Alo + gaof);
            cp16(s0 + TILEB + sof + 64 * ROWB, Alo + gaof + rowK64);
            cp16(s0 + 2 * TILEB + sof, Bhi + gbof);
            cp16(s0 + 2 * TILEB + sof + 64 * ROWB, Bhi + gbof + rowK64);
            cp16(s0 + 3 * TILEB + sof, Blo + gbof);
            cp16(s0 + 3 * TILEB + sof + 64 * ROWB, Blo + gbof + rowK64);
        } else {
            cp16(s0 + TILEB + sof, Bhi + gbof);
            cp16(s0 + TILEB + sof + 64 * ROWB, Bhi + gbof + rowK64);
        }
        cp_commit();
    };

#pragma unroll
    for (int p = 0; p < NSTAGE - 1; p++)
        if (p < kt) load_tile(p, p);

    int buf = 0;
    for (int it = 0; it < kt; it++) {
        if (it + NSTAGE - 2 < kt && NSTAGE == 3) {
            asm volatile("cp.async.wait_group 1;" ::: "memory");
        } else {
            asm volatile("cp.async.wait_group 0;" ::: "memory");
        }
        __syncthreads();

        if (it + NSTAGE - 1 < kt) {
            int nb = buf + NSTAGE - 1; if (nb >= NSTAGE) nb -= NSTAGE;
            load_tile(it + NSTAGE - 1, nb);
        }

        const uint32_t sAh = smem_u + buf * STG;
        const uint32_t sBh = sAh + ((TERMS == 3) ? 2 : 1) * TILEB;
#pragma unroll
        for (int s = 0; s < 2; s++) {
            const int chkA = 2 * s + (g >> 1);
            const int chkB = 2 * s + (g & 1);
            const uint32_t aoff = (wm + ((g & 1) << 3) + r) * ROWB + chkA * 16;
            const uint32_t boff = (wn + ((g >> 1) << 3) + r) * ROWB + chkB * 16;

            uint32_t ah[4][4];
#pragma unroll
            for (int mf = 0; mf < 4; mf++)
                ldm_x4(ah[mf][0], ah[mf][1], ah[mf][2], ah[mf][3], sAh + aoff + mf * 16 * ROWB);
            uint32_t bh[4][2];
#pragma unroll
            for (int ng = 0; ng < 2; ng++)
                ldm_x4(bh[2 * ng][0], bh[2 * ng][1], bh[2 * ng + 1][0], bh[2 * ng + 1][1],
                       sBh + boff + ng * 16 * ROWB);

            if constexpr (TERMS == 3) {
                const uint32_t sAl = sAh + TILEB;
                const uint32_t sBl = sAh + 3 * TILEB;
                uint32_t bl[4][2];
#pragma unroll
                for (int ng = 0; ng < 2; ng++)
                    ldm_x4(bl[2 * ng][0], bl[2 * ng][1], bl[2 * ng + 1][0], bl[2 * ng + 1][1],
                           sBl + boff + ng * 16 * ROWB);
#pragma unroll
                for (int mf = 0; mf < 4; mf++)
#pragma unroll
                    for (int nf = 0; nf < 4; nf++) {
                        mma_t<ISBF16>(acc[mf][nf], ah[mf], bh[nf]);
                        mma_t<ISBF16>(acc[mf][nf], ah[mf], bl[nf]);
                    }
#pragma unroll
                for (int mf = 0; mf < 4; mf++)
                    ldm_x4(ah[mf][0], ah[mf][1], ah[mf][2], ah[mf][3], sAl + aoff + mf * 16 * ROWB);
#pragma unroll
                for (int mf = 0; mf < 4; mf++)
#pragma unroll
                    for (int nf = 0; nf < 4; nf++)
                        mma_t<ISBF16>(acc[mf][nf], ah[mf], bh[nf]);
            } else {
#pragma unroll
                for (int mf = 0; mf < 4; mf++)
#pragma unroll
                    for (int nf = 0; nf < 4; nf++)
                        mma_t<ISBF16>(acc[mf][nf], ah[mf], bh[nf]);
            }
        }
        if (++buf >= NSTAGE) buf = 0;
    }

    // epilogue
    const int rl = lane >> 2, cl = (lane & 3) * 2;
#pragma unroll
    for (int mf = 0; mf < 4; mf++) {
        const int row0 = bm + wm + mf * 16 + rl;
#pragma unroll
        for (int nf = 0; nf < 4; nf++) {
            const int col = bn + wn + nf * 8 + cl;
            const float b0 = bias[col], b1 = bias[col + 1];
            float v0 = acc[mf][nf][0] + b0, v1 = acc[mf][nf][1] + b1;
            float v2 = acc[mf][nf][2] + b0, v3 = acc[mf][nf][3] + b1;
            if (eop == 1) {
                const float* r0 = res + (size_t)row0 * N + col;
                const float* r1 = res + (size_t)(row0 + 8) * N + col;
                v0 += r0[0]; v1 += r0[1]; v2 += r1[0]; v3 += r1[1];
            } else if (eop == 2) {
                v0 = fmaxf(v0, 0.f); v1 = fmaxf(v1, 0.f);
                v2 = fmaxf(v2, 0.f); v3 = fmaxf(v3, 0.f);
                *(__half2*)(Chi + (size_t)row0 * N + col)       = __floats2half2_rn(v0, v1);
                *(__half2*)(Chi + (size_t)(row0 + 8) * N + col) = __floats2half2_rn(v2, v3);
                continue;
            }
            *(float2*)(C + (size_t)row0 * N + col) = make_float2(v0, v1);
            *(float2*)(C + (size_t)(row0 + 8) * N + col) = make_float2(v2, v3);
        }
    }

    // piggybacked constant fill of the score output (streaming stores)
    if (fillp) {
        const int nv4 = fillPerBlk >> 2;
        const int blin = blockIdx.y * gridDim.x + blockIdx.x;
        float4* dst = (float4*)fillp + (size_t)blin * nv4;
        const float c = 1.0f / Lz;
        const float4 f4 = make_float4(c, c, c, c);
        for (int i = tid; i < nv4; i += 256) __stcs(dst + i, f4);
    }
}

// ---------------- x -> bf16 hi/lo + fp16, one read ----------------
__global__ void __launch_bounds__(256)
split_x_kernel(const float* __restrict__ src, __nv_bfloat16* __restrict__ hi,
               __nv_bfloat16* __restrict__ lo, __half* __restrict__ f16)
{
    const size_t i = (size_t)blockIdx.x * 256 + threadIdx.x;
    const float4 v = ((const float4*)src)[i];
    __nv_bfloat16 h0 = __float2bfloat16(v.x), h1 = __float2bfloat16(v.y);
    __nv_bfloat16 h2 = __float2bfloat16(v.z), h3 = __float2bfloat16(v.w);
    __nv_bfloat162 ha; ha.x = h0; ha.y = h1;
    __nv_bfloat162 hb; hb.x = h2; hb.y = h3;
    ((__nv_bfloat162*)hi)[i * 2 + 0] = ha;
    ((__nv_bfloat162*)hi)[i * 2 + 1] = hb;
    __nv_bfloat162 la, lb;
    la.x = __float2bfloat16(v.x - __bfloat162float(h0));
    la.y = __float2bfloat16(v.y - __bfloat162float(h1));
    lb.x = __float2bfloat16(v.z - __bfloat162float(h2));
    lb.y = __float2bfloat16(v.w - __bfloat162float(h3));
    ((__nv_bfloat162*)lo)[i * 2 + 0] = la;
    ((__nv_bfloat162*)lo)[i * 2 + 1] = lb;
    ((__half2*)f16)[i * 2 + 0] = __floats2half2_rn(v.x, v.y);
    ((__half2*)f16)[i * 2 + 1] = __floats2half2_rn(v.z, v.w);
}

// ---------------- weight transpose + bf16 hi/lo split ----------------
__global__ void __launch_bounds__(256)
tsplit_kernel(const float* __restrict__ src, __nv_bfloat16* __restrict__ hi,
              __nv_bfloat16* __restrict__ lo, int K, int N)
{
    __shared__ float tile[32][33];
    const int tx = threadIdx.x & 31, ty = threadIdx.x >> 5;
    const int n0 = blockIdx.x * 32, k0 = blockIdx.y * 32;
#pragma unroll
    for (int i = 0; i < 4; i++)
        tile[ty + 8 * i][tx] = src[(size_t)(k0 + ty + 8 * i) * N + n0 + tx];
    __syncthreads();
#pragma unroll
    for (int i = 0; i < 4; i++) {
        const int n = n0 + ty + 8 * i, k = k0 + tx;
        const float v = tile[tx][ty + 8 * i];
        const __nv_bfloat16 h = __float2bfloat16(v);
        hi[(size_t)n * K + k] = h;
        lo[(size_t)n * K + k] = __float2bfloat16(v - __bfloat162float(h));
    }
}

// ---------------- weight transpose -> fp16 ----------------
__global__ void __launch_bounds__(256)
tsplitf_kernel(const float* __restrict__ src, __half* __restrict__ dst, int K, int N)
{
    __shared__ float tile[32][33];
    const int tx = threadIdx.x & 31, ty = threadIdx.x >> 5;
    const int n0 = blockIdx.x * 32, k0 = blockIdx.y * 32;
#pragma unroll
    for (int i = 0; i < 4; i++)
        tile[ty + 8 * i][tx] = src[(size_t)(k0 + ty + 8 * i) * N + n0 + tx];
    __syncthreads();
#pragma unroll
    for (int i = 0; i < 4; i++) {
        const int n = n0 + ty + 8 * i, k = k0 + tx;
        dst[(size_t)n * K + k] = __float2half(tile[tx][ty + 8 * i]);
    }
}

// ---------------- Sampled scores + fill chunk (5-way interleaved samples) ----------------
__global__ void compute_m_kernel(const int* __restrict__ idx, float* __restrict__ fillp)
{
    {
        const float c = 1.0f / Lz;
        const float4 f4 = make_float4(c, c, c, c);
        float4* dst = (float4*)fillp + (size_t)blockIdx.x * 512;
        __stcs(dst + threadIdx.x, f4);
        __stcs(dst + threadIdx.x + 256, f4);
    }

    const int gw = (blockIdx.x * blockDim.x + threadIdx.x) >> 5;
    const int lane = threadIdx.x & 31;
    const int l = gw & (Lz - 1);
    const int bh = gw >> 10;
    const int h = bh & (Hz - 1), b = bh >> 3;

    const float2* qrow = (const float2*)(g_Q + (size_t)(b * Lz + l) * DMz + h * DKz);
    const float2 q2 = qrow[lane];
    float mx = -INFINITY, sum = 0.f;
#pragma unroll 1
    for (int s0 = 0; s0 < Uz; s0 += 5) {
        float p[5];
#pragma unroll
        for (int q = 0; q < 5; q++) {
            const int j = idx[l * Uz + s0 + q];
            const float2 k2 = ((const float2*)(g_K + (size_t)(b * Lz + j) * DMz + h * DKz))[lane];
            p[q] = q2.x * k2.x + q2.y * k2.y;
        }
#pragma unroll
        for (int o = 16; o; o >>= 1) {
#pragma unroll
            for (int q = 0; q < 5; q++)
                p[q] += __shfl_xor_sync(0xffffffffu, p[q], o);
        }
#pragma unroll
        for (int q = 0; q < 5; q++) { mx = fmaxf(mx, p[q]); sum += p[q]; }
    }
    if (lane == 0) g_M[bh * Lz + l] = mx - sum * (1.0f / Uz);
}

// ---------------- top-35 per (b,h) ----------------
__global__ void __launch_bounds__(256) topk_kernel()
{
    const int bh = blockIdx.x;
    const int tid = threadIdx.x;
    const int wid = tid >> 5, lane = tid & 31;
    __shared__ float vals[Lz];
    __shared__ float wv[8];
    __shared__ int   wi[8];

    for (int l = tid; l < Lz; l += 256) {
        vals[l] = g_M[bh * Lz + l];
        g_rowmap[bh * Lz + l] = -1;
    }
    __syncthreads();

    for (int u = 0; u < Uz; u++) {
        float best = -INFINITY; int bi = 0x7fffffff;
#pragma unroll
        for (int c = 0; c < 4; c++) {
            const int l = tid + c * 256;
            const float v = vals[l];
            if (v > best) { best = v; bi = l; }
        }
#pragma unroll
        for (int o = 16; o; o >>= 1) {
            const float ov = __shfl_xor_sync(0xffffffffu, best, o);
            const int   oi = __shfl_xor_sync(0xffffffffu, bi, o);
            if (ov > best || (ov == best && oi < bi)) { best = ov; bi = oi; }
        }
        if (lane == 0) { wv[wid] = best; wi[wid] = bi; }
        __syncthreads();
        if (tid == 0) {
            float fb = wv[0]; int fi = wi[0];
#pragma unroll
            for (int w = 1; w < 8; w++) {
                if (wv[w] > fb || (wv[w] == fb && wi[w] < fi)) { fb = wv[w]; fi = wi[w]; }
            }
            g_Mtop[bh * Uz + u] = fi;
            g_rowmap[bh * Lz + fi] = u;
            vals[fi] = -INFINITY;
        }
        __syncthreads();
    }
}

// ---------------- scores = Q_top @ K^T / 8 (block = (bh, 256-l chunk)) ----------------
__global__ void __launch_bounds__(256) scores_kernel()
{
    const int bh = blockIdx.x >> 2;
    const int chunk = blockIdx.x & 3;
    const int b = bh >> 3, h = bh & (Hz - 1);
    const int tid = threadIdx.x;
    __shared__ float Qr[Uz * DKz];

    for (int i = tid; i < Uz * DKz; i += 256) {
        const int u = i / DKz, d = i - u * DKz;
        const int l = g_Mtop[bh * Uz + u];
        Qr[i] = g_Q[(size_t)(b * Lz + l) * DMz + h * DKz + d];
    }
    __syncthreads();

    const int l = chunk * 256 + tid;
    float acc[Uz];
#pragma unroll
    for (int u = 0; u < Uz; u++) acc[u] = 0.f;
    const float* krow = g_K + (size_t)(b * Lz + l) * DMz + h * DKz;
#pragma unroll 4
    for (int d = 0; d < DKz; d++) {
        const float kd = krow[d];
#pragma unroll
        for (int u = 0; u < Uz; u++) acc[u] += kd * Qr[u * DKz + d];
    }
#pragma unroll
    for (int u = 0; u < Uz; u++)
        g_attn[((size_t)bh * Uz + u) * Lz + l] = acc[u] * 0.125f;
}

// ---------------- row softmax over L (+ fused score-output write) ----------------
__global__ void __launch_bounds__(256) softmax_kernel(float* __restrict__ outp)
{
    const int row = blockIdx.x;          // bh*Uz + u
    float* p = g_attn + (size_t)row * Lz;
    const int tid = threadIdx.x;
    __shared__ float red[256];

    float4 v = ((float4*)p)[tid];
    float m = fmaxf(fmaxf(v.x, v.y), fmaxf(v.z, v.w));
    red[tid] = m; __syncthreads();
    for (int s = 128; s; s >>= 1) { if (tid < s) red[tid] = fmaxf(red[tid], red[tid + s]); __syncthreads(); }
    m = red[0]; __syncthreads();

    v.x = __expf(v.x - m); v.y = __expf(v.y - m);
    v.z = __expf(v.z - m); v.w = __expf(v.w - m);
    red[tid] = v.x + v.y + v.z + v.w; __syncthreads();
    for (int s = 128; s; s >>= 1) { if (tid < s) red[tid] += red[tid + s]; __syncthreads(); }
    const float inv = 1.0f / red[0];
    v.x *= inv; v.y *= inv; v.z *= inv; v.w *= inv;
    ((float4*)p)[tid] = v;

    const int bh = row / Uz;
    const int l = g_Mtop[row];
    __stcs((float4*)(outp + ((size_t)bh * Lz + l) * Lz) + tid, v);
}

// ---------------- context (+fused V-mean) ----------------
__global__ void __launch_bounds__(256) context_kernel()
{
    const int bh = blockIdx.x;
    const int b = bh >> 3, h = bh & (Hz - 1);
    const int t = threadIdx.x;
    const int d = t & 63, ug = t >> 6;
    __shared__ float sat[Uz][129];

    float acc[9];
#pragma unroll
    for (int k = 0; k < 9; k++) acc[k] = 0.f;
    float vsum = 0.f;

    for (int c = 0; c < 8; c++) {
        for (int i = t; i < Uz * 128; i += 256) {
            const int u = i >> 7, li = i & 127;
            sat[u][li] = g_attn[((size_t)bh * Uz + u) * Lz + c * 128 + li];
        }
        __syncthreads();
        const float* vb = g_V + (size_t)(b * Lz + c * 128) * DMz + h * DVz + d;
#pragma unroll 4
        for (int i = 0; i < 128; i++) {
            const float v = vb[(size_t)i * DMz];
            vsum += v;
#pragma unroll
            for (int k = 0; k < 9; k++) {
                const int u = ug + 4 * k;
                if (u < Uz) acc[k] += sat[u][i] * v;
            }
        }
        __syncthreads();
    }
#pragma unroll
    for (int k = 0; k < 9; k++) {
        const int u = ug + 4 * k;
        if (u < Uz) g_ctxrow[(bh * Uz + u) * DVz + d] = acc[k];
    }
    if (ug == 0) g_vmean[bh * DVz + d] = vsum * (1.0f / Lz);
}

// ---------------- assemble ctx -> fp16 (block per row; rowmap read once per (row,h)) ----------------
__global__ void __launch_bounds__(256) ctx_assemble_kernel(__half* __restrict__ dst)
{
    const int row = blockIdx.x;          // b*Lz + l
    const int b = row >> 10, l = row & (Lz - 1);
    const int tid = threadIdx.x;
    __shared__ int us[Hz];
    if (tid < Hz) us[tid] = g_rowmap[(b * Hz + tid) * Lz + l];
    __syncthreads();
#pragma unroll
    for (int e = tid; e < DMz; e += 256) {
        const int h = e >> 6, d = e & 63;
        const int u = us[h];
        const float v = (u < 0) ? g_vmean[(b * Hz + h) * DVz + d]
                                : g_ctxrow[((b * Hz + h) * Uz + u) * DVz + d];
        dst[(size_t)row * DMz + e] = __float2half(v);
    }
}

// ---------------- LayerNorm (512), optional fused fp16 output ----------------
__global__ void __launch_bounds__(256)
ln_kernel(const float* __restrict__ in, const float* __restrict__ g,
          const float* __restrict__ beta, float* __restrict__ out,
          __half* __restrict__ outf)
{
    const int row = blockIdx.x;
    const int tid = threadIdx.x;
    __shared__ float red[256];
    const float* r = in + (size_t)row * DMz;
    const float a = r[tid], b2 = r[tid + 256];

    red[tid] = a + b2; __syncthreads();
    for (int s = 128; s; s >>= 1) { if (tid < s) red[tid] += red[tid + s]; __syncthreads(); }
    const float mean = red[0] * (1.0f / DMz);
    __syncthreads();
    const float d0 = a - mean, d1 = b2 - mean;
    red[tid] = d0 * d0 + d1 * d1; __syncthreads();
    for (int s = 128; s; s >>= 1) { if (tid < s) red[tid] += red[tid + s]; __syncthreads(); }
    const float inv = rsqrtf(red[0] * (1.0f / DMz) + EPSz);
    const float o0 = g[tid]       * d0 * inv + beta[tid];
    const float o1 = g[tid + 256] * d1 * inv + beta[tid + 256];
    out[(size_t)row * DMz + tid]       = o0;
    out[(size_t)row * DMz + tid + 256] = o1;
    if (outf) {
        outf[(size_t)row * DMz + tid]       = __float2half(o0);
        outf[(size_t)row * DMz + tid + 256] = __float2half(o1);
    }
}

// ---------------- launch ----------------
extern "C" void kernel_launch(void* const* d_in, const int* in_sizes, int n_in,
                              void* d_out, int out_size)
{
    const float* x   = (const float*)d_in[0];
    const float* Wq  = (const float*)d_in[1];
    const float* bq  = (const float*)d_in[2];
    const float* Wk  = (const float*)d_in[3];
    const float* bk  = (const float*)d_in[4];
    const float* Wv  = (const float*)d_in[5];
    const float* bv  = (const float*)d_in[6];
    const float* Wo  = (const float*)d_in[7];
    const float* bo  = (const float*)d_in[8];
    const float* g1  = (const float*)d_in[9];
    const float* be1 = (const float*)d_in[10];
    const float* W1  = (const float*)d_in[11];
    const float* bf1 = (const float*)d_in[12];
    const float* W2  = (const float*)d_in[13];
    const float* bf2 = (const float*)d_in[14];
    const float* g2  = (const float*)d_in[15];
    const float* be2 = (const float*)d_in[16];
    const int*   idx = (const int*)d_in[17];
    float* out = (float*)d_out;
    float* score = out + (size_t)ROWSz * DMz;

    float *Qp, *Kp, *Vp, *yp, *x1p, *y2p;
    cudaGetSymbolAddress((void**)&Qp,   g_Q);
    cudaGetSymbolAddress((void**)&Kp,   g_K);
    cudaGetSymbolAddress((void**)&Vp,   g_V);
    cudaGetSymbolAddress((void**)&yp,   g_y);
    cudaGetSymbolAddress((void**)&x1p,  g_x1);
    cudaGetSymbolAddress((void**)&y2p,  g_y2);

    __nv_bfloat16 *xh, *xl, *WqTh, *WqTl, *WkTh, *WkTl;
    __half *xf, *cf, *x1f, *hf, *WvTf, *WoTf, *W1Tf, *W2Tf;
    cudaGetSymbolAddress((void**)&xh, g_xh);     cudaGetSymbolAddress((void**)&xl, g_xl);
    cudaGetSymbolAddress((void**)&WqTh, g_WqTh); cudaGetSymbolAddress((void**)&WqTl, g_WqTl);
    cudaGetSymbolAddress((void**)&WkTh, g_WkTh); cudaGetSymbolAddress((void**)&WkTl, g_WkTl);
    cudaGetSymbolAddress((void**)&xf, g_xf);     cudaGetSymbolAddress((void**)&cf, g_cf);
    cudaGetSymbolAddress((void**)&x1f, g_x1f);   cudaGetSymbolAddress((void**)&hf, g_hf);
    cudaGetSymbolAddress((void**)&WvTf, g_WvTf); cudaGetSymbolAddress((void**)&WoTf, g_WoTf);
    cudaGetSymbolAddress((void**)&W1Tf, g_W1Tf); cudaGetSymbolAddress((void**)&W2Tf, g_W2Tf);

    const int SM3 = 2 * 4 * TILEB;   // 81920 (2-stage x 4 tiles)
    const int SM1 = 3 * 2 * TILEB;   // 61440 (3-stage x 2 tiles)
    cudaFuncSetAttribute(gemm_kernel<3, true>,
                         cudaFuncAttributeMaxDynamicSharedMemorySize, SM3);
    cudaFuncSetAttribute(gemm_kernel<1, false>,
                         cudaFuncAttributeMaxDynamicSharedMemorySize, SM1);

    const dim3 gN512(4, 128);
    const dim3 gN2048(16, 128);

    // fill partition: 3 GEMM launches x 512 blocks x 65536 floats + compute_m 16384 x 2048
    const int FPB_GEMM = 65536;
    float* fill0 = score;
    float* fill1 = score + (size_t)512 * FPB_GEMM;
    float* fill2 = score + (size_t)1024 * FPB_GEMM;
    float* fill3 = score + (size_t)1536 * FPB_GEMM;

    // conversions for QKV (launch #6 = GEMM Q for ncu)
    split_x_kernel<<<(ROWSz * DMz) / 1024, 256>>>(x, xh, xl, xf);          // 1
    tsplit_kernel<<<dim3(16, 16), 256>>>(Wq, WqTh, WqTl, DMz, DMz);        // 2
    tsplit_kernel<<<dim3(16, 16), 256>>>(Wk, WkTh, WkTl, DMz, DMz);        // 3
    tsplitf_kernel<<<dim3(16, 16), 256>>>(Wv, WvTf, DMz, DMz);             // 4
    tsplitf_kernel<<<dim3(16, 16), 256>>>(Wo, WoTf, DMz, DMz);             // 5

    // QKV projections (+score fill)
    gemm_kernel<3, true><<<gN512, 256, SM3>>>((const uint16_t*)xh, (const uint16_t*)xl,
        (const uint16_t*)WqTh, (const uint16_t*)WqTl, bq, nullptr, Qp, nullptr,
        fill0, FPB_GEMM, ROWSz, DMz, DMz, 0);                              // 6 (ncu)
    gemm_kernel<3, true><<<gN512, 256, SM3>>>((const uint16_t*)xh, (const uint16_t*)xl,
        (const uint16_t*)WkTh, (const uint16_t*)WkTl, bk, nullptr, Kp, nullptr,
        fill1, FPB_GEMM, ROWSz, DMz, DMz, 0);                              // 7
    gemm_kernel<1, false><<<gN512, 256, SM1>>>((const uint16_t*)xf, nullptr,
        (const uint16_t*)WvTf, nullptr, bv, nullptr, Vp, nullptr,
        fill2, FPB_GEMM, ROWSz, DMz, DMz, 0);                              // 8

    // remaining weight conversions
    tsplitf_kernel<<<dim3(64, 16), 256>>>(W1, W1Tf, DMz, DHz);
    tsplitf_kernel<<<dim3(16, 64), 256>>>(W2, W2Tf, DHz, DMz);

    // ProbSparse attention
    compute_m_kernel<<<(BHz * Lz) / 8, 256>>>(idx, fill3);
    topk_kernel<<<BHz, 256>>>();
    scores_kernel<<<BHz * 4, 256>>>();
    softmax_kernel<<<BHz * Uz, 256>>>(score);
    context_kernel<<<BHz, 256>>>();
    ctx_assemble_kernel<<<ROWSz, 256>>>(cf);

    // Wo projection + residual, LN1 (fused fp16 x1)
    gemm_kernel<1, false><<<gN512, 256, SM1>>>((const uint16_t*)cf, nullptr,
        (const uint16_t*)WoTf, nullptr, bo, x, yp, nullptr,
        nullptr, 0, ROWSz, DMz, DMz, 1);
    ln_kernel<<<ROWSz, 256>>>(yp, g1, be1, x1p, x1f);

    // FFN
    gemm_kernel<1, false><<<gN2048, 256, SM1>>>((const uint16_t*)x1f, nullptr,
        (const uint16_t*)W1Tf, nullptr, bf1, nullptr, nullptr, (uint16_t*)hf,
        nullptr, 0, ROWSz, DHz, DMz, 2);
    gemm_kernel<1, false><<<gN512, 256, SM1>>>((const uint16_t*)hf, nullptr,
        (const uint16_t*)W2Tf, nullptr, bf2, x1p, y2p, nullptr,
        nullptr, 0, ROWSz, DMz, DHz, 1);
    ln_kernel<<<ROWSz, 256>>>(y2p, g2, be2, out, nullptr);
}

// round 16
// speedup vs baseline: 1.1063x; 1.0256x over previous
#include <cuda_runtime.h>
#include <cuda_bf16.h>
#include <cuda_fp16.h>
#include <math.h>
#include <stdint.h>

// ---------------- Problem constants ----------------
#define Bz   16
#define Lz   1024
#define DMz  512
#define Hz   8
#define DKz  64
#define DVz  64
#define DHz  2048
#define Uz   35
#define BHz  (Bz*Hz)     // 128
#define ROWSz (Bz*Lz)    // 16384
#define EPSz 1e-5f
#define QKN  1024        // stacked Q|K width

// ---------------- fp32 scratch ----------------
__device__ float g_QK[(size_t)ROWSz*QKN];   // [row][0..512)=Q, [512..1024)=K
__device__ float g_V[ROWSz*DMz];
__device__ float g_M[BHz*Lz];
__device__ int   g_Mtop[BHz*Uz];
__device__ int   g_rowmap[BHz*Lz];
__device__ float g_attn[(size_t)BHz*Uz*Lz];
__device__ float g_ctxrow[BHz*Uz*DVz];
__device__ float g_vmean[BHz*DVz];
__device__ float g_y[ROWSz*DMz];
__device__ float g_x1[ROWSz*DMz];
__device__ float g_y2[ROWSz*DMz];
__device__ float g_bqk[QKN];

// ---------------- bf16 split scratch (Q/K path, 3-term) ----------------
__device__ __nv_bfloat16 g_xh[ROWSz*DMz], g_xl[ROWSz*DMz];
__device__ __nv_bfloat16 g_WqkTh[QKN*DMz], g_WqkTl[QKN*DMz];

// ---------------- fp16 scratch (V/Wo/FFN path, single-pass) ----------------
__device__ __half g_xf[ROWSz*DMz];
__device__ __half g_cf[ROWSz*DMz];
__device__ __half g_x1f[ROWSz*DMz];
__device__ __half g_hf[(size_t)ROWSz*DHz];
__device__ __half g_WvTf[DMz*DMz];
__device__ __half g_WoTf[DMz*DMz];
__device__ __half g_W1Tf[DMz*DHz];
__device__ __half g_W2Tf[DHz*DMz];

// ---------------- helpers ----------------
__device__ __forceinline__ void cp16(uint32_t s, const void* g) {
    asm volatile("cp.async.cg.shared.global [%0], [%1], 16;"
                 :: "r"(s), "l"(__cvta_generic_to_global(g)));
}
__device__ __forceinline__ void cp_commit() {
    asm volatile("cp.async.commit_group;" ::: "memory");
}
__device__ __forceinline__ void ldm_x4(uint32_t& r0, uint32_t& r1, uint32_t& r2, uint32_t& r3,
                                       uint32_t addr) {
    asm volatile("ldmatrix.sync.aligned.m8n8.x4.shared.b16 {%0,%1,%2,%3}, [%4];"
                 : "=r"(r0), "=r"(r1), "=r"(r2), "=r"(r3) : "r"(addr));
}
template<bool ISBF16>
__device__ __forceinline__ void mma_t(float* c, const uint32_t* a, const uint32_t* b) {
    if constexpr (ISBF16)
        asm volatile("mma.sync.aligned.m16n8k16.row.col.f32.bf16.bf16.f32 "
                     "{%0,%1,%2,%3}, {%4,%5,%6,%7}, {%8,%9}, {%0,%1,%2,%3};"
                     : "+f"(c[0]), "+f"(c[1]), "+f"(c[2]), "+f"(c[3])
                     : "r"(a[0]), "r"(a[1]), "r"(a[2]), "r"(a[3]), "r"(b[0]), "r"(b[1]));
    else
        asm volatile("mma.sync.aligned.m16n8k16.row.col.f32.f16.f16.f32 "
                     "{%0,%1,%2,%3}, {%4,%5,%6,%7}, {%8,%9}, {%0,%1,%2,%3};"
                     : "+f"(c[0]), "+f"(c[1]), "+f"(c[2]), "+f"(c[3])
                     : "r"(a[0]), "r"(a[1]), "r"(a[2]), "r"(a[3]), "r"(b[0]), "r"(b[1]));
}

// ---------------- mma.sync GEMM, templated <TERMS, ISBF16> ----------------
// BM=BN=128, warp 64x32, occupancy 2.
// TERMS=3 (bf16 split): 2-stage (4 tiles/stage). TERMS=1 (fp16): 3-stage ring.
#define ROWB 80
#define TILEB (128 * ROWB)

template<int TERMS, bool ISBF16>
__global__ void __launch_bounds__(256, 2)
gemm_kernel(const uint16_t* __restrict__ Ahi, const uint16_t* __restrict__ Alo,
            const uint16_t* __restrict__ Bhi, const uint16_t* __restrict__ Blo,
            const float* __restrict__ bias, const float* __restrict__ res,
            float* __restrict__ C, uint16_t* __restrict__ Chi,
            float* __restrict__ fillp, int fillPerBlk,
            int M, int N, int K, int eop)
{
    constexpr int NT = (TERMS == 3) ? 4 : 2;
    constexpr int NSTAGE = (TERMS == 3) ? 2 : 3;
    constexpr uint32_t STG = NT * TILEB;
    extern __shared__ __align__(16) char smem[];
    const uint32_t smem_u = (uint32_t)__cvta_generic_to_shared(smem);

    const int tid = threadIdx.x;
    const int wid = tid >> 5, lane = tid & 31;
    const int wm = (wid >> 2) * 64;
    const int wn = (wid & 3) * 32;
    const int g = lane >> 3, r = lane & 7;
    const int bm = blockIdx.y * 128;
    const int bn = blockIdx.x * 128;

    const int kt = K >> 5;

    float acc[4][4][4];
#pragma unroll
    for (int i = 0; i < 4; i++)
#pragma unroll
        for (int j = 0; j < 4; j++)
#pragma unroll
            for (int c = 0; c < 4; c++) acc[i][j][c] = 0.f;

    const int ar = tid >> 2, ac = tid & 3;

    auto load_tile = [&](int it, int buf) {
        const int kk = it << 5;
        const uint32_t s0 = smem_u + buf * STG;
        const size_t gaof = (size_t)(bm + ar) * K + kk + ac * 8;
        const size_t gbof = (size_t)(bn + ar) * K + kk + ac * 8;
        const size_t rowK64 = (size_t)64 * K;
        const uint32_t sof = ar * ROWB + ac * 16;
        cp16(s0 + sof, Ahi + gaof);
        cp16(s0 + sof + 64 * ROWB, Ahi + gaof + rowK64);
        if constexpr (TERMS == 3) {
            cp16(s0 + TILEB + sof, Alo + gaof);
            cp16(s0 + TILEB + sof + 64 * ROWB, Alo + gaof + rowK64);
            cp16(s0 + 2 * TILEB + sof, Bhi + gbof);
            cp16(s0 + 2 * TILEB + sof + 64 * ROWB, Bhi + gbof + rowK64);
            cp16(s0 + 3 * TILEB + sof, Blo + gbof);
            cp16(s0 + 3 * TILEB + sof + 64 * ROWB, Blo + gbof + rowK64);
        } else {
            cp16(s0 + TILEB + sof, Bhi + gbof);
            cp16(s0 + TILEB + sof + 64 * ROWB, Bhi + gbof + rowK64);
        }
        cp_commit();
    };

#pragma unroll
    for (int p = 0; p < NSTAGE - 1; p++)
        if (p < kt) load_tile(p, p);

    int buf = 0;
    for (int it = 0; it < kt; it++) {
        if (it + NSTAGE - 2 < kt && NSTAGE == 3) {
            asm volatile("cp.async.wait_group 1;" ::: "memory");
        } else {
            asm volatile("cp.async.wait_group 0;" ::: "memory");
        }
        __syncthreads();

        if (it + NSTAGE - 1 < kt) {
            int nb = buf + NSTAGE - 1; if (nb >= NSTAGE) nb -= NSTAGE;
            load_tile(it + NSTAGE - 1, nb);
        }

        const uint32_t sAh = smem_u + buf * STG;
        const uint32_t sBh = sAh + ((TERMS == 3) ? 2 : 1) * TILEB;
#pragma unroll
        for (int s = 0; s < 2; s++) {
            const int chkA = 2 * s + (g >> 1);
            const int chkB = 2 * s + (g & 1);
            const uint32_t aoff = (wm + ((g & 1) << 3) + r) * ROWB + chkA * 16;
            const uint32_t boff = (wn + ((g >> 1) << 3) + r) * ROWB + chkB * 16;

            uint32_t ah[4][4];
#pragma unroll
            for (int mf = 0; mf < 4; mf++)
                ldm_x4(ah[mf][0], ah[mf][1], ah[mf][2], ah[mf][3], sAh + aoff + mf * 16 * ROWB);
            uint32_t bh[4][2];
#pragma unroll
            for (int ng = 0; ng < 2; ng++)
                ldm_x4(bh[2 * ng][0], bh[2 * ng][1], bh[2 * ng + 1][0], bh[2 * ng + 1][1],
                       sBh + boff + ng * 16 * ROWB);

            if constexpr (TERMS == 3) {
                const uint32_t sAl = sAh + TILEB;
                const uint32_t sBl = sAh + 3 * TILEB;
                uint32_t bl[4][2];
#pragma unroll
                for (int ng = 0; ng < 2; ng++)
                    ldm_x4(bl[2 * ng][0], bl[2 * ng][1], bl[2 * ng + 1][0], bl[2 * ng + 1][1],
                           sBl + boff + ng * 16 * ROWB);
#pragma unroll
                for (int mf = 0; mf < 4; mf++)
#pragma unroll
                    for (int nf = 0; nf < 4; nf++) {
                        mma_t<ISBF16>(acc[mf][nf], ah[mf], bh[nf]);
                        mma_t<ISBF16>(acc[mf][nf], ah[mf], bl[nf]);
                    }
#pragma unroll
                for (int mf = 0; mf < 4; mf++)
                    ldm_x4(ah[mf][0], ah[mf][1], ah[mf][2], ah[mf][3], sAl + aoff + mf * 16 * ROWB);
#pragma unroll
                for (int mf = 0; mf < 4; mf++)
#pragma unroll
                    for (int nf = 0; nf < 4; nf++)
                        mma_t<ISBF16>(acc[mf][nf], ah[mf], bh[nf]);
            } else {
#pragma unroll
                for (int mf = 0; mf < 4; mf++)
#pragma unroll
                    for (int nf = 0; nf < 4; nf++)
                        mma_t<ISBF16>(acc[mf][nf], ah[mf], bh[nf]);
            }
        }
        if (++buf >= NSTAGE) buf = 0;
    }

    // epilogue
    const int rl = lane >> 2, cl = (lane & 3) * 2;
#pragma unroll
    for (int mf = 0; mf < 4; mf++) {
        const int row0 = bm + wm + mf * 16 + rl;
#pragma unroll
        for (int nf = 0; nf < 4; nf++) {
            const int col = bn + wn + nf * 8 + cl;
            const float b0 = bias[col], b1 = bias[col + 1];
            float v0 = acc[mf][nf][0] + b0, v1 = acc[mf][nf][1] + b1;
            float v2 = acc[mf][nf][2] + b0, v3 = acc[mf][nf][3] + b1;
            if (eop == 1) {
                const float* r0 = res + (size_t)row0 * N + col;
                const float* r1 = res + (size_t)(row0 + 8) * N + col;
                v0 += r0[0]; v1 += r0[1]; v2 += r1[0]; v3 += r1[1];
            } else if (eop == 2) {
                v0 = fmaxf(v0, 0.f); v1 = fmaxf(v1, 0.f);
                v2 = fmaxf(v2, 0.f); v3 = fmaxf(v3, 0.f);
                *(__half2*)(Chi + (size_t)row0 * N + col)       = __floats2half2_rn(v0, v1);
                *(__half2*)(Chi + (size_t)(row0 + 8) * N + col) = __floats2half2_rn(v2, v3);
                continue;
            }
            *(float2*)(C + (size_t)row0 * N + col) = make_float2(v0, v1);
            *(float2*)(C + (size_t)(row0 + 8) * N + col) = make_float2(v2, v3);
        }
    }

    // piggybacked constant fill of the score output (streaming stores)
    if (fillp) {
        const int nv4 = fillPerBlk >> 2;
        const int blin = blockIdx.y * gridDim.x + blockIdx.x;
        float4* dst = (float4*)fillp + (size_t)blin * nv4;
        const float c = 1.0f / Lz;
        const float4 f4 = make_float4(c, c, c, c);
        for (int i = tid; i < nv4; i += 256) __stcs(dst + i, f4);
    }
}

// ---------------- x -> bf16 hi/lo + fp16, one read ----------------
__global__ void __launch_bounds__(256)
split_x_kernel(const float* __restrict__ src, __nv_bfloat16* __restrict__ hi,
               __nv_bfloat16* __restrict__ lo, __half* __restrict__ f16)
{
    const size_t i = (size_t)blockIdx.x * 256 + threadIdx.x;
    const float4 v = ((const float4*)src)[i];
    __nv_bfloat16 h0 = __float2bfloat16(v.x), h1 = __float2bfloat16(v.y);
    __nv_bfloat16 h2 = __float2bfloat16(v.z), h3 = __float2bfloat16(v.w);
    __nv_bfloat162 ha; ha.x = h0; ha.y = h1;
    __nv_bfloat162 hb; hb.x = h2; hb.y = h3;
    ((__nv_bfloat162*)hi)[i * 2 + 0] = ha;
    ((__nv_bfloat162*)hi)[i * 2 + 1] = hb;
    __nv_bfloat162 la, lb;
    la.x = __float2bfloat16(v.x - __bfloat162float(h0));
    la.y = __float2bfloat16(v.y - __bfloat162float(h1));
    lb.x = __float2bfloat16(v.z - __bfloat162float(h2));
    lb.y = __float2bfloat16(v.w - __bfloat162float(h3));
    ((__nv_bfloat162*)lo)[i * 2 + 0] = la;
    ((__nv_bfloat162*)lo)[i * 2 + 1] = lb;
    ((__half2*)f16)[i * 2 + 0] = __floats2half2_rn(v.x, v.y);
    ((__half2*)f16)[i * 2 + 1] = __floats2half2_rn(v.z, v.w);
}

// ---------------- weight transpose + bf16 hi/lo split ----------------
__global__ void __launch_bounds__(256)
tsplit_kernel(const float* __restrict__ src, __nv_bfloat16* __restrict__ hi,
              __nv_bfloat16* __restrict__ lo, int K, int N)
{
    __shared__ float tile[32][33];
    const int tx = threadIdx.x & 31, ty = threadIdx.x >> 5;
    const int n0 = blockIdx.x * 32, k0 = blockIdx.y * 32;
#pragma unroll
    for (int i = 0; i < 4; i++)
        tile[ty + 8 * i][tx] = src[(size_t)(k0 + ty + 8 * i) * N + n0 + tx];
    __syncthreads();
#pragma unroll
    for (int i = 0; i < 4; i++) {
        const int n = n0 + ty + 8 * i, k = k0 + tx;
        const float v = tile[tx][ty + 8 * i];
        const __nv_bfloat16 h = __float2bfloat16(v);
        hi[(size_t)n * K + k] = h;
        lo[(size_t)n * K + k] = __float2bfloat16(v - __bfloat162float(h));
    }
}

// ---------------- weight transpose -> fp16 ----------------
__global__ void __launch_bounds__(256)
tsplitf_kernel(const float* __restrict__ src, __half* __restrict__ dst, int K, int N)
{
    __shared__ float tile[32][33];
    const int tx = threadIdx.x & 31, ty = threadIdx.x >> 5;
    const int n0 = blockIdx.x * 32, k0 = blockIdx.y * 32;
#pragma unroll
    for (int i = 0; i < 4; i++)
        tile[ty + 8 * i][tx] = src[(size_t)(k0 + ty + 8 * i) * N + n0 + tx];
    __syncthreads();
#pragma unroll
    for (int i = 0; i < 4; i++) {
        const int n = n0 + ty + 8 * i, k = k0 + tx;
        dst[(size_t)n * K + k] = __float2half(tile[tx][ty + 8 * i]);
    }
}

// ---------------- bias concat [bq | bk] ----------------
__global__ void __launch_bounds__(256)
bias_concat_kernel(const float* __restrict__ bq, const float* __restrict__ bk,
                   float* __restrict__ dst)
{
    const int i = blockIdx.x * 256 + threadIdx.x;
    dst[i] = (i < DMz) ? bq[i] : bk[i - DMz];
}

// ---------------- Sampled scores + fill chunk (5-way interleaved samples) ----------------
__global__ void compute_m_kernel(const int* __restrict__ idx, float* __restrict__ fillp)
{
    {
        const float c = 1.0f / Lz;
        const float4 f4 = make_float4(c, c, c, c);
        float4* dst = (float4*)fillp + (size_t)blockIdx.x * 512;
        __stcs(dst + threadIdx.x, f4);
        __stcs(dst + threadIdx.x + 256, f4);
    }

    const int gw = (blockIdx.x * blockDim.x + threadIdx.x) >> 5;
    const int lane = threadIdx.x & 31;
    const int l = gw & (Lz - 1);
    const int bh = gw >> 10;
    const int h = bh & (Hz - 1), b = bh >> 3;

    const float2* qrow = (const float2*)(g_QK + (size_t)(b * Lz + l) * QKN + h * DKz);
    const float2 q2 = qrow[lane];
    float mx = -INFINITY, sum = 0.f;
#pragma unroll 1
    for (int s0 = 0; s0 < Uz; s0 += 5) {
        float p[5];
#pragma unroll
        for (int q = 0; q < 5; q++) {
            const int j = idx[l * Uz + s0 + q];
            const float2 k2 = ((const float2*)(g_QK + (size_t)(b * Lz + j) * QKN + DMz + h * DKz))[lane];
            p[q] = q2.x * k2.x + q2.y * k2.y;
        }
#pragma unroll
        for (int o = 16; o; o >>= 1) {
#pragma unroll
            for (int q = 0; q < 5; q++)
                p[q] += __shfl_xor_sync(0xffffffffu, p[q], o);
        }
#pragma unroll
        for (int q = 0; q < 5; q++) { mx = fmaxf(mx, p[q]); sum += p[q]; }
    }
    if (lane == 0) g_M[bh * Lz + l] = mx - sum * (1.0f / Uz);
}

// ---------------- top-35 per (b,h) ----------------
__global__ void __launch_bounds__(256) topk_kernel()
{
    const int bh = blockIdx.x;
    const int tid = threadIdx.x;
    const int wid = tid >> 5, lane = tid & 31;
    __shared__ float vals[Lz];
    __shared__ float wv[8];
    __shared__ int   wi[8];

    for (int l = tid; l < Lz; l += 256) {
        vals[l] = g_M[bh * Lz + l];
        g_rowmap[bh * Lz + l] = -1;
    }
    __syncthreads();

    for (int u = 0; u < Uz; u++) {
        float best = -INFINITY; int bi = 0x7fffffff;
#pragma unroll
        for (int c = 0; c < 4; c++) {
            const int l = tid + c * 256;
            const float v = vals[l];
            if (v > best) { best = v; bi = l; }
        }
#pragma unroll
        for (int o = 16; o; o >>= 1) {
            const float ov = __shfl_xor_sync(0xffffffffu, best, o);
            const int   oi = __shfl_xor_sync(0xffffffffu, bi, o);
            if (ov > best || (ov == best && oi < bi)) { best = ov; bi = oi; }
        }
        if (lane == 0) { wv[wid] = best; wi[wid] = bi; }
        __syncthreads();
        if (tid == 0) {
            float fb = wv[0]; int fi = wi[0];
#pragma unroll
            for (int w = 1; w < 8; w++) {
                if (wv[w] > fb || (wv[w] == fb && wi[w] < fi)) { fb = wv[w]; fi = wi[w]; }
            }
            g_Mtop[bh * Uz + u] = fi;
            g_rowmap[bh * Lz + fi] = u;
            vals[fi] = -INFINITY;
        }
        __syncthreads();
    }
}

// ---------------- scores = Q_top @ K^T / 8 (block = (bh, 256-l chunk)) ----------------
__global__ void __launch_bounds__(256) scores_kernel()
{
    const int bh = blockIdx.x >> 2;
    const int chunk = blockIdx.x & 3;
    const int b = bh >> 3, h = bh & (Hz - 1);
    const int tid = threadIdx.x;
    __shared__ float Qr[Uz * DKz];

    for (int i = tid; i < Uz * DKz; i += 256) {
        const int u = i / DKz, d = i - u * DKz;
        const int l = g_Mtop[bh * Uz + u];
        Qr[i] = g_QK[(size_t)(b * Lz + l) * QKN + h * DKz + d];
    }
    __syncthreads();

    const int l = chunk * 256 + tid;
    float acc[Uz];
#pragma unroll
    for (int u = 0; u < Uz; u++) acc[u] = 0.f;
    const float* krow = g_QK + (size_t)(b * Lz + l) * QKN + DMz + h * DKz;
#pragma unroll 4
    for (int d = 0; d < DKz; d++) {
        const float kd = krow[d];
#pragma unroll
        for (int u = 0; u < Uz; u++) acc[u] += kd * Qr[u * DKz + d];
    }
#pragma unroll
    for (int u = 0; u < Uz; u++)
        g_attn[((size_t)bh * Uz + u) * Lz + l] = acc[u] * 0.125f;
}

// ---------------- row softmax over L (+ fused score-output write) ----------------
__global__ void __launch_bounds__(256) softmax_kernel(float* __restrict__ outp)
{
    const int row = blockIdx.x;          // bh*Uz + u
    float* p = g_attn + (size_t)row * Lz;
    const int tid = threadIdx.x;
    __shared__ float red[256];

    float4 v = ((float4*)p)[tid];
    float m = fmaxf(fmaxf(v.x, v.y), fmaxf(v.z, v.w));
    red[tid] = m; __syncthreads();
    for (int s = 128; s; s >>= 1) { if (tid < s) red[tid] = fmaxf(red[tid], red[tid + s]); __syncthreads(); }
    m = red[0]; __syncthreads();

    v.x = __expf(v.x - m); v.y = __expf(v.y - m);
    v.z = __expf(v.z - m); v.w = __expf(v.w - m);
    red[tid] = v.x + v.y + v.z + v.w; __syncthreads();
    for (int s = 128; s; s >>= 1) { if (tid < s) red[tid] += red[tid + s]; __syncthreads(); }
    const float inv = 1.0f / red[0];
    v.x *= inv; v.y *= inv; v.z *= inv; v.w *= inv;
    ((float4*)p)[tid] = v;

    const int bh = row / Uz;
    const int l = g_Mtop[row];
    __stcs((float4*)(outp + ((size_t)bh * Lz + l) * Lz) + tid, v);
}

// ---------------- context (+fused V-mean) ----------------
__global__ void __launch_bounds__(256) context_kernel()
{
    const int bh = blockIdx.x;
    const int b = bh >> 3, h = bh & (Hz - 1);
    const int t = threadIdx.x;
    const int d = t & 63, ug = t >> 6;
    __shared__ float sat[Uz][129];

    float acc[9];
#pragma unroll
    for (int k = 0; k < 9; k++) acc[k] = 0.f;
    float vsum = 0.f;

    for (int c = 0; c < 8; c++) {
        for (int i = t; i < Uz * 128; i += 256) {
            const int u = i >> 7, li = i & 127;
            sat[u][li] = g_attn[((size_t)bh * Uz + u) * Lz + c * 128 + li];
        }
        __syncthreads();
        const float* vb = g_V + (size_t)(b * Lz + c * 128) * DMz + h * DVz + d;
#pragma unroll 4
        for (int i = 0; i < 128; i++) {
            const float v = vb[(size_t)i * DMz];
            vsum += v;
#pragma unroll
            for (int k = 0; k < 9; k++) {
                const int u = ug + 4 * k;
                if (u < Uz) acc[k] += sat[u][i] * v;
            }
        }
        __syncthreads();
    }
#pragma unroll
    for (int k = 0; k < 9; k++) {
        const int u = ug + 4 * k;
        if (u < Uz) g_ctxrow[(bh * Uz + u) * DVz + d] = acc[k];
    }
    if (ug == 0) g_vmean[bh * DVz + d] = vsum * (1.0f / Lz);
}

// ---------------- assemble ctx -> fp16 (block per row) ----------------
__global__ void __launch_bounds__(256) ctx_assemble_kernel(__half* __restrict__ dst)
{
    const int row = blockIdx.x;          // b*Lz + l
    const int b = row >> 10, l = row & (Lz - 1);
    const int tid = threadIdx.x;
    __shared__ int us[Hz];
    if (tid < Hz) us[tid] = g_rowmap[(b * Hz + tid) * Lz + l];
    __syncthreads();
#pragma unroll
    for (int e = tid; e < DMz; e += 256) {
        const int h = e >> 6, d = e & 63;
        const int u = us[h];
        const float v = (u < 0) ? g_vmean[(b * Hz + h) * DVz + d]
                                : g_ctxrow[((b * Hz + h) * Uz + u) * DVz + d];
        dst[(size_t)row * DMz + e] = __float2half(v);
    }
}

// ---------------- LayerNorm (512), optional fused fp16 output ----------------
__global__ void __launch_bounds__(256)
ln_kernel(const float* __restrict__ in, const float* __restrict__ g,
          const float* __restrict__ beta, float* __restrict__ out,
          __half* __restrict__ outf)
{
    const int row = blockIdx.x;
    const int tid = threadIdx.x;
    __shared__ float red[256];
    const float* r = in + (size_t)row * DMz;
    const float a = r[tid], b2 = r[tid + 256];

    red[tid] = a + b2; __syncthreads();
    for (int s = 128; s; s >>= 1) { if (tid < s) red[tid] += red[tid + s]; __syncthreads(); }
    const float mean = red[0] * (1.0f / DMz);
    __syncthreads();
    const float d0 = a - mean, d1 = b2 - mean;
    red[tid] = d0 * d0 + d1 * d1; __syncthreads();
    for (int s = 128; s; s >>= 1) { if (tid < s) red[tid] += red[tid + s]; __syncthreads(); }
    const float inv = rsqrtf(red[0] * (1.0f / DMz) + EPSz);
    const float o0 = g[tid]       * d0 * inv + beta[tid];
    const float o1 = g[tid + 256] * d1 * inv + beta[tid + 256];
    out[(size_t)row * DMz + tid]       = o0;
    out[(size_t)row * DMz + tid + 256] = o1;
    if (outf) {
        outf[(size_t)row * DMz + tid]       = __float2half(o0);
        outf[(size_t)row * DMz + tid + 256] = __float2half(o1);
    }
}

// ---------------- launch ----------------
extern "C" void kernel_launch(void* const* d_in, const int* in_sizes, int n_in,
                              void* d_out, int out_size)
{
    const float* x   = (const float*)d_in[0];
    const float* Wq  = (const float*)d_in[1];
    const float* bq  = (const float*)d_in[2];
    const float* Wk  = (const float*)d_in[3];
    const float* bk  = (const float*)d_in[4];
    const float* Wv  = (const float*)d_in[5];
    const float* bv  = (const float*)d_in[6];
    const float* Wo  = (const float*)d_in[7];
    const float* bo  = (const float*)d_in[8];
    const float* g1  = (const float*)d_in[9];
    const float* be1 = (const float*)d_in[10];
    const float* W1  = (const float*)d_in[11];
    const float* bf1 = (const float*)d_in[12];
    const float* W2  = (const float*)d_in[13];
    const float* bf2 = (const float*)d_in[14];
    const float* g2  = (const float*)d_in[15];
    const float* be2 = (const float*)d_in[16];
    const int*   idx = (const int*)d_in[17];
    float* out = (float*)d_out;
    float* score = out + (size_t)ROWSz * DMz;

    float *QKp, *Vp, *yp, *x1p, *y2p, *bqkp;
    cudaGetSymbolAddress((void**)&QKp,  g_QK);
    cudaGetSymbolAddress((void**)&Vp,   g_V);
    cudaGetSymbolAddress((void**)&yp,   g_y);
    cudaGetSymbolAddress((void**)&x1p,  g_x1);
    cudaGetSymbolAddress((void**)&y2p,  g_y2);
    cudaGetSymbolAddress((void**)&bqkp, g_bqk);

    __nv_bfloat16 *xh, *xl, *WqkTh, *WqkTl;
    __half *xf, *cf, *x1f, *hf, *WvTf, *WoTf, *W1Tf, *W2Tf;
    cudaGetSymbolAddress((void**)&xh, g_xh);       cudaGetSymbolAddress((void**)&xl, g_xl);
    cudaGetSymbolAddress((void**)&WqkTh, g_WqkTh); cudaGetSymbolAddress((void**)&WqkTl, g_WqkTl);
    cudaGetSymbolAddress((void**)&xf, g_xf);       cudaGetSymbolAddress((void**)&cf, g_cf);
    cudaGetSymbolAddress((void**)&x1f, g_x1f);     cudaGetSymbolAddress((void**)&hf, g_hf);
    cudaGetSymbolAddress((void**)&WvTf, g_WvTf);   cudaGetSymbolAddress((void**)&WoTf, g_WoTf);
    cudaGetSymbolAddress((void**)&W1Tf, g_W1Tf);   cudaGetSymbolAddress((void**)&W2Tf, g_W2Tf);

    const int SM3 = 2 * 4 * TILEB;   // 81920 (2-stage x 4 tiles)
    const int SM1 = 3 * 2 * TILEB;   // 61440 (3-stage x 2 tiles)
    cudaFuncSetAttribute(gemm_kernel<3, true>,
                         cudaFuncAttributeMaxDynamicSharedMemorySize, SM3);
    cudaFuncSetAttribute(gemm_kernel<1, false>,
                         cudaFuncAttributeMaxDynamicSharedMemorySize, SM1);

    const dim3 gQK(8, 128);      // N=1024
    const dim3 gN512(4, 128);
    const dim3 gN2048(16, 128);

    // fill partition: QK 1024 blocks x 65536 + V 512 x 65536 + compute_m 16384 x 2048
    //               = 67.1M + 33.5M + 33.5M = 134217728 = BHz*Lz*Lz
    const int FPB_GEMM = 65536;
    float* fill0 = score;
    float* fill2 = score + (size_t)1024 * FPB_GEMM;
    float* fill3 = score + (size_t)1536 * FPB_GEMM;

    // conversions (launch #6 = fused QK GEMM for ncu)
    split_x_kernel<<<(ROWSz * DMz) / 1024, 256>>>(x, xh, xl, xf);              // 1
    tsplit_kernel<<<dim3(16, 16), 256>>>(Wq, WqkTh, WqkTl, DMz, DMz);          // 2
    tsplit_kernel<<<dim3(16, 16), 256>>>(Wk, WqkTh + (size_t)DMz * DMz,
                                         WqkTl + (size_t)DMz * DMz, DMz, DMz); // 3
    tsplitf_kernel<<<dim3(16, 16), 256>>>(Wv, WvTf, DMz, DMz);                 // 4
    bias_concat_kernel<<<QKN / 256, 256>>>(bq, bk, bqkp);                      // 5

    // fused Q|K projection (+score fill)
    gemm_kernel<3, true><<<gQK, 256, SM3>>>((const uint16_t*)xh, (const uint16_t*)xl,
        (const uint16_t*)WqkTh, (const uint16_t*)WqkTl, bqkp, nullptr, QKp, nullptr,
        fill0, FPB_GEMM, ROWSz, QKN, DMz, 0);                                  // 6 (ncu)
    // V projection (+score fill)
    gemm_kernel<1, false><<<gN512, 256, SM1>>>((const uint16_t*)xf, nullptr,
        (const uint16_t*)WvTf, nullptr, bv, nullptr, Vp, nullptr,
        fill2, FPB_GEMM, ROWSz, DMz, DMz, 0);                                  // 7

    // remaining weight conversions
    tsplitf_kernel<<<dim3(16, 16), 256>>>(Wo, WoTf, DMz, DMz);
    tsplitf_kernel<<<dim3(64, 16), 256>>>(W1, W1Tf, DMz, DHz);
    tsplitf_kernel<<<dim3(16, 64), 256>>>(W2, W2Tf, DHz, DMz);

    // ProbSparse attention
    compute_m_kernel<<<(BHz * Lz) / 8, 256>>>(idx, fill3);
    topk_kernel<<<BHz, 256>>>();
    scores_kernel<<<BHz * 4, 256>>>();
    softmax_kernel<<<BHz * Uz, 256>>>(score);
    context_kernel<<<BHz, 256>>>();
    ctx_assemble_kernel<<<ROWSz, 256>>>(cf);

    // Wo projection + residual, LN1 (fused fp16 x1)
    gemm_kernel<1, false><<<gN512, 256, SM1>>>((const uint16_t*)cf, nullptr,
        (const uint16_t*)WoTf, nullptr, bo, x, yp, nullptr,
        nullptr, 0, ROWSz, DMz, DMz, 1);
    ln_kernel<<<ROWSz, 256>>>(yp, g1, be1, x1p, x1f);

    // FFN
    gemm_kernel<1, false><<<gN2048, 256, SM1>>>((const uint16_t*)x1f, nullptr,
        (const uint16_t*)W1Tf, nullptr, bf1, nullptr, nullptr, (uint16_t*)hf,
        nullptr, 0, ROWSz, DHz, DMz, 2);
    gemm_kernel<1, false><<<gN512, 256, SM1>>>((const uint16_t*)hf, nullptr,
        (const uint16_t*)W2Tf, nullptr, bf2, x1p, y2p, nullptr,
        nullptr, 0, ROWSz, DMz, DHz, 1);
    ln_kernel<<<ROWSz, 256>>>(y2p, g2, be2, out, nullptr);
}

// round 17
// speedup vs baseline: 1.1660x; 1.0540x over previous
#include <cuda_runtime.h>
#include <cuda_bf16.h>
#include <cuda_fp16.h>
#include <math.h>
#include <stdint.h>

// ---------------- Problem constants ----------------
#define Bz   16
#define Lz   1024
#define DMz  512
#define Hz   8
#define DKz  64
#define DVz  64
#define DHz  2048
#define Uz   35
#define BHz  (Bz*Hz)     // 128
#define ROWSz (Bz*Lz)    // 16384
#define EPSz 1e-5f
#define QKN  1024        // stacked Q|K width

// ---------------- fp32 scratch ----------------
__device__ float g_QK[(size_t)ROWSz*QKN];   // [row][0..512)=Q, [512..1024)=K
__device__ float g_V[ROWSz*DMz];
__device__ float g_M[BHz*Lz];
__device__ int   g_Mtop[BHz*Uz];
__device__ int   g_rowmap[BHz*Lz];
__device__ float g_attn[(size_t)BHz*Uz*Lz];
__device__ float g_ctxrow[BHz*Uz*DVz];
__device__ float g_vmean[BHz*DVz];
__device__ float g_y[ROWSz*DMz];
__device__ float g_x1[ROWSz*DMz];
__device__ float g_y2[ROWSz*DMz];
__device__ float g_bqk[QKN];

// ---------------- bf16 split scratch (Q/K path, 3-term) ----------------
__device__ __nv_bfloat16 g_xh[ROWSz*DMz], g_xl[ROWSz*DMz];
__device__ __nv_bfloat16 g_WqkTh[QKN*DMz], g_WqkTl[QKN*DMz];

// ---------------- fp16 scratch (V/Wo/FFN path, single-pass) ----------------
__device__ __half g_xf[ROWSz*DMz];
__device__ __half g_cf[ROWSz*DMz];
__device__ __half g_x1f[ROWSz*DMz];
__device__ __half g_hf[(size_t)ROWSz*DHz];
__device__ __half g_WvTf[DMz*DMz];
__device__ __half g_WoTf[DMz*DMz];
__device__ __half g_W1Tf[DMz*DHz];
__device__ __half g_W2Tf[DHz*DMz];

// ---------------- helpers ----------------
__device__ __forceinline__ void cp16(uint32_t s, const void* g) {
    asm volatile("cp.async.cg.shared.global [%0], [%1], 16;"
                 :: "r"(s), "l"(__cvta_generic_to_global(g)));
}
__device__ __forceinline__ void cp_commit() {
    asm volatile("cp.async.commit_group;" ::: "memory");
}
__device__ __forceinline__ void ldm_x4(uint32_t& r0, uint32_t& r1, uint32_t& r2, uint32_t& r3,
                                       uint32_t addr) {
    asm volatile("ldmatrix.sync.aligned.m8n8.x4.shared.b16 {%0,%1,%2,%3}, [%4];"
                 : "=r"(r0), "=r"(r1), "=r"(r2), "=r"(r3) : "r"(addr));
}
template<bool ISBF16>
__device__ __forceinline__ void mma_t(float* c, const uint32_t* a, const uint32_t* b) {
    if constexpr (ISBF16)
        asm volatile("mma.sync.aligned.m16n8k16.row.col.f32.bf16.bf16.f32 "
                     "{%0,%1,%2,%3}, {%4,%5,%6,%7}, {%8,%9}, {%0,%1,%2,%3};"
                     : "+f"(c[0]), "+f"(c[1]), "+f"(c[2]), "+f"(c[3])
                     : "r"(a[0]), "r"(a[1]), "r"(a[2]), "r"(a[3]), "r"(b[0]), "r"(b[1]));
    else
        asm volatile("mma.sync.aligned.m16n8k16.row.col.f32.f16.f16.f32 "
                     "{%0,%1,%2,%3}, {%4,%5,%6,%7}, {%8,%9}, {%0,%1,%2,%3};"
                     : "+f"(c[0]), "+f"(c[1]), "+f"(c[2]), "+f"(c[3])
                     : "r"(a[0]), "r"(a[1]), "r"(a[2]), "r"(a[3]), "r"(b[0]), "r"(b[1]));
}

// ---------------- mma.sync GEMM, templated <TERMS, ISBF16> ----------------
#define ROWB 80
#define TILEB (128 * ROWB)

template<int TERMS, bool ISBF16>
__global__ void __launch_bounds__(256, 2)
gemm_kernel(const uint16_t* __restrict__ Ahi, const uint16_t* __restrict__ Alo,
            const uint16_t* __restrict__ Bhi, const uint16_t* __restrict__ Blo,
            const float* __restrict__ bias, const float* __restrict__ res,
            float* __restrict__ C, uint16_t* __restrict__ Chi,
            float* __restrict__ fillp, int fillPerBlk,
            int M, int N, int K, int eop)
{
    constexpr int NT = (TERMS == 3) ? 4 : 2;
    constexpr int NSTAGE = (TERMS == 3) ? 2 : 3;
    constexpr uint32_t STG = NT * TILEB;
    extern __shared__ __align__(16) char smem[];
    const uint32_t smem_u = (uint32_t)__cvta_generic_to_shared(smem);

    const int tid = threadIdx.x;
    const int wid = tid >> 5, lane = tid & 31;
    const int wm = (wid >> 2) * 64;
    const int wn = (wid & 3) * 32;
    const int g = lane >> 3, r = lane & 7;
    const int bm = blockIdx.y * 128;
    const int bn = blockIdx.x * 128;

    const int kt = K >> 5;

    float acc[4][4][4];
#pragma unroll
    for (int i = 0; i < 4; i++)
#pragma unroll
        for (int j = 0; j < 4; j++)
#pragma unroll
            for (int c = 0; c < 4; c++) acc[i][j][c] = 0.f;

    const int ar = tid >> 2, ac = tid & 3;

    auto load_tile = [&](int it, int buf) {
        const int kk = it << 5;
        const uint32_t s0 = smem_u + buf * STG;
        const size_t gaof = (size_t)(bm + ar) * K + kk + ac * 8;
        const size_t gbof = (size_t)(bn + ar) * K + kk + ac * 8;
        const size_t rowK64 = (size_t)64 * K;
        const uint32_t sof = ar * ROWB + ac * 16;
        cp16(s0 + sof, Ahi + gaof);
        cp16(s0 + sof + 64 * ROWB, Ahi + gaof + rowK64);
        if constexpr (TERMS == 3) {
            cp16(s0 + TILEB + sof, Alo + gaof);
            cp16(s0 + TILEB + sof + 64 * ROWB, Alo + gaof + rowK64);
            cp16(s0 + 2 * TILEB + sof, Bhi + gbof);
            cp16(s0 + 2 * TILEB + sof + 64 * ROWB, Bhi + gbof + rowK64);
            cp16(s0 + 3 * TILEB + sof, Blo + gbof);
            cp16(s0 + 3 * TILEB + sof + 64 * ROWB, Blo + gbof + rowK64);
        } else {
            cp16(s0 + TILEB + sof, Bhi + gbof);
            cp16(s0 + TILEB + sof + 64 * ROWB, Bhi + gbof + rowK64);
        }
        cp_commit();
    };

#pragma unroll
    for (int p = 0; p < NSTAGE - 1; p++)
        if (p < kt) load_tile(p, p);

    int buf = 0;
    for (int it = 0; it < kt; it++) {
        if (it + NSTAGE - 2 < kt && NSTAGE == 3) {
            asm volatile("cp.async.wait_group 1;" ::: "memory");
        } else {
            asm volatile("cp.async.wait_group 0;" ::: "memory");
        }
        __syncthreads();

        if (it + NSTAGE - 1 < kt) {
            int nb = buf + NSTAGE - 1; if (nb >= NSTAGE) nb -= NSTAGE;
            load_tile(it + NSTAGE - 1, nb);
        }

        const uint32_t sAh = smem_u + buf * STG;
        const uint32_t sBh = sAh + ((TERMS == 3) ? 2 : 1) * TILEB;
#pragma unroll
        for (int s = 0; s < 2; s++) {
            const int chkA = 2 * s + (g >> 1);
            const int chkB = 2 * s + (g & 1);
            const uint32_t aoff = (wm + ((g & 1) << 3) + r) * ROWB + chkA * 16;
            const uint32_t boff = (wn + ((g >> 1) << 3) + r) * ROWB + chkB * 16;

            uint32_t ah[4][4];
#pragma unroll
            for (int mf = 0; mf < 4; mf++)
                ldm_x4(ah[mf][0], ah[mf][1], ah[mf][2], ah[mf][3], sAh + aoff + mf * 16 * ROWB);
            uint32_t bh[4][2];
#pragma unroll
            for (int ng = 0; ng < 2; ng++)
                ldm_x4(bh[2 * ng][0], bh[2 * ng][1], bh[2 * ng + 1][0], bh[2 * ng + 1][1],
                       sBh + boff + ng * 16 * ROWB);

            if constexpr (TERMS == 3) {
                const uint32_t sAl = sAh + TILEB;
                const uint32_t sBl = sAh + 3 * TILEB;
                uint32_t bl[4][2];
#pragma unroll
                for (int ng = 0; ng < 2; ng++)
                    ldm_x4(bl[2 * ng][0], bl[2 * ng][1], bl[2 * ng + 1][0], bl[2 * ng + 1][1],
                           sBl + boff + ng * 16 * ROWB);
#pragma unroll
                for (int mf = 0; mf < 4; mf++)
#pragma unroll
                    for (int nf = 0; nf < 4; nf++) {
                        mma_t<ISBF16>(acc[mf][nf], ah[mf], bh[nf]);
                        mma_t<ISBF16>(acc[mf][nf], ah[mf], bl[nf]);
                    }
#pragma unroll
                for (int mf = 0; mf < 4; mf++)
                    ldm_x4(ah[mf][0], ah[mf][1], ah[mf][2], ah[mf][3], sAl + aoff + mf * 16 * ROWB);
#pragma unroll
                for (int mf = 0; mf < 4; mf++)
#pragma unroll
                    for (int nf = 0; nf < 4; nf++)
                        mma_t<ISBF16>(acc[mf][nf], ah[mf], bh[nf]);
            } else {
#pragma unroll
                for (int mf = 0; mf < 4; mf++)
#pragma unroll
                    for (int nf = 0; nf < 4; nf++)
                        mma_t<ISBF16>(acc[mf][nf], ah[mf], bh[nf]);
            }
        }
        if (++buf >= NSTAGE) buf = 0;
    }

    // epilogue
    const int rl = lane >> 2, cl = (lane & 3) * 2;
#pragma unroll
    for (int mf = 0; mf < 4; mf++) {
        const int row0 = bm + wm + mf * 16 + rl;
#pragma unroll
        for (int nf = 0; nf < 4; nf++) {
            const int col = bn + wn + nf * 8 + cl;
            const float b0 = bias[col], b1 = bias[col + 1];
            float v0 = acc[mf][nf][0] + b0, v1 = acc[mf][nf][1] + b1;
            float v2 = acc[mf][nf][2] + b0, v3 = acc[mf][nf][3] + b1;
            if (eop == 1) {
                const float* r0 = res + (size_t)row0 * N + col;
                const float* r1 = res + (size_t)(row0 + 8) * N + col;
                v0 += r0[0]; v1 += r0[1]; v2 += r1[0]; v3 += r1[1];
            } else if (eop == 2) {
                v0 = fmaxf(v0, 0.f); v1 = fmaxf(v1, 0.f);
                v2 = fmaxf(v2, 0.f); v3 = fmaxf(v3, 0.f);
                *(__half2*)(Chi + (size_t)row0 * N + col)       = __floats2half2_rn(v0, v1);
                *(__half2*)(Chi + (size_t)(row0 + 8) * N + col) = __floats2half2_rn(v2, v3);
                continue;
            }
            *(float2*)(C + (size_t)row0 * N + col) = make_float2(v0, v1);
            *(float2*)(C + (size_t)(row0 + 8) * N + col) = make_float2(v2, v3);
        }
    }

    // piggybacked constant fill of the score output (streaming stores)
    if (fillp) {
        const int nv4 = fillPerBlk >> 2;
        const int blin = blockIdx.y * gridDim.x + blockIdx.x;
        float4* dst = (float4*)fillp + (size_t)blin * nv4;
        const float c = 1.0f / Lz;
        const float4 f4 = make_float4(c, c, c, c);
        for (int i = tid; i < nv4; i += 256) __stcs(dst + i, f4);
    }
}

// ---------------- x -> bf16 hi/lo + fp16, one read ----------------
__global__ void __launch_bounds__(256)
split_x_kernel(const float* __restrict__ src, __nv_bfloat16* __restrict__ hi,
               __nv_bfloat16* __restrict__ lo, __half* __restrict__ f16)
{
    const size_t i = (size_t)blockIdx.x * 256 + threadIdx.x;
    const float4 v = ((const float4*)src)[i];
    __nv_bfloat16 h0 = __float2bfloat16(v.x), h1 = __float2bfloat16(v.y);
    __nv_bfloat16 h2 = __float2bfloat16(v.z), h3 = __float2bfloat16(v.w);
    __nv_bfloat162 ha; ha.x = h0; ha.y = h1;
    __nv_bfloat162 hb; hb.x = h2; hb.y = h3;
    ((__nv_bfloat162*)hi)[i * 2 + 0] = ha;
    ((__nv_bfloat162*)hi)[i * 2 + 1] = hb;
    __nv_bfloat162 la, lb;
    la.x = __float2bfloat16(v.x - __bfloat162float(h0));
    la.y = __float2bfloat16(v.y - __bfloat162float(h1));
    lb.x = __float2bfloat16(v.z - __bfloat162float(h2));
    lb.y = __float2bfloat16(v.w - __bfloat162float(h3));
    ((__nv_bfloat162*)lo)[i * 2 + 0] = la;
    ((__nv_bfloat162*)lo)[i * 2 + 1] = lb;
    ((__half2*)f16)[i * 2 + 0] = __floats2half2_rn(v.x, v.y);
    ((__half2*)f16)[i * 2 + 1] = __floats2half2_rn(v.z, v.w);
}

// ---------------- weight transpose + bf16 hi/lo split ----------------
__global__ void __launch_bounds__(256)
tsplit_kernel(const float* __restrict__ src, __nv_bfloat16* __restrict__ hi,
              __nv_bfloat16* __restrict__ lo, int K, int N)
{
    __shared__ float tile[32][33];
    const int tx = threadIdx.x & 31, ty = threadIdx.x >> 5;
    const int n0 = blockIdx.x * 32, k0 = blockIdx.y * 32;
#pragma unroll
    for (int i = 0; i < 4; i++)
        tile[ty + 8 * i][tx] = src[(size_t)(k0 + ty + 8 * i) * N + n0 + tx];
    __syncthreads();
#pragma unroll
    for (int i = 0; i < 4; i++) {
        const int n = n0 + ty + 8 * i, k = k0 + tx;
        const float v = tile[tx][ty + 8 * i];
        const __nv_bfloat16 h = __float2bfloat16(v);
        hi[(size_t)n * K + k] = h;
        lo[(size_t)n * K + k] = __float2bfloat16(v - __bfloat162float(h));
    }
}

// ---------------- batched fp16 weight transposes: Wv|Wo|W1|W2 in one launch ----------------
// tiles: Wv 16x16=256, Wo 256, W1 (64x16)=1024, W2 (16x64)=1024 -> 2560 blocks
__global__ void __launch_bounds__(256)
tsplitf_all_kernel(const float* __restrict__ Wv, const float* __restrict__ Wo,
                   const float* __restrict__ W1, const float* __restrict__ W2,
                   __half* __restrict__ WvT, __half* __restrict__ WoT,
                   __half* __restrict__ W1T, __half* __restrict__ W2T)
{
    const float* src; __half* dst; int K, N, bx, by;
    int blk = blockIdx.x;
    if (blk < 256)        { src = Wv; dst = WvT; K = DMz; N = DMz; bx = blk & 15; by = blk >> 4; }
    else if (blk < 512)   { blk -= 256; src = Wo; dst = WoT; K = DMz; N = DMz; bx = blk & 15; by = blk >> 4; }
    else if (blk < 1536)  { blk -= 512; src = W1; dst = W1T; K = DMz; N = DHz; bx = blk & 63; by = blk >> 6; }
    else                  { blk -= 1536; src = W2; dst = W2T; K = DHz; N = DMz; bx = blk & 15; by = blk >> 4; }

    __shared__ float tile[32][33];
    const int tx = threadIdx.x & 31, ty = threadIdx.x >> 5;
    const int n0 = bx * 32, k0 = by * 32;
#pragma unroll
    for (int i = 0; i < 4; i++)
        tile[ty + 8 * i][tx] = src[(size_t)(k0 + ty + 8 * i) * N + n0 + tx];
    __syncthreads();
#pragma unroll
    for (int i = 0; i < 4; i++) {
        const int n = n0 + ty + 8 * i, k = k0 + tx;
        dst[(size_t)n * K + k] = __float2half(tile[tx][ty + 8 * i]);
    }
}

// ---------------- bias concat [bq | bk] ----------------
__global__ void __launch_bounds__(256)
bias_concat_kernel(const float* __restrict__ bq, const float* __restrict__ bk,
                   float* __restrict__ dst)
{
    const int i = blockIdx.x * 256 + threadIdx.x;
    dst[i] = (i < DMz) ? bq[i] : bk[i - DMz];
}

// ---------------- Sampled scores + fill chunk (5-way interleaved samples) ----------------
__global__ void compute_m_kernel(const int* __restrict__ idx, float* __restrict__ fillp)
{
    {
        const float c = 1.0f / Lz;
        const float4 f4 = make_float4(c, c, c, c);
        float4* dst = (float4*)fillp + (size_t)blockIdx.x * 512;
        __stcs(dst + threadIdx.x, f4);
        __stcs(dst + threadIdx.x + 256, f4);
    }

    const int gw = (blockIdx.x * blockDim.x + threadIdx.x) >> 5;
    const int lane = threadIdx.x & 31;
    const int l = gw & (Lz - 1);
    const int bh = gw >> 10;
    const int h = bh & (Hz - 1), b = bh >> 3;

    const float2* qrow = (const float2*)(g_QK + (size_t)(b * Lz + l) * QKN + h * DKz);
    const float2 q2 = qrow[lane];
    float mx = -INFINITY, sum = 0.f;
#pragma unroll 1
    for (int s0 = 0; s0 < Uz; s0 += 5) {
        float p[5];
#pragma unroll
        for (int q = 0; q < 5; q++) {
            const int j = idx[l * Uz + s0 + q];
            const float2 k2 = ((const float2*)(g_QK + (size_t)(b * Lz + j) * QKN + DMz + h * DKz))[lane];
            p[q] = q2.x * k2.x + q2.y * k2.y;
        }
#pragma unroll
        for (int o = 16; o; o >>= 1) {
#pragma unroll
            for (int q = 0; q < 5; q++)
                p[q] += __shfl_xor_sync(0xffffffffu, p[q], o);
        }
#pragma unroll
        for (int q = 0; q < 5; q++) { mx = fmaxf(mx, p[q]); sum += p[q]; }
    }
    if (lane == 0) g_M[bh * Lz + l] = mx - sum * (1.0f / Uz);
}

// ---------------- top-35 per (b,h) ----------------
__global__ void __launch_bounds__(256) topk_kernel()
{
    const int bh = blockIdx.x;
    const int tid = threadIdx.x;
    const int wid = tid >> 5, lane = tid & 31;
    __shared__ float vals[Lz];
    __shared__ float wv[8];
    __shared__ int   wi[8];

    for (int l = tid; l < Lz; l += 256) {
        vals[l] = g_M[bh * Lz + l];
        g_rowmap[bh * Lz + l] = -1;
    }
    __syncthreads();

    for (int u = 0; u < Uz; u++) {
        float best = -INFINITY; int bi = 0x7fffffff;
#pragma unroll
        for (int c = 0; c < 4; c++) {
            const int l = tid + c * 256;
            const float v = vals[l];
            if (v > best) { best = v; bi = l; }
        }
#pragma unroll
        for (int o = 16; o; o >>= 1) {
            const float ov = __shfl_xor_sync(0xffffffffu, best, o);
            const int   oi = __shfl_xor_sync(0xffffffffu, bi, o);
            if (ov > best || (ov == best && oi < bi)) { best = ov; bi = oi; }
        }
        if (lane == 0) { wv[wid] = best; wi[wid] = bi; }
        __syncthreads();
        if (tid == 0) {
            float fb = wv[0]; int fi = wi[0];
#pragma unroll
            for (int w = 1; w < 8; w++) {
                if (wv[w] > fb || (wv[w] == fb && wi[w] < fi)) { fb = wv[w]; fi = wi[w]; }
            }
            g_Mtop[bh * Uz + u] = fi;
            g_rowmap[bh * Lz + fi] = u;
            vals[fi] = -INFINITY;
        }
        __syncthreads();
    }
}

// ---------------- scores = Q_top @ K^T / 8 (block = (bh, 256-l chunk)) ----------------
__global__ void __launch_bounds__(256) scores_kernel()
{
    const int bh = blockIdx.x >> 2;
    const int chunk = blockIdx.x & 3;
    const int b = bh >> 3, h = bh & (Hz - 1);
    const int tid = threadIdx.x;
    __shared__ float Qr[Uz * DKz];

    for (int i = tid; i < Uz * DKz; i += 256) {
        const int u = i / DKz, d = i - u * DKz;
        const int l = g_Mtop[bh * Uz + u];
        Qr[i] = g_QK[(size_t)(b * Lz + l) * QKN + h * DKz + d];
    }
    __syncthreads();

    const int l = chunk * 256 + tid;
    float acc[Uz];
#pragma unroll
    for (int u = 0; u < Uz; u++) acc[u] = 0.f;
    const float* krow = g_QK + (size_t)(b * Lz + l) * QKN + DMz + h * DKz;
#pragma unroll 4
    for (int d = 0; d < DKz; d++) {
        const float kd = krow[d];
#pragma unroll
        for (int u = 0; u < Uz; u++) acc[u] += kd * Qr[u * DKz + d];
    }
#pragma unroll
    for (int u = 0; u < Uz; u++)
        g_attn[((size_t)bh * Uz + u) * Lz + l] = acc[u] * 0.125f;
}

// ---------------- row softmax over L (+ fused score-output write) ----------------
__global__ void __launch_bounds__(256) softmax_kernel(float* __restrict__ outp)
{
    const int row = blockIdx.x;          // bh*Uz + u
    float* p = g_attn + (size_t)row * Lz;
    const int tid = threadIdx.x;
    __shared__ float red[256];

    float4 v = ((float4*)p)[tid];
    float m = fmaxf(fmaxf(v.x, v.y), fmaxf(v.z, v.w));
    red[tid] = m; __syncthreads();
    for (int s = 128; s; s >>= 1) { if (tid < s) red[tid] = fmaxf(red[tid], red[tid + s]); __syncthreads(); }
    m = red[0]; __syncthreads();

    v.x = __expf(v.x - m); v.y = __expf(v.y - m);
    v.z = __expf(v.z - m); v.w = __expf(v.w - m);
    red[tid] = v.x + v.y + v.z + v.w; __syncthreads();
    for (int s = 128; s; s >>= 1) { if (tid < s) red[tid] += red[tid + s]; __syncthreads(); }
    const float inv = 1.0f / red[0];
    v.x *= inv; v.y *= inv; v.z *= inv; v.w *= inv;
    ((float4*)p)[tid] = v;

    const int bh = row / Uz;
    const int l = g_Mtop[row];
    __stcs((float4*)(outp + ((size_t)bh * Lz + l) * Lz) + tid, v);
}

// ---------------- context (+fused V-mean) ----------------
__global__ void __launch_bounds__(256) context_kernel()
{
    const int bh = blockIdx.x;
    const int b = bh >> 3, h = bh & (Hz - 1);
    const int t = threadIdx.x;
    const int d = t & 63, ug = t >> 6;
    __shared__ float sat[Uz][129];

    float acc[9];
#pragma unroll
    for (int k = 0; k < 9; k++) acc[k] = 0.f;
    float vsum = 0.f;

    for (int c = 0; c < 8; c++) {
        for (int i = t; i < Uz * 128; i += 256) {
            const int u = i >> 7, li = i & 127;
            sat[u][li] = g_attn[((size_t)bh * Uz + u) * Lz + c * 128 + li];
        }
        __syncthreads();
        const float* vb = g_V + (size_t)(b * Lz + c * 128) * DMz + h * DVz + d;
#pragma unroll 4
        for (int i = 0; i < 128; i++) {
            const float v = vb[(size_t)i * DMz];
            vsum += v;
#pragma unroll
            for (int k = 0; k < 9; k++) {
                const int u = ug + 4 * k;
                if (u < Uz) acc[k] += sat[u][i] * v;
            }
        }
        __syncthreads();
    }
#pragma unroll
    for (int k = 0; k < 9; k++) {
        const int u = ug + 4 * k;
        if (u < Uz) g_ctxrow[(bh * Uz + u) * DVz + d] = acc[k];
    }
    if (ug == 0) g_vmean[bh * DVz + d] = vsum * (1.0f / Lz);
}

// ---------------- assemble ctx -> fp16 (block per row) ----------------
__global__ void __launch_bounds__(256) ctx_assemble_kernel(__half* __restrict__ dst)
{
    const int row = blockIdx.x;          // b*Lz + l
    const int b = row >> 10, l = row & (Lz - 1);
    const int tid = threadIdx.x;
    __shared__ int us[Hz];
    if (tid < Hz) us[tid] = g_rowmap[(b * Hz + tid) * Lz + l];
    __syncthreads();
#pragma unroll
    for (int e = tid; e < DMz; e += 256) {
        const int h = e >> 6, d = e & 63;
        const int u = us[h];
        const float v = (u < 0) ? g_vmean[(b * Hz + h) * DVz + d]
                                : g_ctxrow[((b * Hz + h) * Uz + u) * DVz + d];
        dst[(size_t)row * DMz + e] = __float2half(v);
    }
}

// ---------------- LayerNorm: warp per row (512 floats, 16/lane), shfl reduction ----------------
__global__ void __launch_bounds__(256)
ln_kernel(const float* __restrict__ in, const float* __restrict__ g,
          const float* __restrict__ beta, float* __restrict__ out,
          __half* __restrict__ outf)
{
    const int row = blockIdx.x * 8 + (threadIdx.x >> 5);
    const int lane = threadIdx.x & 31;
    const float4* r = (const float4*)(in + (size_t)row * DMz);

    float4 a = r[lane], b4 = r[lane + 32], c4 = r[lane + 64], d4 = r[lane + 96];
    float s = a.x + a.y + a.z + a.w + b4.x + b4.y + b4.z + b4.w
            + c4.x + c4.y + c4.z + c4.w + d4.x + d4.y + d4.z + d4.w;
#pragma unroll
    for (int o = 16; o; o >>= 1) s += __shfl_xor_sync(0xffffffffu, s, o);
    const float mean = s * (1.0f / DMz);

    float var = 0.f;
    a.x -= mean; a.y -= mean; a.z -= mean; a.w -= mean;
    b4.x -= mean; b4.y -= mean; b4.z -= mean; b4.w -= mean;
    c4.x -= mean; c4.y -= mean; c4.z -= mean; c4.w -= mean;
    d4.x -= mean; d4.y -= mean; d4.z -= mean; d4.w -= mean;
    var = a.x*a.x + a.y*a.y + a.z*a.z + a.w*a.w
        + b4.x*b4.x + b4.y*b4.y + b4.z*b4.z + b4.w*b4.w
        + c4.x*c4.x + c4.y*c4.y + c4.z*c4.z + c4.w*c4.w
        + d4.x*d4.x + d4.y*d4.y + d4.z*d4.z + d4.w*d4.w;
#pragma unroll
    for (int o = 16; o; o >>= 1) var += __shfl_xor_sync(0xffffffffu, var, o);
    const float inv = rsqrtf(var * (1.0f / DMz) + EPSz);

    float4* ob = (float4*)(out + (size_t)row * DMz);
    const float4* gg = (const float4*)g;
    const float4* bb = (const float4*)beta;
#pragma unroll
    for (int q = 0; q < 4; q++) {
        const int e = lane + 32 * q;
        const float4 gv = gg[e], bv = bb[e];
        float4 xv = (q == 0) ? a : (q == 1) ? b4 : (q == 2) ? c4 : d4;
        float4 o;
        o.x = gv.x * xv.x * inv + bv.x;
        o.y = gv.y * xv.y * inv + bv.y;
        o.z = gv.z * xv.z * inv + bv.z;
        o.w = gv.w * xv.w * inv + bv.w;
        ob[e] = o;
        if (outf) {
            __half2* of = (__half2*)(outf + (size_t)row * DMz);
            of[e * 2 + 0] = __floats2half2_rn(o.x, o.y);
            of[e * 2 + 1] = __floats2half2_rn(o.z, o.w);
        }
    }
}

// ---------------- launch ----------------
extern "C" void kernel_launch(void* const* d_in, const int* in_sizes, int n_in,
                              void* d_out, int out_size)
{
    const float* x   = (const float*)d_in[0];
    const float* Wq  = (const float*)d_in[1];
    const float* bq  = (const float*)d_in[2];
    const float* Wk  = (const float*)d_in[3];
    const float* bk  = (const float*)d_in[4];
    const float* Wv  = (const float*)d_in[5];
    const float* bv  = (const float*)d_in[6];
    const float* Wo  = (const float*)d_in[7];
    const float* bo  = (const float*)d_in[8];
    const float* g1  = (const float*)d_in[9];
    const float* be1 = (const float*)d_in[10];
    const float* W1  = (const float*)d_in[11];
    const float* bf1 = (const float*)d_in[12];
    const float* W2  = (const float*)d_in[13];
    const float* bf2 = (const float*)d_in[14];
    const float* g2  = (const float*)d_in[15];
    const float* be2 = (const float*)d_in[16];
    const int*   idx = (const int*)d_in[17];
    float* out = (float*)d_out;
    float* score = out + (size_t)ROWSz * DMz;

    float *QKp, *Vp, *yp, *x1p, *y2p, *bqkp;
    cudaGetSymbolAddress((void**)&QKp,  g_QK);
    cudaGetSymbolAddress((void**)&Vp,   g_V);
    cudaGetSymbolAddress((void**)&yp,   g_y);
    cudaGetSymbolAddress((void**)&x1p,  g_x1);
    cudaGetSymbolAddress((void**)&y2p,  g_y2);
    cudaGetSymbolAddress((void**)&bqkp, g_bqk);

    __nv_bfloat16 *xh, *xl, *WqkTh, *WqkTl;
    __half *xf, *cf, *x1f, *hf, *WvTf, *WoTf, *W1Tf, *W2Tf;
    cudaGetSymbolAddress((void**)&xh, g_xh);       cudaGetSymbolAddress((void**)&xl, g_xl);
    cudaGetSymbolAddress((void**)&WqkTh, g_WqkTh); cudaGetSymbolAddress((void**)&WqkTl, g_WqkTl);
    cudaGetSymbolAddress((void**)&xf, g_xf);       cudaGetSymbolAddress((void**)&cf, g_cf);
    cudaGetSymbolAddress((void**)&x1f, g_x1f);     cudaGetSymbolAddress((void**)&hf, g_hf);
    cudaGetSymbolAddress((void**)&WvTf, g_WvTf);   cudaGetSymbolAddress((void**)&WoTf, g_WoTf);
    cudaGetSymbolAddress((void**)&W1Tf, g_W1Tf);   cudaGetSymbolAddress((void**)&W2Tf, g_W2Tf);

    const int SM3 = 2 * 4 * TILEB;
    const int SM1 = 3 * 2 * TILEB;
    cudaFuncSetAttribute(gemm_kernel<3, true>,
                         cudaFuncAttributeMaxDynamicSharedMemorySize, SM3);
    cudaFuncSetAttribute(gemm_kernel<1, false>,
                         cudaFuncAttributeMaxDynamicSharedMemorySize, SM1);

    const dim3 gQK(8, 128);
    const dim3 gN512(4, 128);
    const dim3 gN2048(16, 128);

    const int FPB_GEMM = 65536;
    float* fill0 = score;
    float* fill2 = score + (size_t)1024 * FPB_GEMM;
    float* fill3 = score + (size_t)1536 * FPB_GEMM;

    // conversions (launch #6 = fused QK GEMM for ncu)
    split_x_kernel<<<(ROWSz * DMz) / 1024, 256>>>(x, xh, xl, xf);              // 1
    tsplit_kernel<<<dim3(16, 16), 256>>>(Wq, WqkTh, WqkTl, DMz, DMz);          // 2
    tsplit_kernel<<<dim3(16, 16), 256>>>(Wk, WqkTh + (size_t)DMz * DMz,
                                         WqkTl + (size_t)DMz * DMz, DMz, DMz); // 3
    tsplitf_all_kernel<<<2560, 256>>>(Wv, Wo, W1, W2, WvTf, WoTf, W1Tf, W2Tf); // 4
    bias_concat_kernel<<<QKN / 256, 256>>>(bq, bk, bqkp);                      // 5

    // fused Q|K projection (+score fill)
    gemm_kernel<3, true><<<gQK, 256, SM3>>>((const uint16_t*)xh, (const uint16_t*)xl,
        (const uint16_t*)WqkTh, (const uint16_t*)WqkTl, bqkp, nullptr, QKp, nullptr,
        fill0, FPB_GEMM, ROWSz, QKN, DMz, 0);                                  // 6 (ncu)
    // V projection (+score fill)
    gemm_kernel<1, false><<<gN512, 256, SM1>>>((const uint16_t*)xf, nullptr,
        (const uint16_t*)WvTf, nullptr, bv, nullptr, Vp, nullptr,
        fill2, FPB_GEMM, ROWSz, DMz, DMz, 0);                                  // 7

    // ProbSparse attention
    compute_m_kernel<<<(BHz * Lz) / 8, 256>>>(idx, fill3);
    topk_kernel<<<BHz, 256>>>();
    scores_kernel<<<BHz * 4, 256>>>();
    softmax_kernel<<<BHz * Uz, 256>>>(score);
    context_kernel<<<BHz, 256>>>();
    ctx_assemble_kernel<<<ROWSz, 256>>>(cf);

    // Wo projection + residual, LN1 (fused fp16 x1)
    gemm_kernel<1, false><<<gN512, 256, SM1>>>((const uint16_t*)cf, nullptr,
        (const uint16_t*)WoTf, nullptr, bo, x, yp, nullptr,
        nullptr, 0, ROWSz, DMz, DMz, 1);
    ln_kernel<<<ROWSz / 8, 256>>>(yp, g1, be1, x1p, x1f);

    // FFN
    gemm_kernel<1, false><<<gN2048, 256, SM1>>>((const uint16_t*)x1f, nullptr,
        (const uint16_t*)W1Tf, nullptr, bf1, nullptr, nullptr, (uint16_t*)hf,
        nullptr, 0, ROWSz, DHz, DMz, 2);
    gemm_kernel<1, false><<<gN512, 256, SM1>>>((const uint16_t*)hf, nullptr,
        (const uint16_t*)W2Tf, nullptr, bf2, x1p, y2p, nullptr,
        nullptr, 0, ROWSz, DMz, DHz, 1);
    ln_kernel<<<ROWSz / 8, 256>>>(y2p, g2, be2, out, nullptr);
}